// round 1
// baseline (speedup 1.0000x reference)
#include <cuda_runtime.h>
#include <math.h>

// ---------------------------------------------------------------------------
// DiagonalMicroAttention: b=8, c=256, h=w=32, heads=8, d=32, n=1024
// Pipeline:
//   K1 qkv GEMM  -> q,k,v in [bh][n][d] layout
//   K2 colsum(V), diag_vec
//   K3 flash attention (no max-sub; logits tiny) + diag term -> [b][c][n]
//   K4 gate MLP (asym pooled -> 64 ch gelu -> 1 ch sigmoid)
//   K5 out-proj GEMM with (1+g) gate folded in
// ---------------------------------------------------------------------------

#define B 8
#define HEADS 8
#define D 32
#define N 1024
#define C 256
#define SCALE 0.1767766952966369f   // 1/sqrt(32)

__device__ float g_q[B * HEADS * N * D];
__device__ float g_k[B * HEADS * N * D];
__device__ float g_v[B * HEADS * N * D];
__device__ float g_ao[B * C * N];          // attention output, [b][c][n]
__device__ float g_g1buf[B * 64 * N];      // gate hidden
__device__ float g_gate[B * N];            // sigmoid gate per pixel
__device__ float g_dvec[B * D];            // 0.3 * scale/8 * diag sums
__device__ float g_csum[B * HEADS * D];    // column sums of V

// ---------------------------------------------------------------------------
// K1: qkv projection.  Y[b,o,p] = sum_c W[o,c] * x[b,c,p], o in [0,768)
// Tile 64(o) x 64(p), K-chunks of 32. tx -> o (so dd is float4-contiguous on
// store into [n][d] layout), ty -> p.
// ---------------------------------------------------------------------------
__global__ __launch_bounds__(256) void qkv_kernel(const float* __restrict__ x,
                                                  const float* __restrict__ w) {
    const int b = blockIdx.z;
    const int o0 = blockIdx.y * 64;
    const int p0 = blockIdx.x * 64;
    const int tid = threadIdx.x;
    const int tx = tid & 15, ty = tid >> 4;

    __shared__ float Ws[32 * 68];   // [c][o], padded
    __shared__ float Xs[32 * 64];   // [c][p]

    float acc[4][4];
#pragma unroll
    for (int i = 0; i < 4; i++)
#pragma unroll
        for (int j = 0; j < 4; j++) acc[i][j] = 0.f;

    for (int kk = 0; kk < 256; kk += 32) {
#pragma unroll
        for (int t = 0; t < 2; t++) {
            int idx4 = tid + t * 256;
            int oo = idx4 >> 3;
            int cc4 = idx4 & 7;
            float4 wv = *(const float4*)&w[(o0 + oo) * 256 + kk + cc4 * 4];
            Ws[(cc4 * 4 + 0) * 68 + oo] = wv.x;
            Ws[(cc4 * 4 + 1) * 68 + oo] = wv.y;
            Ws[(cc4 * 4 + 2) * 68 + oo] = wv.z;
            Ws[(cc4 * 4 + 3) * 68 + oo] = wv.w;
        }
#pragma unroll
        for (int t = 0; t < 2; t++) {
            int idx4 = tid + t * 256;
            int cc = idx4 >> 4;
            int pp4 = idx4 & 15;
            *(float4*)&Xs[cc * 64 + pp4 * 4] =
                *(const float4*)&x[((b * 256) + kk + cc) * 1024 + p0 + pp4 * 4];
        }
        __syncthreads();
#pragma unroll
        for (int c = 0; c < 32; c++) {
            float4 a = *(float4*)&Ws[c * 68 + tx * 4];
            float4 bv = *(float4*)&Xs[c * 64 + ty * 4];
            acc[0][0] += a.x * bv.x; acc[0][1] += a.x * bv.y; acc[0][2] += a.x * bv.z; acc[0][3] += a.x * bv.w;
            acc[1][0] += a.y * bv.x; acc[1][1] += a.y * bv.y; acc[1][2] += a.y * bv.z; acc[1][3] += a.y * bv.w;
            acc[2][0] += a.z * bv.x; acc[2][1] += a.z * bv.y; acc[2][2] += a.z * bv.z; acc[2][3] += a.z * bv.w;
            acc[3][0] += a.w * bv.x; acc[3][1] += a.w * bv.y; acc[3][2] += a.w * bv.z; acc[3][3] += a.w * bv.w;
        }
        __syncthreads();
    }

    // route to q/k/v: o -> (part, head, dd). o-block of 4 stays within one head.
    const int ob = o0 + tx * 4;
    const int part = ob >> 8;
    const int ci = ob & 255;
    const int head = ci >> 5;
    const int dd = ci & 31;
    float* dst = (part == 0) ? g_q : ((part == 1) ? g_k : g_v);
    float* base = dst + (((size_t)(b * 8 + head) * 1024)) * 32 + dd;
#pragma unroll
    for (int pj = 0; pj < 4; pj++) {
        int p = p0 + ty * 4 + pj;
        float4 val = make_float4(acc[0][pj], acc[1][pj], acc[2][pj], acc[3][pj]);
        *(float4*)&base[(size_t)p * 32] = val;
    }
}

// ---------------------------------------------------------------------------
// K2a: column sums of V per (b,h):  csum[bh][d] = sum_j v[bh][j][d]
// ---------------------------------------------------------------------------
__global__ __launch_bounds__(256) void colsum_kernel() {
    const int bh = blockIdx.x;
    const int tid = threadIdx.x;
    const int dd = tid & 31;
    const int sl = tid >> 5;
    const float* vb = g_v + (size_t)bh * 1024 * 32;
    float s = 0.f;
    for (int j = sl * 128; j < sl * 128 + 128; j++) s += vb[(size_t)j * 32 + dd];
    __shared__ float red[256];
    red[tid] = s;
    __syncthreads();
    if (tid < 32) {
        float t = 0.f;
#pragma unroll
        for (int r = 0; r < 8; r++) t += red[tid + r * 32];
        g_csum[bh * 32 + tid] = t;
    }
}

// ---------------------------------------------------------------------------
// K2b: diag_vec[b][i] = 0.3 * (scale/8) * sum_h sum_s q[b,h,33s,i]*k[b,h,33s,i]
// ---------------------------------------------------------------------------
__global__ __launch_bounds__(256) void diag_kernel() {
    const int b = blockIdx.x;
    const int tid = threadIdx.x;
    const int i = tid & 31;
    const int h = tid >> 5;
    const size_t base = ((size_t)(b * 8 + h) * 1024) * 32;
    float s = 0.f;
#pragma unroll 4
    for (int ss = 0; ss < 32; ss++) {
        size_t off = base + (size_t)(ss * 33) * 32 + i;
        s += g_q[off] * g_k[off];
    }
    __shared__ float red[256];
    red[tid] = s;
    __syncthreads();
    if (tid < 32) {
        float t = 0.f;
#pragma unroll
        for (int r = 0; r < 8; r++) t += red[tid + r * 32];
        g_dvec[b * 32 + tid] = t * (0.3f * SCALE / 8.0f);
    }
}

// ---------------------------------------------------------------------------
// K3: flash attention. One CTA = (bh, 128-query tile). One thread = one row.
// Logits |s| < ~1 so exp without max subtraction is exact & safe.
// out[b][head*32+d][i] = (sum_j exp(s_j) v_j[d]) / l + dvec[i]*csum[d]
// ---------------------------------------------------------------------------
__global__ __launch_bounds__(128) void attn_kernel() {
    const int bh = blockIdx.y;
    const int b = bh >> 3;
    const int head = bh & 7;
    const int i = blockIdx.x * 128 + threadIdx.x;

    const float* qrow = g_q + ((size_t)bh * 1024 + i) * 32;
    float qr[32];
#pragma unroll
    for (int d4 = 0; d4 < 8; d4++) {
        float4 qv = ((const float4*)qrow)[d4];
        qr[4 * d4 + 0] = qv.x * SCALE;
        qr[4 * d4 + 1] = qv.y * SCALE;
        qr[4 * d4 + 2] = qv.z * SCALE;
        qr[4 * d4 + 3] = qv.w * SCALE;
    }

    float o[32];
#pragma unroll
    for (int d = 0; d < 32; d++) o[d] = 0.f;
    float l = 0.f;

    __shared__ float Ks[128 * 32];
    __shared__ float Vs[128 * 32];
    const float4* kg = (const float4*)(g_k + (size_t)bh * 1024 * 32);
    const float4* vg = (const float4*)(g_v + (size_t)bh * 1024 * 32);

    for (int t0 = 0; t0 < 8; t0++) {
        const int off4 = t0 * 128 * 8;
#pragma unroll
        for (int r = 0; r < 8; r++) {
            ((float4*)Ks)[threadIdx.x + r * 128] = kg[off4 + threadIdx.x + r * 128];
            ((float4*)Vs)[threadIdx.x + r * 128] = vg[off4 + threadIdx.x + r * 128];
        }
        __syncthreads();
#pragma unroll 2
        for (int j = 0; j < 128; j++) {
            const float4* kr = (const float4*)(Ks + j * 32);
            float s0 = 0.f, s1 = 0.f, s2 = 0.f, s3 = 0.f;
#pragma unroll
            for (int d4 = 0; d4 < 8; d4++) {
                float4 kk = kr[d4];
                s0 += qr[4 * d4 + 0] * kk.x;
                s1 += qr[4 * d4 + 1] * kk.y;
                s2 += qr[4 * d4 + 2] * kk.z;
                s3 += qr[4 * d4 + 3] * kk.w;
            }
            float p = __expf((s0 + s1) + (s2 + s3));
            l += p;
            const float4* vr = (const float4*)(Vs + j * 32);
#pragma unroll
            for (int d4 = 0; d4 < 8; d4++) {
                float4 vv = vr[d4];
                o[4 * d4 + 0] += p * vv.x;
                o[4 * d4 + 1] += p * vv.y;
                o[4 * d4 + 2] += p * vv.z;
                o[4 * d4 + 3] += p * vv.w;
            }
        }
        __syncthreads();
    }

    const float inv = 1.f / l;
    const float dv = (i < 32) ? g_dvec[b * 32 + i] : 0.f;
    const float* cs = g_csum + bh * 32;
    float* obase = g_ao + ((size_t)b * 256 + head * 32) * 1024 + i;
#pragma unroll
    for (int d = 0; d < 32; d++) obase[(size_t)d * 1024] = o[d] * inv + dv * cs[d];
}

// ---------------------------------------------------------------------------
// K4a: gate hidden.  g1[b,u,p] = gelu(b_g1[u] + sum_c pooled[b,c,p]*w_g1[u,c])
// pooled[b,c,(hh,ww)] = |x[b,c,hh,ww/2] - x[b,c,hh,31-ww/2]|
// Tile 64(u) x 64(p), ty -> u, tx -> p (p coalesced on store).
// ---------------------------------------------------------------------------
__global__ __launch_bounds__(256) void gate1_kernel(const float* __restrict__ x,
                                                    const float* __restrict__ w_g1,
                                                    const float* __restrict__ b_g1) {
    const int b = blockIdx.y;
    const int p0 = blockIdx.x * 64;
    const int tid = threadIdx.x;
    const int tx = tid & 15, ty = tid >> 4;

    __shared__ float Ws[32 * 68];   // [c][u]
    __shared__ float Xs[32 * 64];   // [c][p]

    float acc[4][4];
#pragma unroll
    for (int i = 0; i < 4; i++)
#pragma unroll
        for (int j = 0; j < 4; j++) acc[i][j] = 0.f;

    for (int kk = 0; kk < 256; kk += 32) {
#pragma unroll
        for (int t = 0; t < 2; t++) {
            int idx4 = tid + t * 256;
            int uu = idx4 >> 3;
            int cc4 = idx4 & 7;
            float4 wv = *(const float4*)&w_g1[uu * 256 + kk + cc4 * 4];
            Ws[(cc4 * 4 + 0) * 68 + uu] = wv.x;
            Ws[(cc4 * 4 + 1) * 68 + uu] = wv.y;
            Ws[(cc4 * 4 + 2) * 68 + uu] = wv.z;
            Ws[(cc4 * 4 + 3) * 68 + uu] = wv.w;
        }
#pragma unroll
        for (int t = 0; t < 8; t++) {
            int idx = tid + t * 256;
            int cc = idx >> 6;
            int pp = idx & 63;
            int p = p0 + pp;
            int hh = p >> 5;
            int wj = (p & 31) >> 1;
            const float* row = x + ((size_t)(b * 256) + kk + cc) * 1024 + hh * 32;
            Xs[cc * 64 + pp] = fabsf(row[wj] - row[31 - wj]);
        }
        __syncthreads();
#pragma unroll
        for (int c = 0; c < 32; c++) {
            float4 a = *(float4*)&Ws[c * 68 + ty * 4];   // u direction
            float4 bv = *(float4*)&Xs[c * 64 + tx * 4];  // p direction
            acc[0][0] += a.x * bv.x; acc[0][1] += a.x * bv.y; acc[0][2] += a.x * bv.z; acc[0][3] += a.x * bv.w;
            acc[1][0] += a.y * bv.x; acc[1][1] += a.y * bv.y; acc[1][2] += a.y * bv.z; acc[1][3] += a.y * bv.w;
            acc[2][0] += a.z * bv.x; acc[2][1] += a.z * bv.y; acc[2][2] += a.z * bv.z; acc[2][3] += a.z * bv.w;
            acc[3][0] += a.w * bv.x; acc[3][1] += a.w * bv.y; acc[3][2] += a.w * bv.z; acc[3][3] += a.w * bv.w;
        }
        __syncthreads();
    }

#pragma unroll
    for (int ui = 0; ui < 4; ui++) {
        int u = ty * 4 + ui;
        float bias = b_g1[u];
        float4 vout;
        float v0 = acc[ui][0] + bias, v1 = acc[ui][1] + bias;
        float v2 = acc[ui][2] + bias, v3 = acc[ui][3] + bias;
        vout.x = 0.5f * v0 * (1.f + erff(v0 * 0.70710678118654752f));
        vout.y = 0.5f * v1 * (1.f + erff(v1 * 0.70710678118654752f));
        vout.z = 0.5f * v2 * (1.f + erff(v2 * 0.70710678118654752f));
        vout.w = 0.5f * v3 * (1.f + erff(v3 * 0.70710678118654752f));
        *(float4*)&g_g1buf[((size_t)(b * 64) + u) * 1024 + p0 + tx * 4] = vout;
    }
}

// ---------------------------------------------------------------------------
// K4b: gate output.  g[b,p] = sigmoid(b_g2 + sum_u g1[b,u,p]*w_g2[u])
// ---------------------------------------------------------------------------
__global__ __launch_bounds__(256) void gate2_kernel(const float* __restrict__ w_g2,
                                                    const float* __restrict__ b_g2) {
    const int idx = blockIdx.x * 256 + threadIdx.x;  // 0..8191
    const int b = idx >> 10;
    const int p = idx & 1023;
    float acc = b_g2[0];
#pragma unroll 8
    for (int u = 0; u < 64; u++)
        acc += g_g1buf[((size_t)(b * 64) + u) * 1024 + p] * w_g2[u];
    g_gate[idx] = 1.f / (1.f + expf(-acc));
}

// ---------------------------------------------------------------------------
// K5: out-proj.  y[b,o,p] = b_out[o] + sum_c (ao[b,c,p]*(1+g[b,p])) * w_out[o,c]
// ty -> o, tx -> p (p coalesced on store).
// ---------------------------------------------------------------------------
__global__ __launch_bounds__(256) void outproj_kernel(const float* __restrict__ w_out,
                                                      const float* __restrict__ b_out,
                                                      float* __restrict__ out) {
    const int b = blockIdx.z;
    const int o0 = blockIdx.y * 64;
    const int p0 = blockIdx.x * 64;
    const int tid = threadIdx.x;
    const int tx = tid & 15, ty = tid >> 4;

    __shared__ float Ws[32 * 68];
    __shared__ float Xs[32 * 64];
    __shared__ float Gs[64];

    if (tid < 64) Gs[tid] = 1.f + g_gate[b * 1024 + p0 + tid];
    __syncthreads();

    float acc[4][4];
#pragma unroll
    for (int i = 0; i < 4; i++)
#pragma unroll
        for (int j = 0; j < 4; j++) acc[i][j] = 0.f;

    for (int kk = 0; kk < 256; kk += 32) {
#pragma unroll
        for (int t = 0; t < 2; t++) {
            int idx4 = tid + t * 256;
            int oo = idx4 >> 3;
            int cc4 = idx4 & 7;
            float4 wv = *(const float4*)&w_out[(o0 + oo) * 256 + kk + cc4 * 4];
            Ws[(cc4 * 4 + 0) * 68 + oo] = wv.x;
            Ws[(cc4 * 4 + 1) * 68 + oo] = wv.y;
            Ws[(cc4 * 4 + 2) * 68 + oo] = wv.z;
            Ws[(cc4 * 4 + 3) * 68 + oo] = wv.w;
        }
#pragma unroll
        for (int t = 0; t < 2; t++) {
            int idx4 = tid + t * 256;
            int cc = idx4 >> 4;
            int pp4 = idx4 & 15;
            float4 av = *(const float4*)&g_ao[((size_t)(b * 256) + kk + cc) * 1024 + p0 + pp4 * 4];
            av.x *= Gs[pp4 * 4 + 0];
            av.y *= Gs[pp4 * 4 + 1];
            av.z *= Gs[pp4 * 4 + 2];
            av.w *= Gs[pp4 * 4 + 3];
            *(float4*)&Xs[cc * 64 + pp4 * 4] = av;
        }
        __syncthreads();
#pragma unroll
        for (int c = 0; c < 32; c++) {
            float4 a = *(float4*)&Ws[c * 68 + ty * 4];   // o direction
            float4 bv = *(float4*)&Xs[c * 64 + tx * 4];  // p direction
            acc[0][0] += a.x * bv.x; acc[0][1] += a.x * bv.y; acc[0][2] += a.x * bv.z; acc[0][3] += a.x * bv.w;
            acc[1][0] += a.y * bv.x; acc[1][1] += a.y * bv.y; acc[1][2] += a.y * bv.z; acc[1][3] += a.y * bv.w;
            acc[2][0] += a.z * bv.x; acc[2][1] += a.z * bv.y; acc[2][2] += a.z * bv.z; acc[2][3] += a.z * bv.w;
            acc[3][0] += a.w * bv.x; acc[3][1] += a.w * bv.y; acc[3][2] += a.w * bv.z; acc[3][3] += a.w * bv.w;
        }
        __syncthreads();
    }

#pragma unroll
    for (int oi = 0; oi < 4; oi++) {
        int o = o0 + ty * 4 + oi;
        float bias = b_out[o];
        float4 vout = make_float4(acc[oi][0] + bias, acc[oi][1] + bias,
                                  acc[oi][2] + bias, acc[oi][3] + bias);
        *(float4*)&out[((size_t)(b * 256) + o) * 1024 + p0 + tx * 4] = vout;
    }
}

// ---------------------------------------------------------------------------
extern "C" void kernel_launch(void* const* d_in, const int* in_sizes, int n_in,
                              void* d_out, int out_size) {
    const float* x     = (const float*)d_in[0];
    const float* w_qkv = (const float*)d_in[1];
    const float* w_out = (const float*)d_in[2];
    const float* b_out = (const float*)d_in[3];
    const float* w_g1  = (const float*)d_in[4];
    const float* b_g1  = (const float*)d_in[5];
    const float* w_g2  = (const float*)d_in[6];
    const float* b_g2  = (const float*)d_in[7];
    float* out = (float*)d_out;

    qkv_kernel<<<dim3(16, 12, 8), 256>>>(x, w_qkv);
    colsum_kernel<<<64, 256>>>();
    diag_kernel<<<8, 256>>>();
    attn_kernel<<<dim3(8, 64), 128>>>();
    gate1_kernel<<<dim3(16, 8), 256>>>(x, w_g1, b_g1);
    gate2_kernel<<<32, 256>>>(w_g2, b_g2);
    outproj_kernel<<<dim3(16, 4, 8), 256>>>(w_out, b_out, out);
}

// round 2
// speedup vs baseline: 1.0480x; 1.0480x over previous
#include <cuda_runtime.h>
#include <math.h>

// ---------------------------------------------------------------------------
// DiagonalMicroAttention: b=8, c=256, h=w=32, heads=8, d=32, n=1024
//   K1 qkv GEMM  -> q,k,v in [bh][n][d] layout          (f32x2 inner loop)
//   K2 colsum(V), diag_vec
//   K3 flash attention + diag term -> [b][c][n]          (f32x2 inner loop)
//   K4 gate MLP
//   K5 out-proj GEMM with (1+g) gate folded in           (f32x2 inner loop)
// ---------------------------------------------------------------------------

#define B 8
#define HEADS 8
#define D 32
#define N 1024
#define C 256
#define SCALE 0.1767766952966369f   // 1/sqrt(32)

typedef unsigned long long u64;

__device__ __forceinline__ u64 ffma2(u64 a, u64 b, u64 c) {
    u64 d; asm("fma.rn.f32x2 %0,%1,%2,%3;" : "=l"(d) : "l"(a), "l"(b), "l"(c));
    return d;
}
__device__ __forceinline__ u64 pack2(float lo, float hi) {
    u64 r; asm("mov.b64 %0, {%1,%2};" : "=l"(r) : "f"(lo), "f"(hi));
    return r;
}
__device__ __forceinline__ u64 dup2(float v) {
    u64 r; asm("mov.b64 %0, {%1,%1};" : "=l"(r) : "f"(v));
    return r;
}
__device__ __forceinline__ float2 unpk(u64 v) {
    float2 f; asm("mov.b64 {%0,%1}, %2;" : "=f"(f.x), "=f"(f.y) : "l"(v));
    return f;
}
__device__ __forceinline__ u64 d2u(double d) { return __double_as_longlong(d); }

__device__ float g_q[B * HEADS * N * D];
__device__ float g_k[B * HEADS * N * D];
__device__ float g_v[B * HEADS * N * D];
__device__ float g_ao[B * C * N];          // attention output, [b][c][n]
__device__ float g_g1buf[B * 64 * N];      // gate hidden
__device__ float g_gate[B * N];            // sigmoid gate per pixel
__device__ float g_dvec[B * D];            // 0.3 * scale/8 * diag sums
__device__ float g_csum[B * HEADS * D];    // column sums of V

// ---------------------------------------------------------------------------
// K1: qkv projection.  Y[b,o,p] = sum_c W[o,c] * x[b,c,p], o in [0,768)
// Tile 64(o) x 64(p). tx -> o (dd float4-contiguous on store), ty -> p.
// f32x2: pack p-pairs, dup the o-broadcast.
// ---------------------------------------------------------------------------
__global__ __launch_bounds__(256) void qkv_kernel(const float* __restrict__ x,
                                                  const float* __restrict__ w) {
    const int b = blockIdx.z;
    const int o0 = blockIdx.y * 64;
    const int p0 = blockIdx.x * 64;
    const int tid = threadIdx.x;
    const int tx = tid & 15, ty = tid >> 4;

    __shared__ float Ws[32 * 68];   // [c][o], padded
    __shared__ float Xs[32 * 64];   // [c][p]

    u64 acc2[4][2];
#pragma unroll
    for (int i = 0; i < 4; i++) { acc2[i][0] = 0ull; acc2[i][1] = 0ull; }

    for (int kk = 0; kk < 256; kk += 32) {
#pragma unroll
        for (int t = 0; t < 2; t++) {
            int idx4 = tid + t * 256;
            int oo = idx4 >> 3;
            int cc4 = idx4 & 7;
            float4 wv = *(const float4*)&w[(o0 + oo) * 256 + kk + cc4 * 4];
            Ws[(cc4 * 4 + 0) * 68 + oo] = wv.x;
            Ws[(cc4 * 4 + 1) * 68 + oo] = wv.y;
            Ws[(cc4 * 4 + 2) * 68 + oo] = wv.z;
            Ws[(cc4 * 4 + 3) * 68 + oo] = wv.w;
        }
#pragma unroll
        for (int t = 0; t < 2; t++) {
            int idx4 = tid + t * 256;
            int cc = idx4 >> 4;
            int pp4 = idx4 & 15;
            *(float4*)&Xs[cc * 64 + pp4 * 4] =
                *(const float4*)&x[((b * 256) + kk + cc) * 1024 + p0 + pp4 * 4];
        }
        __syncthreads();
#pragma unroll
        for (int c = 0; c < 32; c++) {
            float4 a = *(float4*)&Ws[c * 68 + tx * 4];
            double2 bd = *(const double2*)&Xs[c * 64 + ty * 4];
            u64 b01 = d2u(bd.x), b23 = d2u(bd.y);
            acc2[0][0] = ffma2(dup2(a.x), b01, acc2[0][0]);
            acc2[0][1] = ffma2(dup2(a.x), b23, acc2[0][1]);
            acc2[1][0] = ffma2(dup2(a.y), b01, acc2[1][0]);
            acc2[1][1] = ffma2(dup2(a.y), b23, acc2[1][1]);
            acc2[2][0] = ffma2(dup2(a.z), b01, acc2[2][0]);
            acc2[2][1] = ffma2(dup2(a.z), b23, acc2[2][1]);
            acc2[3][0] = ffma2(dup2(a.w), b01, acc2[3][0]);
            acc2[3][1] = ffma2(dup2(a.w), b23, acc2[3][1]);
        }
        __syncthreads();
    }

    float acc[4][4];
#pragma unroll
    for (int i = 0; i < 4; i++) {
        float2 lo = unpk(acc2[i][0]), hi = unpk(acc2[i][1]);
        acc[i][0] = lo.x; acc[i][1] = lo.y; acc[i][2] = hi.x; acc[i][3] = hi.y;
    }

    // route to q/k/v: o -> (part, head, dd). o-block of 4 stays within one head.
    const int ob = o0 + tx * 4;
    const int part = ob >> 8;
    const int ci = ob & 255;
    const int head = ci >> 5;
    const int dd = ci & 31;
    float* dst = (part == 0) ? g_q : ((part == 1) ? g_k : g_v);
    float* base = dst + (((size_t)(b * 8 + head) * 1024)) * 32 + dd;
#pragma unroll
    for (int pj = 0; pj < 4; pj++) {
        int p = p0 + ty * 4 + pj;
        float4 val = make_float4(acc[0][pj], acc[1][pj], acc[2][pj], acc[3][pj]);
        *(float4*)&base[(size_t)p * 32] = val;
    }
}

// ---------------------------------------------------------------------------
// K2a: column sums of V per (b,h):  csum[bh][d] = sum_j v[bh][j][d]
// ---------------------------------------------------------------------------
__global__ __launch_bounds__(256) void colsum_kernel() {
    const int bh = blockIdx.x;
    const int tid = threadIdx.x;
    const int dd = tid & 31;
    const int sl = tid >> 5;
    const float* vb = g_v + (size_t)bh * 1024 * 32;
    float s = 0.f;
    for (int j = sl * 128; j < sl * 128 + 128; j++) s += vb[(size_t)j * 32 + dd];
    __shared__ float red[256];
    red[tid] = s;
    __syncthreads();
    if (tid < 32) {
        float t = 0.f;
#pragma unroll
        for (int r = 0; r < 8; r++) t += red[tid + r * 32];
        g_csum[bh * 32 + tid] = t;
    }
}

// ---------------------------------------------------------------------------
// K2b: diag_vec[b][i] = 0.3 * (scale/8) * sum_h sum_s q[b,h,33s,i]*k[b,h,33s,i]
// ---------------------------------------------------------------------------
__global__ __launch_bounds__(256) void diag_kernel() {
    const int b = blockIdx.x;
    const int tid = threadIdx.x;
    const int i = tid & 31;
    const int h = tid >> 5;
    const size_t base = ((size_t)(b * 8 + h) * 1024) * 32;
    float s = 0.f;
#pragma unroll 4
    for (int ss = 0; ss < 32; ss++) {
        size_t off = base + (size_t)(ss * 33) * 32 + i;
        s += g_q[off] * g_k[off];
    }
    __shared__ float red[256];
    red[tid] = s;
    __syncthreads();
    if (tid < 32) {
        float t = 0.f;
#pragma unroll
        for (int r = 0; r < 8; r++) t += red[tid + r * 32];
        g_dvec[b * 32 + tid] = t * (0.3f * SCALE / 8.0f);
    }
}

// ---------------------------------------------------------------------------
// K3: flash attention with f32x2. One CTA = (bh, 128-query tile).
// One thread = one query row. Logits tiny -> exp without max-sub is exact.
// out[b][head*32+d][i] = (sum_j exp(s_j) v_j[d]) / l + dvec[i]*csum[d]
// ---------------------------------------------------------------------------
__global__ __launch_bounds__(128) void attn_kernel() {
    const int bh = blockIdx.y;
    const int b = bh >> 3;
    const int head = bh & 7;
    const int i = blockIdx.x * 128 + threadIdx.x;

    const float* qrow = g_q + ((size_t)bh * 1024 + i) * 32;
    u64 qr2[16];
#pragma unroll
    for (int d4 = 0; d4 < 8; d4++) {
        float4 qv = ((const float4*)qrow)[d4];
        qr2[2 * d4 + 0] = pack2(qv.x * SCALE, qv.y * SCALE);
        qr2[2 * d4 + 1] = pack2(qv.z * SCALE, qv.w * SCALE);
    }

    u64 o2[16];
#pragma unroll
    for (int d = 0; d < 16; d++) o2[d] = 0ull;
    float l = 0.f;

    __shared__ float Ks[128 * 32];
    __shared__ float Vs[128 * 32];
    const float4* kg = (const float4*)(g_k + (size_t)bh * 1024 * 32);
    const float4* vg = (const float4*)(g_v + (size_t)bh * 1024 * 32);

    for (int t0 = 0; t0 < 8; t0++) {
        const int off4 = t0 * 128 * 8;
#pragma unroll
        for (int r = 0; r < 8; r++) {
            ((float4*)Ks)[threadIdx.x + r * 128] = kg[off4 + threadIdx.x + r * 128];
            ((float4*)Vs)[threadIdx.x + r * 128] = vg[off4 + threadIdx.x + r * 128];
        }
        __syncthreads();
#pragma unroll 2
        for (int j = 0; j < 128; j++) {
            const double2* kr = (const double2*)(Ks + j * 32);
            u64 sA = 0ull, sB = 0ull, sC = 0ull, sD = 0ull;
#pragma unroll
            for (int t2 = 0; t2 < 4; t2++) {
                double2 k0 = kr[2 * t2 + 0];
                double2 k1 = kr[2 * t2 + 1];
                sA = ffma2(qr2[4 * t2 + 0], d2u(k0.x), sA);
                sB = ffma2(qr2[4 * t2 + 1], d2u(k0.y), sB);
                sC = ffma2(qr2[4 * t2 + 2], d2u(k1.x), sC);
                sD = ffma2(qr2[4 * t2 + 3], d2u(k1.y), sD);
            }
            float2 fa = unpk(sA), fb = unpk(sB), fc = unpk(sC), fd = unpk(sD);
            float s = ((fa.x + fa.y) + (fb.x + fb.y)) + ((fc.x + fc.y) + (fd.x + fd.y));
            float p = __expf(s);
            l += p;
            u64 p2 = dup2(p);
            const double2* vr = (const double2*)(Vs + j * 32);
#pragma unroll
            for (int t2 = 0; t2 < 8; t2++) {
                double2 vv = vr[t2];
                o2[2 * t2 + 0] = ffma2(p2, d2u(vv.x), o2[2 * t2 + 0]);
                o2[2 * t2 + 1] = ffma2(p2, d2u(vv.y), o2[2 * t2 + 1]);
            }
        }
        __syncthreads();
    }

    const float inv = 1.f / l;
    const float dv = (i < 32) ? g_dvec[b * 32 + i] : 0.f;
    const float* cs = g_csum + bh * 32;
    float* obase = g_ao + ((size_t)b * 256 + head * 32) * 1024 + i;
#pragma unroll
    for (int t = 0; t < 16; t++) {
        float2 ov = unpk(o2[t]);
        obase[(size_t)(2 * t + 0) * 1024] = ov.x * inv + dv * cs[2 * t + 0];
        obase[(size_t)(2 * t + 1) * 1024] = ov.y * inv + dv * cs[2 * t + 1];
    }
}

// ---------------------------------------------------------------------------
// K4a: gate hidden.  g1[b,u,p] = gelu(b_g1[u] + sum_c pooled[b,c,p]*w_g1[u,c])
// pooled[b,c,(hh,ww)] = |x[b,c,hh,ww/2] - x[b,c,hh,31-ww/2]|
// Tile 64(u) x 64(p), ty -> u, tx -> p.
// ---------------------------------------------------------------------------
__global__ __launch_bounds__(256) void gate1_kernel(const float* __restrict__ x,
                                                    const float* __restrict__ w_g1,
                                                    const float* __restrict__ b_g1) {
    const int b = blockIdx.y;
    const int p0 = blockIdx.x * 64;
    const int tid = threadIdx.x;
    const int tx = tid & 15, ty = tid >> 4;

    __shared__ float Ws[32 * 68];   // [c][u]
    __shared__ float Xs[32 * 64];   // [c][p]

    u64 acc2[4][2];
#pragma unroll
    for (int i = 0; i < 4; i++) { acc2[i][0] = 0ull; acc2[i][1] = 0ull; }

    for (int kk = 0; kk < 256; kk += 32) {
#pragma unroll
        for (int t = 0; t < 2; t++) {
            int idx4 = tid + t * 256;
            int uu = idx4 >> 3;
            int cc4 = idx4 & 7;
            float4 wv = *(const float4*)&w_g1[uu * 256 + kk + cc4 * 4];
            Ws[(cc4 * 4 + 0) * 68 + uu] = wv.x;
            Ws[(cc4 * 4 + 1) * 68 + uu] = wv.y;
            Ws[(cc4 * 4 + 2) * 68 + uu] = wv.z;
            Ws[(cc4 * 4 + 3) * 68 + uu] = wv.w;
        }
#pragma unroll
        for (int t = 0; t < 8; t++) {
            int idx = tid + t * 256;
            int cc = idx >> 6;
            int pp = idx & 63;
            int p = p0 + pp;
            int hh = p >> 5;
            int wj = (p & 31) >> 1;
            const float* row = x + ((size_t)(b * 256) + kk + cc) * 1024 + hh * 32;
            Xs[cc * 64 + pp] = fabsf(row[wj] - row[31 - wj]);
        }
        __syncthreads();
#pragma unroll
        for (int c = 0; c < 32; c++) {
            float4 a = *(float4*)&Ws[c * 68 + ty * 4];       // u direction
            double2 bd = *(const double2*)&Xs[c * 64 + tx * 4];  // p direction
            u64 b01 = d2u(bd.x), b23 = d2u(bd.y);
            acc2[0][0] = ffma2(dup2(a.x), b01, acc2[0][0]);
            acc2[0][1] = ffma2(dup2(a.x), b23, acc2[0][1]);
            acc2[1][0] = ffma2(dup2(a.y), b01, acc2[1][0]);
            acc2[1][1] = ffma2(dup2(a.y), b23, acc2[1][1]);
            acc2[2][0] = ffma2(dup2(a.z), b01, acc2[2][0]);
            acc2[2][1] = ffma2(dup2(a.z), b23, acc2[2][1]);
            acc2[3][0] = ffma2(dup2(a.w), b01, acc2[3][0]);
            acc2[3][1] = ffma2(dup2(a.w), b23, acc2[3][1]);
        }
        __syncthreads();
    }

#pragma unroll
    for (int ui = 0; ui < 4; ui++) {
        int u = ty * 4 + ui;
        float bias = b_g1[u];
        float2 lo = unpk(acc2[ui][0]), hi = unpk(acc2[ui][1]);
        float v0 = lo.x + bias, v1 = lo.y + bias;
        float v2 = hi.x + bias, v3 = hi.y + bias;
        float4 vout;
        vout.x = 0.5f * v0 * (1.f + erff(v0 * 0.70710678118654752f));
        vout.y = 0.5f * v1 * (1.f + erff(v1 * 0.70710678118654752f));
        vout.z = 0.5f * v2 * (1.f + erff(v2 * 0.70710678118654752f));
        vout.w = 0.5f * v3 * (1.f + erff(v3 * 0.70710678118654752f));
        *(float4*)&g_g1buf[((size_t)(b * 64) + u) * 1024 + p0 + tx * 4] = vout;
    }
}

// ---------------------------------------------------------------------------
// K4b: gate output.  g[b,p] = sigmoid(b_g2 + sum_u g1[b,u,p]*w_g2[u])
// ---------------------------------------------------------------------------
__global__ __launch_bounds__(256) void gate2_kernel(const float* __restrict__ w_g2,
                                                    const float* __restrict__ b_g2) {
    const int idx = blockIdx.x * 256 + threadIdx.x;  // 0..8191
    const int b = idx >> 10;
    const int p = idx & 1023;
    float acc = b_g2[0];
#pragma unroll 8
    for (int u = 0; u < 64; u++)
        acc += g_g1buf[((size_t)(b * 64) + u) * 1024 + p] * w_g2[u];
    g_gate[idx] = 1.f / (1.f + expf(-acc));
}

// ---------------------------------------------------------------------------
// K5: out-proj.  y[b,o,p] = b_out[o] + sum_c (ao[b,c,p]*(1+g[b,p])) * w_out[o,c]
// ty -> o, tx -> p.
// ---------------------------------------------------------------------------
__global__ __launch_bounds__(256) void outproj_kernel(const float* __restrict__ w_out,
                                                      const float* __restrict__ b_out,
                                                      float* __restrict__ out) {
    const int b = blockIdx.z;
    const int o0 = blockIdx.y * 64;
    const int p0 = blockIdx.x * 64;
    const int tid = threadIdx.x;
    const int tx = tid & 15, ty = tid >> 4;

    __shared__ float Ws[32 * 68];
    __shared__ float Xs[32 * 64];
    __shared__ float Gs[64];

    if (tid < 64) Gs[tid] = 1.f + g_gate[b * 1024 + p0 + tid];
    __syncthreads();

    u64 acc2[4][2];
#pragma unroll
    for (int i = 0; i < 4; i++) { acc2[i][0] = 0ull; acc2[i][1] = 0ull; }

    for (int kk = 0; kk < 256; kk += 32) {
#pragma unroll
        for (int t = 0; t < 2; t++) {
            int idx4 = tid + t * 256;
            int oo = idx4 >> 3;
            int cc4 = idx4 & 7;
            float4 wv = *(const float4*)&w_out[(o0 + oo) * 256 + kk + cc4 * 4];
            Ws[(cc4 * 4 + 0) * 68 + oo] = wv.x;
            Ws[(cc4 * 4 + 1) * 68 + oo] = wv.y;
            Ws[(cc4 * 4 + 2) * 68 + oo] = wv.z;
            Ws[(cc4 * 4 + 3) * 68 + oo] = wv.w;
        }
#pragma unroll
        for (int t = 0; t < 2; t++) {
            int idx4 = tid + t * 256;
            int cc = idx4 >> 4;
            int pp4 = idx4 & 15;
            float4 av = *(const float4*)&g_ao[((size_t)(b * 256) + kk + cc) * 1024 + p0 + pp4 * 4];
            av.x *= Gs[pp4 * 4 + 0];
            av.y *= Gs[pp4 * 4 + 1];
            av.z *= Gs[pp4 * 4 + 2];
            av.w *= Gs[pp4 * 4 + 3];
            *(float4*)&Xs[cc * 64 + pp4 * 4] = av;
        }
        __syncthreads();
#pragma unroll
        for (int c = 0; c < 32; c++) {
            float4 a = *(float4*)&Ws[c * 68 + ty * 4];       // o direction
            double2 bd = *(const double2*)&Xs[c * 64 + tx * 4];  // p direction
            u64 b01 = d2u(bd.x), b23 = d2u(bd.y);
            acc2[0][0] = ffma2(dup2(a.x), b01, acc2[0][0]);
            acc2[0][1] = ffma2(dup2(a.x), b23, acc2[0][1]);
            acc2[1][0] = ffma2(dup2(a.y), b01, acc2[1][0]);
            acc2[1][1] = ffma2(dup2(a.y), b23, acc2[1][1]);
            acc2[2][0] = ffma2(dup2(a.z), b01, acc2[2][0]);
            acc2[2][1] = ffma2(dup2(a.z), b23, acc2[2][1]);
            acc2[3][0] = ffma2(dup2(a.w), b01, acc2[3][0]);
            acc2[3][1] = ffma2(dup2(a.w), b23, acc2[3][1]);
        }
        __syncthreads();
    }

#pragma unroll
    for (int oi = 0; oi < 4; oi++) {
        int o = o0 + ty * 4 + oi;
        float bias = b_out[o];
        float2 lo = unpk(acc2[oi][0]), hi = unpk(acc2[oi][1]);
        float4 vout = make_float4(lo.x + bias, lo.y + bias, hi.x + bias, hi.y + bias);
        *(float4*)&out[((size_t)(b * 256) + o) * 1024 + p0 + tx * 4] = vout;
    }
}

// ---------------------------------------------------------------------------
extern "C" void kernel_launch(void* const* d_in, const int* in_sizes, int n_in,
                              void* d_out, int out_size) {
    const float* x     = (const float*)d_in[0];
    const float* w_qkv = (const float*)d_in[1];
    const float* w_out = (const float*)d_in[2];
    const float* b_out = (const float*)d_in[3];
    const float* w_g1  = (const float*)d_in[4];
    const float* b_g1  = (const float*)d_in[5];
    const float* w_g2  = (const float*)d_in[6];
    const float* b_g2  = (const float*)d_in[7];
    float* out = (float*)d_out;

    qkv_kernel<<<dim3(16, 12, 8), 256>>>(x, w_qkv);
    colsum_kernel<<<64, 256>>>();
    diag_kernel<<<8, 256>>>();
    attn_kernel<<<dim3(8, 64), 128>>>();
    gate1_kernel<<<dim3(16, 8), 256>>>(x, w_g1, b_g1);
    gate2_kernel<<<32, 256>>>(w_g2, b_g2);
    outproj_kernel<<<dim3(16, 4, 8), 256>>>(w_out, b_out, out);
}

// round 3
// speedup vs baseline: 1.1039x; 1.0533x over previous
#include <cuda_runtime.h>
#include <math.h>

// ---------------------------------------------------------------------------
// DiagonalMicroAttention: b=8, c=256, h=w=32, heads=8, d=32, n=1024
//   K1 qkv GEMM  -> q,k,v in [bh][n][d] layout          (f32x2)
//   K2 colsum(V), diag_vec
//   K3 flash attention, R=2 rows/thread, 2-way key split (f32x2)
//   K3b finalize: combine splits, divide by l, add diag term
//   K4 gate MLP
//   K5 out-proj GEMM with (1+g) gate folded in           (f32x2)
// ---------------------------------------------------------------------------

#define B 8
#define HEADS 8
#define D 32
#define N 1024
#define C 256
#define SCALE 0.1767766952966369f   // 1/sqrt(32)
#define BHND (B * HEADS * N * D)
#define BHN  (B * HEADS * N)

typedef unsigned long long u64;

__device__ __forceinline__ u64 ffma2(u64 a, u64 b, u64 c) {
    u64 d; asm("fma.rn.f32x2 %0,%1,%2,%3;" : "=l"(d) : "l"(a), "l"(b), "l"(c));
    return d;
}
__device__ __forceinline__ u64 pack2(float lo, float hi) {
    u64 r; asm("mov.b64 %0, {%1,%2};" : "=l"(r) : "f"(lo), "f"(hi));
    return r;
}
__device__ __forceinline__ u64 dup2(float v) {
    u64 r; asm("mov.b64 %0, {%1,%1};" : "=l"(r) : "f"(v));
    return r;
}
__device__ __forceinline__ float2 unpk(u64 v) {
    float2 f; asm("mov.b64 {%0,%1}, %2;" : "=f"(f.x), "=f"(f.y) : "l"(v));
    return f;
}
__device__ __forceinline__ u64 d2u(double d) { return __double_as_longlong(d); }

__device__ float g_q[BHND];
__device__ float g_k[BHND];
__device__ float g_v[BHND];
__device__ float g_po[2 * BHND];           // split partial o (unnormalized)
__device__ float g_pl[2 * BHN];            // split partial row sums
__device__ float g_ao[B * C * N];          // attention output, [b][c][n]
__device__ float g_g1buf[B * 64 * N];      // gate hidden
__device__ float g_gate[B * N];            // sigmoid gate per pixel
__device__ float g_dvec[B * D];            // 0.3 * scale/8 * diag sums
__device__ float g_csum[B * HEADS * D];    // column sums of V

// ---------------------------------------------------------------------------
// K1: qkv projection.  Y[b,o,p] = sum_c W[o,c] * x[b,c,p], o in [0,768)
// ---------------------------------------------------------------------------
__global__ __launch_bounds__(256) void qkv_kernel(const float* __restrict__ x,
                                                  const float* __restrict__ w) {
    const int b = blockIdx.z;
    const int o0 = blockIdx.y * 64;
    const int p0 = blockIdx.x * 64;
    const int tid = threadIdx.x;
    const int tx = tid & 15, ty = tid >> 4;

    __shared__ float Ws[32 * 68];   // [c][o], padded
    __shared__ float Xs[32 * 64];   // [c][p]

    u64 acc2[4][2];
#pragma unroll
    for (int i = 0; i < 4; i++) { acc2[i][0] = 0ull; acc2[i][1] = 0ull; }

    for (int kk = 0; kk < 256; kk += 32) {
#pragma unroll
        for (int t = 0; t < 2; t++) {
            int idx4 = tid + t * 256;
            int oo = idx4 >> 3;
            int cc4 = idx4 & 7;
            float4 wv = *(const float4*)&w[(o0 + oo) * 256 + kk + cc4 * 4];
            Ws[(cc4 * 4 + 0) * 68 + oo] = wv.x;
            Ws[(cc4 * 4 + 1) * 68 + oo] = wv.y;
            Ws[(cc4 * 4 + 2) * 68 + oo] = wv.z;
            Ws[(cc4 * 4 + 3) * 68 + oo] = wv.w;
        }
#pragma unroll
        for (int t = 0; t < 2; t++) {
            int idx4 = tid + t * 256;
            int cc = idx4 >> 4;
            int pp4 = idx4 & 15;
            *(float4*)&Xs[cc * 64 + pp4 * 4] =
                *(const float4*)&x[((b * 256) + kk + cc) * 1024 + p0 + pp4 * 4];
        }
        __syncthreads();
#pragma unroll
        for (int c = 0; c < 32; c++) {
            float4 a = *(float4*)&Ws[c * 68 + tx * 4];
            double2 bd = *(const double2*)&Xs[c * 64 + ty * 4];
            u64 b01 = d2u(bd.x), b23 = d2u(bd.y);
            acc2[0][0] = ffma2(dup2(a.x), b01, acc2[0][0]);
            acc2[0][1] = ffma2(dup2(a.x), b23, acc2[0][1]);
            acc2[1][0] = ffma2(dup2(a.y), b01, acc2[1][0]);
            acc2[1][1] = ffma2(dup2(a.y), b23, acc2[1][1]);
            acc2[2][0] = ffma2(dup2(a.z), b01, acc2[2][0]);
            acc2[2][1] = ffma2(dup2(a.z), b23, acc2[2][1]);
            acc2[3][0] = ffma2(dup2(a.w), b01, acc2[3][0]);
            acc2[3][1] = ffma2(dup2(a.w), b23, acc2[3][1]);
        }
        __syncthreads();
    }

    float acc[4][4];
#pragma unroll
    for (int i = 0; i < 4; i++) {
        float2 lo = unpk(acc2[i][0]), hi = unpk(acc2[i][1]);
        acc[i][0] = lo.x; acc[i][1] = lo.y; acc[i][2] = hi.x; acc[i][3] = hi.y;
    }

    const int ob = o0 + tx * 4;
    const int part = ob >> 8;
    const int ci = ob & 255;
    const int head = ci >> 5;
    const int dd = ci & 31;
    float* dst = (part == 0) ? g_q : ((part == 1) ? g_k : g_v);
    float* base = dst + (((size_t)(b * 8 + head) * 1024)) * 32 + dd;
#pragma unroll
    for (int pj = 0; pj < 4; pj++) {
        int p = p0 + ty * 4 + pj;
        float4 val = make_float4(acc[0][pj], acc[1][pj], acc[2][pj], acc[3][pj]);
        *(float4*)&base[(size_t)p * 32] = val;
    }
}

// ---------------------------------------------------------------------------
// K2a: column sums of V per (b,h)
// ---------------------------------------------------------------------------
__global__ __launch_bounds__(256) void colsum_kernel() {
    const int bh = blockIdx.x;
    const int tid = threadIdx.x;
    const int dd = tid & 31;
    const int sl = tid >> 5;
    const float* vb = g_v + (size_t)bh * 1024 * 32;
    float s = 0.f;
    for (int j = sl * 128; j < sl * 128 + 128; j++) s += vb[(size_t)j * 32 + dd];
    __shared__ float red[256];
    red[tid] = s;
    __syncthreads();
    if (tid < 32) {
        float t = 0.f;
#pragma unroll
        for (int r = 0; r < 8; r++) t += red[tid + r * 32];
        g_csum[bh * 32 + tid] = t;
    }
}

// ---------------------------------------------------------------------------
// K2b: diag_vec
// ---------------------------------------------------------------------------
__global__ __launch_bounds__(256) void diag_kernel() {
    const int b = blockIdx.x;
    const int tid = threadIdx.x;
    const int i = tid & 31;
    const int h = tid >> 5;
    const size_t base = ((size_t)(b * 8 + h) * 1024) * 32;
    float s = 0.f;
#pragma unroll 4
    for (int ss = 0; ss < 32; ss++) {
        size_t off = base + (size_t)(ss * 33) * 32 + i;
        s += g_q[off] * g_k[off];
    }
    __shared__ float red[256];
    red[tid] = s;
    __syncthreads();
    if (tid < 32) {
        float t = 0.f;
#pragma unroll
        for (int r = 0; r < 8; r++) t += red[tid + r * 32];
        g_dvec[b * 32 + tid] = t * (0.3f * SCALE / 8.0f);
    }
}

// ---------------------------------------------------------------------------
// K3: flash attention, R=2 query rows / thread, 2-way split over keys.
// CTA = (256-query tile, bh, key-split). 128 threads; thread t owns query
// rows i0 = qt*256+t and i1 = i0+128. Each key split covers 512 keys.
// Writes unnormalized partial sums to g_po / g_pl.
// ---------------------------------------------------------------------------
__global__ __launch_bounds__(128) void attn_kernel() {
    const int bh = blockIdx.y;
    const int sp = blockIdx.z;
    const int i0 = blockIdx.x * 256 + threadIdx.x;
    const int i1 = i0 + 128;

    const float* qbase = g_q + (size_t)bh * 1024 * 32;
    u64 qa2[16], qb2[16];
#pragma unroll
    for (int d4 = 0; d4 < 8; d4++) {
        float4 qv = ((const float4*)(qbase + (size_t)i0 * 32))[d4];
        qa2[2 * d4 + 0] = pack2(qv.x * SCALE, qv.y * SCALE);
        qa2[2 * d4 + 1] = pack2(qv.z * SCALE, qv.w * SCALE);
        float4 qw = ((const float4*)(qbase + (size_t)i1 * 32))[d4];
        qb2[2 * d4 + 0] = pack2(qw.x * SCALE, qw.y * SCALE);
        qb2[2 * d4 + 1] = pack2(qw.z * SCALE, qw.w * SCALE);
    }

    u64 oa2[16], ob2[16];
#pragma unroll
    for (int d = 0; d < 16; d++) { oa2[d] = 0ull; ob2[d] = 0ull; }
    float la = 0.f, lb = 0.f;

    __shared__ float Ks[128 * 32];
    __shared__ float Vs[128 * 32];
    const float4* kg = (const float4*)(g_k + (size_t)bh * 1024 * 32);
    const float4* vg = (const float4*)(g_v + (size_t)bh * 1024 * 32);

    for (int t0 = sp * 4; t0 < sp * 4 + 4; t0++) {
        const int off4 = t0 * 128 * 8;
#pragma unroll
        for (int r = 0; r < 8; r++) {
            ((float4*)Ks)[threadIdx.x + r * 128] = kg[off4 + threadIdx.x + r * 128];
            ((float4*)Vs)[threadIdx.x + r * 128] = vg[off4 + threadIdx.x + r * 128];
        }
        __syncthreads();
#pragma unroll 2
        for (int j = 0; j < 128; j++) {
            const double2* kr = (const double2*)(Ks + j * 32);
            u64 aA = 0ull, aB = 0ull, aC = 0ull, aD = 0ull;
            u64 bA = 0ull, bB = 0ull, bC = 0ull, bD = 0ull;
#pragma unroll
            for (int t2 = 0; t2 < 4; t2++) {
                double2 k0 = kr[2 * t2 + 0];
                double2 k1 = kr[2 * t2 + 1];
                u64 k0x = d2u(k0.x), k0y = d2u(k0.y);
                u64 k1x = d2u(k1.x), k1y = d2u(k1.y);
                aA = ffma2(qa2[4 * t2 + 0], k0x, aA);
                aB = ffma2(qa2[4 * t2 + 1], k0y, aB);
                aC = ffma2(qa2[4 * t2 + 2], k1x, aC);
                aD = ffma2(qa2[4 * t2 + 3], k1y, aD);
                bA = ffma2(qb2[4 * t2 + 0], k0x, bA);
                bB = ffma2(qb2[4 * t2 + 1], k0y, bB);
                bC = ffma2(qb2[4 * t2 + 2], k1x, bC);
                bD = ffma2(qb2[4 * t2 + 3], k1y, bD);
            }
            float2 fa = unpk(aA), fb = unpk(aB), fc = unpk(aC), fd = unpk(aD);
            float sa = ((fa.x + fa.y) + (fb.x + fb.y)) + ((fc.x + fc.y) + (fd.x + fd.y));
            float2 ga = unpk(bA), gb = unpk(bB), gc = unpk(bC), gd = unpk(bD);
            float sb = ((ga.x + ga.y) + (gb.x + gb.y)) + ((gc.x + gc.y) + (gd.x + gd.y));
            float pa = __expf(sa);
            float pb = __expf(sb);
            la += pa;
            lb += pb;
            u64 pa2 = dup2(pa), pb2 = dup2(pb);
            const double2* vr = (const double2*)(Vs + j * 32);
#pragma unroll
            for (int t2 = 0; t2 < 8; t2++) {
                double2 vv = vr[t2];
                u64 vx = d2u(vv.x), vy = d2u(vv.y);
                oa2[2 * t2 + 0] = ffma2(pa2, vx, oa2[2 * t2 + 0]);
                oa2[2 * t2 + 1] = ffma2(pa2, vy, oa2[2 * t2 + 1]);
                ob2[2 * t2 + 0] = ffma2(pb2, vx, ob2[2 * t2 + 0]);
                ob2[2 * t2 + 1] = ffma2(pb2, vy, ob2[2 * t2 + 1]);
            }
        }
        __syncthreads();
    }

    float* dstA = g_po + (size_t)sp * BHND + ((size_t)bh * 1024 + i0) * 32;
    float* dstB = g_po + (size_t)sp * BHND + ((size_t)bh * 1024 + i1) * 32;
#pragma unroll
    for (int t = 0; t < 8; t++) {
        float2 l0 = unpk(oa2[2 * t + 0]), h0 = unpk(oa2[2 * t + 1]);
        *(float4*)&dstA[t * 4] = make_float4(l0.x, l0.y, h0.x, h0.y);
        float2 l1 = unpk(ob2[2 * t + 0]), h1 = unpk(ob2[2 * t + 1]);
        *(float4*)&dstB[t * 4] = make_float4(l1.x, l1.y, h1.x, h1.y);
    }
    g_pl[sp * BHN + bh * 1024 + i0] = la;
    g_pl[sp * BHN + bh * 1024 + i1] = lb;
}

// ---------------------------------------------------------------------------
// K3b: finalize — combine splits, normalize, add diag term, transpose store.
// One thread per (bh, i).
// ---------------------------------------------------------------------------
__global__ __launch_bounds__(256) void attn_final_kernel() {
    const int idx = blockIdx.x * 256 + threadIdx.x;   // 0..65535
    const int bh = idx >> 10;
    const int i = idx & 1023;
    const int b = bh >> 3;
    const int head = bh & 7;

    const float l = g_pl[idx] + g_pl[BHN + idx];
    const float inv = 1.f / l;
    const float dv = (i < 32) ? g_dvec[b * 32 + i] : 0.f;
    const float* cs = g_csum + bh * 32;
    const float4* p0 = (const float4*)(g_po + ((size_t)bh * 1024 + i) * 32);
    const float4* p1 = (const float4*)(g_po + (size_t)BHND + ((size_t)bh * 1024 + i) * 32);
    float* obase = g_ao + ((size_t)b * 256 + head * 32) * 1024 + i;
#pragma unroll
    for (int t = 0; t < 8; t++) {
        float4 a = p0[t];
        float4 c = p1[t];
        obase[(size_t)(4 * t + 0) * 1024] = (a.x + c.x) * inv + dv * cs[4 * t + 0];
        obase[(size_t)(4 * t + 1) * 1024] = (a.y + c.y) * inv + dv * cs[4 * t + 1];
        obase[(size_t)(4 * t + 2) * 1024] = (a.z + c.z) * inv + dv * cs[4 * t + 2];
        obase[(size_t)(4 * t + 3) * 1024] = (a.w + c.w) * inv + dv * cs[4 * t + 3];
    }
}

// ---------------------------------------------------------------------------
// K4a: gate hidden
// ---------------------------------------------------------------------------
__global__ __launch_bounds__(256) void gate1_kernel(const float* __restrict__ x,
                                                    const float* __restrict__ w_g1,
                                                    const float* __restrict__ b_g1) {
    const int b = blockIdx.y;
    const int p0 = blockIdx.x * 64;
    const int tid = threadIdx.x;
    const int tx = tid & 15, ty = tid >> 4;

    __shared__ float Ws[32 * 68];   // [c][u]
    __shared__ float Xs[32 * 64];   // [c][p]

    u64 acc2[4][2];
#pragma unroll
    for (int i = 0; i < 4; i++) { acc2[i][0] = 0ull; acc2[i][1] = 0ull; }

    for (int kk = 0; kk < 256; kk += 32) {
#pragma unroll
        for (int t = 0; t < 2; t++) {
            int idx4 = tid + t * 256;
            int uu = idx4 >> 3;
            int cc4 = idx4 & 7;
            float4 wv = *(const float4*)&w_g1[uu * 256 + kk + cc4 * 4];
            Ws[(cc4 * 4 + 0) * 68 + uu] = wv.x;
            Ws[(cc4 * 4 + 1) * 68 + uu] = wv.y;
            Ws[(cc4 * 4 + 2) * 68 + uu] = wv.z;
            Ws[(cc4 * 4 + 3) * 68 + uu] = wv.w;
        }
#pragma unroll
        for (int t = 0; t < 8; t++) {
            int idx = tid + t * 256;
            int cc = idx >> 6;
            int pp = idx & 63;
            int p = p0 + pp;
            int hh = p >> 5;
            int wj = (p & 31) >> 1;
            const float* row = x + ((size_t)(b * 256) + kk + cc) * 1024 + hh * 32;
            Xs[cc * 64 + pp] = fabsf(row[wj] - row[31 - wj]);
        }
        __syncthreads();
#pragma unroll
        for (int c = 0; c < 32; c++) {
            float4 a = *(float4*)&Ws[c * 68 + ty * 4];
            double2 bd = *(const double2*)&Xs[c * 64 + tx * 4];
            u64 b01 = d2u(bd.x), b23 = d2u(bd.y);
            acc2[0][0] = ffma2(dup2(a.x), b01, acc2[0][0]);
            acc2[0][1] = ffma2(dup2(a.x), b23, acc2[0][1]);
            acc2[1][0] = ffma2(dup2(a.y), b01, acc2[1][0]);
            acc2[1][1] = ffma2(dup2(a.y), b23, acc2[1][1]);
            acc2[2][0] = ffma2(dup2(a.z), b01, acc2[2][0]);
            acc2[2][1] = ffma2(dup2(a.z), b23, acc2[2][1]);
            acc2[3][0] = ffma2(dup2(a.w), b01, acc2[3][0]);
            acc2[3][1] = ffma2(dup2(a.w), b23, acc2[3][1]);
        }
        __syncthreads();
    }

#pragma unroll
    for (int ui = 0; ui < 4; ui++) {
        int u = ty * 4 + ui;
        float bias = b_g1[u];
        float2 lo = unpk(acc2[ui][0]), hi = unpk(acc2[ui][1]);
        float v0 = lo.x + bias, v1 = lo.y + bias;
        float v2 = hi.x + bias, v3 = hi.y + bias;
        float4 vout;
        vout.x = 0.5f * v0 * (1.f + erff(v0 * 0.70710678118654752f));
        vout.y = 0.5f * v1 * (1.f + erff(v1 * 0.70710678118654752f));
        vout.z = 0.5f * v2 * (1.f + erff(v2 * 0.70710678118654752f));
        vout.w = 0.5f * v3 * (1.f + erff(v3 * 0.70710678118654752f));
        *(float4*)&g_g1buf[((size_t)(b * 64) + u) * 1024 + p0 + tx * 4] = vout;
    }
}

// ---------------------------------------------------------------------------
// K4b: gate output
// ---------------------------------------------------------------------------
__global__ __launch_bounds__(256) void gate2_kernel(const float* __restrict__ w_g2,
                                                    const float* __restrict__ b_g2) {
    const int idx = blockIdx.x * 256 + threadIdx.x;  // 0..8191
    const int b = idx >> 10;
    const int p = idx & 1023;
    float acc = b_g2[0];
#pragma unroll 8
    for (int u = 0; u < 64; u++)
        acc += g_g1buf[((size_t)(b * 64) + u) * 1024 + p] * w_g2[u];
    g_gate[idx] = 1.f / (1.f + expf(-acc));
}

// ---------------------------------------------------------------------------
// K5: out-proj with gate folded in
// ---------------------------------------------------------------------------
__global__ __launch_bounds__(256) void outproj_kernel(const float* __restrict__ w_out,
                                                      const float* __restrict__ b_out,
                                                      float* __restrict__ out) {
    const int b = blockIdx.z;
    const int o0 = blockIdx.y * 64;
    const int p0 = blockIdx.x * 64;
    const int tid = threadIdx.x;
    const int tx = tid & 15, ty = tid >> 4;

    __shared__ float Ws[32 * 68];
    __shared__ float Xs[32 * 64];
    __shared__ float Gs[64];

    if (tid < 64) Gs[tid] = 1.f + g_gate[b * 1024 + p0 + tid];
    __syncthreads();

    u64 acc2[4][2];
#pragma unroll
    for (int i = 0; i < 4; i++) { acc2[i][0] = 0ull; acc2[i][1] = 0ull; }

    for (int kk = 0; kk < 256; kk += 32) {
#pragma unroll
        for (int t = 0; t < 2; t++) {
            int idx4 = tid + t * 256;
            int oo = idx4 >> 3;
            int cc4 = idx4 & 7;
            float4 wv = *(const float4*)&w_out[(o0 + oo) * 256 + kk + cc4 * 4];
            Ws[(cc4 * 4 + 0) * 68 + oo] = wv.x;
            Ws[(cc4 * 4 + 1) * 68 + oo] = wv.y;
            Ws[(cc4 * 4 + 2) * 68 + oo] = wv.z;
            Ws[(cc4 * 4 + 3) * 68 + oo] = wv.w;
        }
#pragma unroll
        for (int t = 0; t < 2; t++) {
            int idx4 = tid + t * 256;
            int cc = idx4 >> 4;
            int pp4 = idx4 & 15;
            float4 av = *(const float4*)&g_ao[((size_t)(b * 256) + kk + cc) * 1024 + p0 + pp4 * 4];
            av.x *= Gs[pp4 * 4 + 0];
            av.y *= Gs[pp4 * 4 + 1];
            av.z *= Gs[pp4 * 4 + 2];
            av.w *= Gs[pp4 * 4 + 3];
            *(float4*)&Xs[cc * 64 + pp4 * 4] = av;
        }
        __syncthreads();
#pragma unroll
        for (int c = 0; c < 32; c++) {
            float4 a = *(float4*)&Ws[c * 68 + ty * 4];
            double2 bd = *(const double2*)&Xs[c * 64 + tx * 4];
            u64 b01 = d2u(bd.x), b23 = d2u(bd.y);
            acc2[0][0] = ffma2(dup2(a.x), b01, acc2[0][0]);
            acc2[0][1] = ffma2(dup2(a.x), b23, acc2[0][1]);
            acc2[1][0] = ffma2(dup2(a.y), b01, acc2[1][0]);
            acc2[1][1] = ffma2(dup2(a.y), b23, acc2[1][1]);
            acc2[2][0] = ffma2(dup2(a.z), b01, acc2[2][0]);
            acc2[2][1] = ffma2(dup2(a.z), b23, acc2[2][1]);
            acc2[3][0] = ffma2(dup2(a.w), b01, acc2[3][0]);
            acc2[3][1] = ffma2(dup2(a.w), b23, acc2[3][1]);
        }
        __syncthreads();
    }

#pragma unroll
    for (int oi = 0; oi < 4; oi++) {
        int o = o0 + ty * 4 + oi;
        float bias = b_out[o];
        float2 lo = unpk(acc2[oi][0]), hi = unpk(acc2[oi][1]);
        float4 vout = make_float4(lo.x + bias, lo.y + bias, hi.x + bias, hi.y + bias);
        *(float4*)&out[((size_t)(b * 256) + o) * 1024 + p0 + tx * 4] = vout;
    }
}

// ---------------------------------------------------------------------------
extern "C" void kernel_launch(void* const* d_in, const int* in_sizes, int n_in,
                              void* d_out, int out_size) {
    const float* x     = (const float*)d_in[0];
    const float* w_qkv = (const float*)d_in[1];
    const float* w_out = (const float*)d_in[2];
    const float* b_out = (const float*)d_in[3];
    const float* w_g1  = (const float*)d_in[4];
    const float* b_g1  = (const float*)d_in[5];
    const float* w_g2  = (const float*)d_in[6];
    const float* b_g2  = (const float*)d_in[7];
    float* out = (float*)d_out;

    qkv_kernel<<<dim3(16, 12, 8), 256>>>(x, w_qkv);
    colsum_kernel<<<64, 256>>>();
    diag_kernel<<<8, 256>>>();
    attn_kernel<<<dim3(4, 64, 2), 128>>>();
    attn_final_kernel<<<256, 256>>>();
    gate1_kernel<<<dim3(16, 8), 256>>>(x, w_g1, b_g1);
    gate2_kernel<<<32, 256>>>(w_g2, b_g2);
    outproj_kernel<<<dim3(16, 4, 8), 256>>>(w_out, b_out, out);
}

// round 4
// speedup vs baseline: 1.1502x; 1.0420x over previous
#include <cuda_runtime.h>
#include <math.h>

// ---------------------------------------------------------------------------
// DiagonalMicroAttention: b=8, c=256, h=w=32, heads=8, d=32, n=1024
//   K1 qkv GEMM  -> q,k,v in [bh][n][d] layout          (f32x2)
//   K2 colsum(V), diag_vec
//   K3 flash attention: 2 rows/thread, d split across thread pairs,
//      2-way key split (f32x2)  -> partials
//   K3b finalize
//   K4 gate MLP
//   K5 out-proj GEMM with (1+g) gate folded in           (f32x2)
// ---------------------------------------------------------------------------

#define B 8
#define HEADS 8
#define D 32
#define N 1024
#define C 256
#define SCALE 0.1767766952966369f   // 1/sqrt(32)
#define BHND (B * HEADS * N * D)
#define BHN  (B * HEADS * N)

typedef unsigned long long u64;

__device__ __forceinline__ u64 ffma2(u64 a, u64 b, u64 c) {
    u64 d; asm("fma.rn.f32x2 %0,%1,%2,%3;" : "=l"(d) : "l"(a), "l"(b), "l"(c));
    return d;
}
__device__ __forceinline__ u64 pack2(float lo, float hi) {
    u64 r; asm("mov.b64 %0, {%1,%2};" : "=l"(r) : "f"(lo), "f"(hi));
    return r;
}
__device__ __forceinline__ u64 dup2(float v) {
    u64 r; asm("mov.b64 %0, {%1,%1};" : "=l"(r) : "f"(v));
    return r;
}
__device__ __forceinline__ float2 unpk(u64 v) {
    float2 f; asm("mov.b64 {%0,%1}, %2;" : "=f"(f.x), "=f"(f.y) : "l"(v));
    return f;
}
__device__ __forceinline__ u64 d2u(double d) { return __double_as_longlong(d); }

__device__ float g_q[BHND];
__device__ float g_k[BHND];
__device__ float g_v[BHND];
__device__ float g_po[2 * BHND];           // split partial o (unnormalized)
__device__ float g_pl[2 * BHN];            // split partial row sums
__device__ float g_ao[B * C * N];          // attention output, [b][c][n]
__device__ float g_g1buf[B * 64 * N];      // gate hidden
__device__ float g_gate[B * N];            // sigmoid gate per pixel
__device__ float g_dvec[B * D];            // 0.3 * scale/8 * diag sums
__device__ float g_csum[B * HEADS * D];    // column sums of V

// ---------------------------------------------------------------------------
// K1: qkv projection.  Y[b,o,p] = sum_c W[o,c] * x[b,c,p], o in [0,768)
// ---------------------------------------------------------------------------
__global__ __launch_bounds__(256) void qkv_kernel(const float* __restrict__ x,
                                                  const float* __restrict__ w) {
    const int b = blockIdx.z;
    const int o0 = blockIdx.y * 64;
    const int p0 = blockIdx.x * 64;
    const int tid = threadIdx.x;
    const int tx = tid & 15, ty = tid >> 4;

    __shared__ float Ws[32 * 68];   // [c][o], padded
    __shared__ float Xs[32 * 64];   // [c][p]

    u64 acc2[4][2];
#pragma unroll
    for (int i = 0; i < 4; i++) { acc2[i][0] = 0ull; acc2[i][1] = 0ull; }

    for (int kk = 0; kk < 256; kk += 32) {
#pragma unroll
        for (int t = 0; t < 2; t++) {
            int idx4 = tid + t * 256;
            int oo = idx4 >> 3;
            int cc4 = idx4 & 7;
            float4 wv = *(const float4*)&w[(o0 + oo) * 256 + kk + cc4 * 4];
            Ws[(cc4 * 4 + 0) * 68 + oo] = wv.x;
            Ws[(cc4 * 4 + 1) * 68 + oo] = wv.y;
            Ws[(cc4 * 4 + 2) * 68 + oo] = wv.z;
            Ws[(cc4 * 4 + 3) * 68 + oo] = wv.w;
        }
#pragma unroll
        for (int t = 0; t < 2; t++) {
            int idx4 = tid + t * 256;
            int cc = idx4 >> 4;
            int pp4 = idx4 & 15;
            *(float4*)&Xs[cc * 64 + pp4 * 4] =
                *(const float4*)&x[((b * 256) + kk + cc) * 1024 + p0 + pp4 * 4];
        }
        __syncthreads();
#pragma unroll
        for (int c = 0; c < 32; c++) {
            float4 a = *(float4*)&Ws[c * 68 + tx * 4];
            double2 bd = *(const double2*)&Xs[c * 64 + ty * 4];
            u64 b01 = d2u(bd.x), b23 = d2u(bd.y);
            acc2[0][0] = ffma2(dup2(a.x), b01, acc2[0][0]);
            acc2[0][1] = ffma2(dup2(a.x), b23, acc2[0][1]);
            acc2[1][0] = ffma2(dup2(a.y), b01, acc2[1][0]);
            acc2[1][1] = ffma2(dup2(a.y), b23, acc2[1][1]);
            acc2[2][0] = ffma2(dup2(a.z), b01, acc2[2][0]);
            acc2[2][1] = ffma2(dup2(a.z), b23, acc2[2][1]);
            acc2[3][0] = ffma2(dup2(a.w), b01, acc2[3][0]);
            acc2[3][1] = ffma2(dup2(a.w), b23, acc2[3][1]);
        }
        __syncthreads();
    }

    float acc[4][4];
#pragma unroll
    for (int i = 0; i < 4; i++) {
        float2 lo = unpk(acc2[i][0]), hi = unpk(acc2[i][1]);
        acc[i][0] = lo.x; acc[i][1] = lo.y; acc[i][2] = hi.x; acc[i][3] = hi.y;
    }

    const int ob = o0 + tx * 4;
    const int part = ob >> 8;
    const int ci = ob & 255;
    const int head = ci >> 5;
    const int dd = ci & 31;
    float* dst = (part == 0) ? g_q : ((part == 1) ? g_k : g_v);
    float* base = dst + (((size_t)(b * 8 + head) * 1024)) * 32 + dd;
#pragma unroll
    for (int pj = 0; pj < 4; pj++) {
        int p = p0 + ty * 4 + pj;
        float4 val = make_float4(acc[0][pj], acc[1][pj], acc[2][pj], acc[3][pj]);
        *(float4*)&base[(size_t)p * 32] = val;
    }
}

// ---------------------------------------------------------------------------
// K2a: column sums of V per (b,h)
// ---------------------------------------------------------------------------
__global__ __launch_bounds__(256) void colsum_kernel() {
    const int bh = blockIdx.x;
    const int tid = threadIdx.x;
    const int dd = tid & 31;
    const int sl = tid >> 5;
    const float* vb = g_v + (size_t)bh * 1024 * 32;
    float s = 0.f;
    for (int j = sl * 128; j < sl * 128 + 128; j++) s += vb[(size_t)j * 32 + dd];
    __shared__ float red[256];
    red[tid] = s;
    __syncthreads();
    if (tid < 32) {
        float t = 0.f;
#pragma unroll
        for (int r = 0; r < 8; r++) t += red[tid + r * 32];
        g_csum[bh * 32 + tid] = t;
    }
}

// ---------------------------------------------------------------------------
// K2b: diag_vec
// ---------------------------------------------------------------------------
__global__ __launch_bounds__(256) void diag_kernel() {
    const int b = blockIdx.x;
    const int tid = threadIdx.x;
    const int i = tid & 31;
    const int h = tid >> 5;
    const size_t base = ((size_t)(b * 8 + h) * 1024) * 32;
    float s = 0.f;
#pragma unroll 4
    for (int ss = 0; ss < 32; ss++) {
        size_t off = base + (size_t)(ss * 33) * 32 + i;
        s += g_q[off] * g_k[off];
    }
    __shared__ float red[256];
    red[tid] = s;
    __syncthreads();
    if (tid < 32) {
        float t = 0.f;
#pragma unroll
        for (int r = 0; r < 8; r++) t += red[tid + r * 32];
        g_dvec[b * 32 + tid] = t * (0.3f * SCALE / 8.0f);
    }
}

// ---------------------------------------------------------------------------
// K3: flash attention. Thread = (query pair, d-half). Lanes 2k/2k+1 hold the
// two d-halves of the same query pair -> shfl.bfly(1) completes the logit.
// CTA covers 128 queries; grid (8 qtiles, 64 bh, 2 key-splits).
// ---------------------------------------------------------------------------
__global__ __launch_bounds__(128) void attn_kernel() {
    const int bh = blockIdx.y;
    const int sp = blockIdx.z;
    const int qp = threadIdx.x >> 1;          // 0..63
    const int dh = threadIdx.x & 1;           // d-half
    const int i0 = blockIdx.x * 128 + qp;
    const int i1 = i0 + 64;

    const float* qbase = g_q + (size_t)bh * 1024 * 32;
    u64 qa2[8], qb2[8];
    {
        const float4* qa = (const float4*)(qbase + (size_t)i0 * 32 + dh * 16);
        const float4* qb = (const float4*)(qbase + (size_t)i1 * 32 + dh * 16);
#pragma unroll
        for (int t = 0; t < 4; t++) {
            float4 v = qa[t];
            qa2[2 * t + 0] = pack2(v.x * SCALE, v.y * SCALE);
            qa2[2 * t + 1] = pack2(v.z * SCALE, v.w * SCALE);
            float4 w = qb[t];
            qb2[2 * t + 0] = pack2(w.x * SCALE, w.y * SCALE);
            qb2[2 * t + 1] = pack2(w.z * SCALE, w.w * SCALE);
        }
    }

    u64 oa2[8], ob2[8];
#pragma unroll
    for (int d = 0; d < 8; d++) { oa2[d] = 0ull; ob2[d] = 0ull; }
    float la = 0.f, lb = 0.f;

    __shared__ float Ks[128 * 32];
    __shared__ float Vs[128 * 32];
    const float4* kg = (const float4*)(g_k + (size_t)bh * 1024 * 32);
    const float4* vg = (const float4*)(g_v + (size_t)bh * 1024 * 32);

    for (int t0 = sp * 4; t0 < sp * 4 + 4; t0++) {
        const int off4 = t0 * 128 * 8;
#pragma unroll
        for (int r = 0; r < 8; r++) {
            ((float4*)Ks)[threadIdx.x + r * 128] = kg[off4 + threadIdx.x + r * 128];
            ((float4*)Vs)[threadIdx.x + r * 128] = vg[off4 + threadIdx.x + r * 128];
        }
        __syncthreads();
#pragma unroll 2
        for (int j = 0; j < 128; j++) {
            const double2* kr = (const double2*)(Ks + j * 32 + dh * 16);
            u64 aA = 0ull, aB = 0ull, bA = 0ull, bB = 0ull;
#pragma unroll
            for (int t2 = 0; t2 < 4; t2++) {
                double2 kk = kr[t2];
                u64 kx = d2u(kk.x), ky = d2u(kk.y);
                aA = ffma2(qa2[2 * t2 + 0], kx, aA);
                aB = ffma2(qa2[2 * t2 + 1], ky, aB);
                bA = ffma2(qb2[2 * t2 + 0], kx, bA);
                bB = ffma2(qb2[2 * t2 + 1], ky, bB);
            }
            float2 fa = unpk(aA), fb = unpk(aB);
            float sah = (fa.x + fa.y) + (fb.x + fb.y);
            float2 ga = unpk(bA), gb = unpk(bB);
            float sbh = (ga.x + ga.y) + (gb.x + gb.y);
            float sa = sah + __shfl_xor_sync(0xffffffffu, sah, 1);
            float sb = sbh + __shfl_xor_sync(0xffffffffu, sbh, 1);
            float pa = __expf(sa);
            float pb = __expf(sb);
            la += pa;
            lb += pb;
            u64 pa2 = dup2(pa), pb2 = dup2(pb);
            const double2* vr = (const double2*)(Vs + j * 32 + dh * 16);
#pragma unroll
            for (int t2 = 0; t2 < 4; t2++) {
                double2 vv = vr[t2];
                u64 vx = d2u(vv.x), vy = d2u(vv.y);
                oa2[2 * t2 + 0] = ffma2(pa2, vx, oa2[2 * t2 + 0]);
                oa2[2 * t2 + 1] = ffma2(pa2, vy, oa2[2 * t2 + 1]);
                ob2[2 * t2 + 0] = ffma2(pb2, vx, ob2[2 * t2 + 0]);
                ob2[2 * t2 + 1] = ffma2(pb2, vy, ob2[2 * t2 + 1]);
            }
        }
        __syncthreads();
    }

    float* dstA = g_po + (size_t)sp * BHND + ((size_t)bh * 1024 + i0) * 32 + dh * 16;
    float* dstB = g_po + (size_t)sp * BHND + ((size_t)bh * 1024 + i1) * 32 + dh * 16;
#pragma unroll
    for (int t = 0; t < 4; t++) {
        float2 l0 = unpk(oa2[2 * t + 0]), h0 = unpk(oa2[2 * t + 1]);
        *(float4*)&dstA[4 * t] = make_float4(l0.x, l0.y, h0.x, h0.y);
        float2 l1 = unpk(ob2[2 * t + 0]), h1 = unpk(ob2[2 * t + 1]);
        *(float4*)&dstB[4 * t] = make_float4(l1.x, l1.y, h1.x, h1.y);
    }
    if (dh == 0) {
        g_pl[sp * BHN + bh * 1024 + i0] = la;
        g_pl[sp * BHN + bh * 1024 + i1] = lb;
    }
}

// ---------------------------------------------------------------------------
// K3b: finalize — combine splits, normalize, add diag term, transpose store.
// ---------------------------------------------------------------------------
__global__ __launch_bounds__(256) void attn_final_kernel() {
    const int idx = blockIdx.x * 256 + threadIdx.x;   // 0..65535
    const int bh = idx >> 10;
    const int i = idx & 1023;
    const int b = bh >> 3;
    const int head = bh & 7;

    const float l = g_pl[idx] + g_pl[BHN + idx];
    const float inv = 1.f / l;
    const float dv = (i < 32) ? g_dvec[b * 32 + i] : 0.f;
    const float* cs = g_csum + bh * 32;
    const float4* p0 = (const float4*)(g_po + ((size_t)bh * 1024 + i) * 32);
    const float4* p1 = (const float4*)(g_po + (size_t)BHND + ((size_t)bh * 1024 + i) * 32);
    float* obase = g_ao + ((size_t)b * 256 + head * 32) * 1024 + i;
#pragma unroll
    for (int t = 0; t < 8; t++) {
        float4 a = p0[t];
        float4 c = p1[t];
        obase[(size_t)(4 * t + 0) * 1024] = (a.x + c.x) * inv + dv * cs[4 * t + 0];
        obase[(size_t)(4 * t + 1) * 1024] = (a.y + c.y) * inv + dv * cs[4 * t + 1];
        obase[(size_t)(4 * t + 2) * 1024] = (a.z + c.z) * inv + dv * cs[4 * t + 2];
        obase[(size_t)(4 * t + 3) * 1024] = (a.w + c.w) * inv + dv * cs[4 * t + 3];
    }
}

// ---------------------------------------------------------------------------
// K4a: gate hidden
// ---------------------------------------------------------------------------
__global__ __launch_bounds__(256) void gate1_kernel(const float* __restrict__ x,
                                                    const float* __restrict__ w_g1,
                                                    const float* __restrict__ b_g1) {
    const int b = blockIdx.y;
    const int p0 = blockIdx.x * 64;
    const int tid = threadIdx.x;
    const int tx = tid & 15, ty = tid >> 4;

    __shared__ float Ws[32 * 68];   // [c][u]
    __shared__ float Xs[32 * 64];   // [c][p]

    u64 acc2[4][2];
#pragma unroll
    for (int i = 0; i < 4; i++) { acc2[i][0] = 0ull; acc2[i][1] = 0ull; }

    for (int kk = 0; kk < 256; kk += 32) {
#pragma unroll
        for (int t = 0; t < 2; t++) {
            int idx4 = tid + t * 256;
            int uu = idx4 >> 3;
            int cc4 = idx4 & 7;
            float4 wv = *(const float4*)&w_g1[uu * 256 + kk + cc4 * 4];
            Ws[(cc4 * 4 + 0) * 68 + uu] = wv.x;
            Ws[(cc4 * 4 + 1) * 68 + uu] = wv.y;
            Ws[(cc4 * 4 + 2) * 68 + uu] = wv.z;
            Ws[(cc4 * 4 + 3) * 68 + uu] = wv.w;
        }
#pragma unroll
        for (int t = 0; t < 8; t++) {
            int idx = tid + t * 256;
            int cc = idx >> 6;
            int pp = idx & 63;
            int p = p0 + pp;
            int hh = p >> 5;
            int wj = (p & 31) >> 1;
            const float* row = x + ((size_t)(b * 256) + kk + cc) * 1024 + hh * 32;
            Xs[cc * 64 + pp] = fabsf(row[wj] - row[31 - wj]);
        }
        __syncthreads();
#pragma unroll
        for (int c = 0; c < 32; c++) {
            float4 a = *(float4*)&Ws[c * 68 + ty * 4];
            double2 bd = *(const double2*)&Xs[c * 64 + tx * 4];
            u64 b01 = d2u(bd.x), b23 = d2u(bd.y);
            acc2[0][0] = ffma2(dup2(a.x), b01, acc2[0][0]);
            acc2[0][1] = ffma2(dup2(a.x), b23, acc2[0][1]);
            acc2[1][0] = ffma2(dup2(a.y), b01, acc2[1][0]);
            acc2[1][1] = ffma2(dup2(a.y), b23, acc2[1][1]);
            acc2[2][0] = ffma2(dup2(a.z), b01, acc2[2][0]);
            acc2[2][1] = ffma2(dup2(a.z), b23, acc2[2][1]);
            acc2[3][0] = ffma2(dup2(a.w), b01, acc2[3][0]);
            acc2[3][1] = ffma2(dup2(a.w), b23, acc2[3][1]);
        }
        __syncthreads();
    }

#pragma unroll
    for (int ui = 0; ui < 4; ui++) {
        int u = ty * 4 + ui;
        float bias = b_g1[u];
        float2 lo = unpk(acc2[ui][0]), hi = unpk(acc2[ui][1]);
        float v0 = lo.x + bias, v1 = lo.y + bias;
        float v2 = hi.x + bias, v3 = hi.y + bias;
        float4 vout;
        vout.x = 0.5f * v0 * (1.f + erff(v0 * 0.70710678118654752f));
        vout.y = 0.5f * v1 * (1.f + erff(v1 * 0.70710678118654752f));
        vout.z = 0.5f * v2 * (1.f + erff(v2 * 0.70710678118654752f));
        vout.w = 0.5f * v3 * (1.f + erff(v3 * 0.70710678118654752f));
        *(float4*)&g_g1buf[((size_t)(b * 64) + u) * 1024 + p0 + tx * 4] = vout;
    }
}

// ---------------------------------------------------------------------------
// K4b: gate output
// ---------------------------------------------------------------------------
__global__ __launch_bounds__(256) void gate2_kernel(const float* __restrict__ w_g2,
                                                    const float* __restrict__ b_g2) {
    const int idx = blockIdx.x * 256 + threadIdx.x;  // 0..8191
    const int b = idx >> 10;
    const int p = idx & 1023;
    float acc = b_g2[0];
#pragma unroll 8
    for (int u = 0; u < 64; u++)
        acc += g_g1buf[((size_t)(b * 64) + u) * 1024 + p] * w_g2[u];
    g_gate[idx] = 1.f / (1.f + expf(-acc));
}

// ---------------------------------------------------------------------------
// K5: out-proj with gate folded in
// ---------------------------------------------------------------------------
__global__ __launch_bounds__(256) void outproj_kernel(const float* __restrict__ w_out,
                                                      const float* __restrict__ b_out,
                                                      float* __restrict__ out) {
    const int b = blockIdx.z;
    const int o0 = blockIdx.y * 64;
    const int p0 = blockIdx.x * 64;
    const int tid = threadIdx.x;
    const int tx = tid & 15, ty = tid >> 4;

    __shared__ float Ws[32 * 68];
    __shared__ float Xs[32 * 64];
    __shared__ float Gs[64];

    if (tid < 64) Gs[tid] = 1.f + g_gate[b * 1024 + p0 + tid];
    __syncthreads();

    u64 acc2[4][2];
#pragma unroll
    for (int i = 0; i < 4; i++) { acc2[i][0] = 0ull; acc2[i][1] = 0ull; }

    for (int kk = 0; kk < 256; kk += 32) {
#pragma unroll
        for (int t = 0; t < 2; t++) {
            int idx4 = tid + t * 256;
            int oo = idx4 >> 3;
            int cc4 = idx4 & 7;
            float4 wv = *(const float4*)&w_out[(o0 + oo) * 256 + kk + cc4 * 4];
            Ws[(cc4 * 4 + 0) * 68 + oo] = wv.x;
            Ws[(cc4 * 4 + 1) * 68 + oo] = wv.y;
            Ws[(cc4 * 4 + 2) * 68 + oo] = wv.z;
            Ws[(cc4 * 4 + 3) * 68 + oo] = wv.w;
        }
#pragma unroll
        for (int t = 0; t < 2; t++) {
            int idx4 = tid + t * 256;
            int cc = idx4 >> 4;
            int pp4 = idx4 & 15;
            float4 av = *(const float4*)&g_ao[((size_t)(b * 256) + kk + cc) * 1024 + p0 + pp4 * 4];
            av.x *= Gs[pp4 * 4 + 0];
            av.y *= Gs[pp4 * 4 + 1];
            av.z *= Gs[pp4 * 4 + 2];
            av.w *= Gs[pp4 * 4 + 3];
            *(float4*)&Xs[cc * 64 + pp4 * 4] = av;
        }
        __syncthreads();
#pragma unroll
        for (int c = 0; c < 32; c++) {
            float4 a = *(float4*)&Ws[c * 68 + ty * 4];
            double2 bd = *(const double2*)&Xs[c * 64 + tx * 4];
            u64 b01 = d2u(bd.x), b23 = d2u(bd.y);
            acc2[0][0] = ffma2(dup2(a.x), b01, acc2[0][0]);
            acc2[0][1] = ffma2(dup2(a.x), b23, acc2[0][1]);
            acc2[1][0] = ffma2(dup2(a.y), b01, acc2[1][0]);
            acc2[1][1] = ffma2(dup2(a.y), b23, acc2[1][1]);
            acc2[2][0] = ffma2(dup2(a.z), b01, acc2[2][0]);
            acc2[2][1] = ffma2(dup2(a.z), b23, acc2[2][1]);
            acc2[3][0] = ffma2(dup2(a.w), b01, acc2[3][0]);
            acc2[3][1] = ffma2(dup2(a.w), b23, acc2[3][1]);
        }
        __syncthreads();
    }

#pragma unroll
    for (int oi = 0; oi < 4; oi++) {
        int o = o0 + ty * 4 + oi;
        float bias = b_out[o];
        float2 lo = unpk(acc2[oi][0]), hi = unpk(acc2[oi][1]);
        float4 vout = make_float4(lo.x + bias, lo.y + bias, hi.x + bias, hi.y + bias);
        *(float4*)&out[((size_t)(b * 256) + o) * 1024 + p0 + tx * 4] = vout;
    }
}

// ---------------------------------------------------------------------------
extern "C" void kernel_launch(void* const* d_in, const int* in_sizes, int n_in,
                              void* d_out, int out_size) {
    const float* x     = (const float*)d_in[0];
    const float* w_qkv = (const float*)d_in[1];
    const float* w_out = (const float*)d_in[2];
    const float* b_out = (const float*)d_in[3];
    const float* w_g1  = (const float*)d_in[4];
    const float* b_g1  = (const float*)d_in[5];
    const float* w_g2  = (const float*)d_in[6];
    const float* b_g2  = (const float*)d_in[7];
    float* out = (float*)d_out;

    qkv_kernel<<<dim3(16, 12, 8), 256>>>(x, w_qkv);
    colsum_kernel<<<64, 256>>>();
    diag_kernel<<<8, 256>>>();
    attn_kernel<<<dim3(8, 64, 2), 128>>>();
    attn_final_kernel<<<256, 256>>>();
    gate1_kernel<<<dim3(16, 8), 256>>>(x, w_g1, b_g1);
    gate2_kernel<<<32, 256>>>(w_g2, b_g2);
    outproj_kernel<<<dim3(16, 4, 8), 256>>>(w_out, b_out, out);
}

// round 5
// speedup vs baseline: 1.8773x; 1.6321x over previous
#include <cuda_runtime.h>
#include <math.h>
#include <stdint.h>

// ---------------------------------------------------------------------------
// DiagonalMicroAttention: b=8, c=256, h=w=32, heads=8, d=32, n=1024
//   K1 qkv GEMM  -> q,k,v in [bh][n][d] layout          (f32x2)
//   K2 colsum(V), diag_vec
//   K3 flash attention via tf32 mma.sync (m16n8k8), fused epilogue
//   K4 gate MLP
//   K5 out-proj GEMM with (1+g) gate folded in           (f32x2)
// ---------------------------------------------------------------------------

#define B 8
#define HEADS 8
#define D 32
#define N 1024
#define C 256
#define SCALE 0.1767766952966369f   // 1/sqrt(32)
#define BHND (B * HEADS * N * D)

typedef unsigned long long u64;

__device__ __forceinline__ u64 ffma2(u64 a, u64 b, u64 c) {
    u64 d; asm("fma.rn.f32x2 %0,%1,%2,%3;" : "=l"(d) : "l"(a), "l"(b), "l"(c));
    return d;
}
__device__ __forceinline__ u64 dup2(float v) {
    u64 r; asm("mov.b64 %0, {%1,%1};" : "=l"(r) : "f"(v));
    return r;
}
__device__ __forceinline__ float2 unpk(u64 v) {
    float2 f; asm("mov.b64 {%0,%1}, %2;" : "=f"(f.x), "=f"(f.y) : "l"(v));
    return f;
}
__device__ __forceinline__ u64 d2u(double d) { return __double_as_longlong(d); }

__device__ __forceinline__ uint32_t f2tf(float f) {
    uint32_t r; asm("cvt.rna.tf32.f32 %0, %1;" : "=r"(r) : "f"(f));
    return r;
}
__device__ __forceinline__ void mma_tf32(float& d0, float& d1, float& d2, float& d3,
                                         uint32_t a0, uint32_t a1, uint32_t a2, uint32_t a3,
                                         uint32_t b0, uint32_t b1) {
    asm("mma.sync.aligned.m16n8k8.row.col.f32.tf32.tf32.f32 "
        "{%0,%1,%2,%3}, {%4,%5,%6,%7}, {%8,%9}, {%0,%1,%2,%3};"
        : "+f"(d0), "+f"(d1), "+f"(d2), "+f"(d3)
        : "r"(a0), "r"(a1), "r"(a2), "r"(a3), "r"(b0), "r"(b1));
}

__device__ float g_q[BHND];
__device__ float g_k[BHND];
__device__ float g_v[BHND];
__device__ float g_ao[B * C * N];          // attention output, [b][c][n]
__device__ float g_g1buf[B * 64 * N];      // gate hidden
__device__ float g_gate[B * N];            // sigmoid gate per pixel
__device__ float g_dvec[B * D];            // 0.3 * scale/8 * diag sums
__device__ float g_csum[B * HEADS * D];    // column sums of V

// ---------------------------------------------------------------------------
// K1: qkv projection.  Y[b,o,p] = sum_c W[o,c] * x[b,c,p], o in [0,768)
// ---------------------------------------------------------------------------
__global__ __launch_bounds__(256) void qkv_kernel(const float* __restrict__ x,
                                                  const float* __restrict__ w) {
    const int b = blockIdx.z;
    const int o0 = blockIdx.y * 64;
    const int p0 = blockIdx.x * 64;
    const int tid = threadIdx.x;
    const int tx = tid & 15, ty = tid >> 4;

    __shared__ float Ws[32 * 68];   // [c][o], padded
    __shared__ float Xs[32 * 64];   // [c][p]

    u64 acc2[4][2];
#pragma unroll
    for (int i = 0; i < 4; i++) { acc2[i][0] = 0ull; acc2[i][1] = 0ull; }

    for (int kk = 0; kk < 256; kk += 32) {
#pragma unroll
        for (int t = 0; t < 2; t++) {
            int idx4 = tid + t * 256;
            int oo = idx4 >> 3;
            int cc4 = idx4 & 7;
            float4 wv = *(const float4*)&w[(o0 + oo) * 256 + kk + cc4 * 4];
            Ws[(cc4 * 4 + 0) * 68 + oo] = wv.x;
            Ws[(cc4 * 4 + 1) * 68 + oo] = wv.y;
            Ws[(cc4 * 4 + 2) * 68 + oo] = wv.z;
            Ws[(cc4 * 4 + 3) * 68 + oo] = wv.w;
        }
#pragma unroll
        for (int t = 0; t < 2; t++) {
            int idx4 = tid + t * 256;
            int cc = idx4 >> 4;
            int pp4 = idx4 & 15;
            *(float4*)&Xs[cc * 64 + pp4 * 4] =
                *(const float4*)&x[((b * 256) + kk + cc) * 1024 + p0 + pp4 * 4];
        }
        __syncthreads();
#pragma unroll
        for (int c = 0; c < 32; c++) {
            float4 a = *(float4*)&Ws[c * 68 + tx * 4];
            double2 bd = *(const double2*)&Xs[c * 64 + ty * 4];
            u64 b01 = d2u(bd.x), b23 = d2u(bd.y);
            acc2[0][0] = ffma2(dup2(a.x), b01, acc2[0][0]);
            acc2[0][1] = ffma2(dup2(a.x), b23, acc2[0][1]);
            acc2[1][0] = ffma2(dup2(a.y), b01, acc2[1][0]);
            acc2[1][1] = ffma2(dup2(a.y), b23, acc2[1][1]);
            acc2[2][0] = ffma2(dup2(a.z), b01, acc2[2][0]);
            acc2[2][1] = ffma2(dup2(a.z), b23, acc2[2][1]);
            acc2[3][0] = ffma2(dup2(a.w), b01, acc2[3][0]);
            acc2[3][1] = ffma2(dup2(a.w), b23, acc2[3][1]);
        }
        __syncthreads();
    }

    float acc[4][4];
#pragma unroll
    for (int i = 0; i < 4; i++) {
        float2 lo = unpk(acc2[i][0]), hi = unpk(acc2[i][1]);
        acc[i][0] = lo.x; acc[i][1] = lo.y; acc[i][2] = hi.x; acc[i][3] = hi.y;
    }

    const int ob = o0 + tx * 4;
    const int part = ob >> 8;
    const int ci = ob & 255;
    const int head = ci >> 5;
    const int dd = ci & 31;
    float* dst = (part == 0) ? g_q : ((part == 1) ? g_k : g_v);
    float* base = dst + (((size_t)(b * 8 + head) * 1024)) * 32 + dd;
#pragma unroll
    for (int pj = 0; pj < 4; pj++) {
        int p = p0 + ty * 4 + pj;
        float4 val = make_float4(acc[0][pj], acc[1][pj], acc[2][pj], acc[3][pj]);
        *(float4*)&base[(size_t)p * 32] = val;
    }
}

// ---------------------------------------------------------------------------
// K2a: column sums of V per (b,h)
// ---------------------------------------------------------------------------
__global__ __launch_bounds__(256) void colsum_kernel() {
    const int bh = blockIdx.x;
    const int tid = threadIdx.x;
    const int dd = tid & 31;
    const int sl = tid >> 5;
    const float* vb = g_v + (size_t)bh * 1024 * 32;
    float s = 0.f;
    for (int j = sl * 128; j < sl * 128 + 128; j++) s += vb[(size_t)j * 32 + dd];
    __shared__ float red[256];
    red[tid] = s;
    __syncthreads();
    if (tid < 32) {
        float t = 0.f;
#pragma unroll
        for (int r = 0; r < 8; r++) t += red[tid + r * 32];
        g_csum[bh * 32 + tid] = t;
    }
}

// ---------------------------------------------------------------------------
// K2b: diag_vec
// ---------------------------------------------------------------------------
__global__ __launch_bounds__(256) void diag_kernel() {
    const int b = blockIdx.x;
    const int tid = threadIdx.x;
    const int i = tid & 31;
    const int h = tid >> 5;
    const size_t base = ((size_t)(b * 8 + h) * 1024) * 32;
    float s = 0.f;
#pragma unroll 4
    for (int ss = 0; ss < 32; ss++) {
        size_t off = base + (size_t)(ss * 33) * 32 + i;
        s += g_q[off] * g_k[off];
    }
    __shared__ float red[256];
    red[tid] = s;
    __syncthreads();
    if (tid < 32) {
        float t = 0.f;
#pragma unroll
        for (int r = 0; r < 8; r++) t += red[tid + r * 32];
        g_dvec[b * 32 + tid] = t * (0.3f * SCALE / 8.0f);
    }
}

// ---------------------------------------------------------------------------
// K3: tf32 tensor-core flash attention.
// CTA = 256 thr = 8 warps; warp owns 16 query rows (CTA covers 128).
// K/V tiles of 128 keys staged in SMEM, pre-converted to tf32 bits.
// Per 8-key chunk: S[16,8] = Q@K^T via 4 mma; p = exp(S) (tf32-rounded, so
// l matches the MMA numerator); P C-frag -> A-frag via shfl; O += P@V via
// 4 mma. Epilogue: reduce l over the 4-thread group, normalize, add
// dvec*csum, scatter-store to [b][c][n].
// ---------------------------------------------------------------------------
#define KPAD 36
#define VPAD 40

__global__ __launch_bounds__(256) void attn_kernel() {
    const int bh = blockIdx.y;
    const int b = bh >> 3;
    const int head = bh & 7;
    const int tid = threadIdx.x;
    const int warp = tid >> 5;
    const int lane = tid & 31;
    const int gid = lane >> 2;
    const int tig = lane & 3;
    const int q0 = blockIdx.x * 128 + warp * 16;

    __shared__ uint32_t Ks[128 * KPAD];
    __shared__ uint32_t Vs[128 * VPAD];

    // Q A-fragments (held in registers the whole kernel), scaled + tf32.
    const float* qb = g_q + (size_t)bh * (N * D);
    uint32_t qa[4][4];
#pragma unroll
    for (int kc = 0; kc < 4; kc++) {
        qa[kc][0] = f2tf(qb[(q0 + gid) * 32 + kc * 8 + tig] * SCALE);
        qa[kc][1] = f2tf(qb[(q0 + gid + 8) * 32 + kc * 8 + tig] * SCALE);
        qa[kc][2] = f2tf(qb[(q0 + gid) * 32 + kc * 8 + tig + 4] * SCALE);
        qa[kc][3] = f2tf(qb[(q0 + gid + 8) * 32 + kc * 8 + tig + 4] * SCALE);
    }

    float o[4][4];
#pragma unroll
    for (int nt = 0; nt < 4; nt++)
#pragma unroll
        for (int r = 0; r < 4; r++) o[nt][r] = 0.f;
    float llo = 0.f, lhi = 0.f;

    const float* kgl = g_k + (size_t)bh * (N * D);
    const float* vgl = g_v + (size_t)bh * (N * D);
    const int src0 = (lane & 28) | (tig >> 1);
    const bool odd = (tig & 1);

    for (int t0 = 0; t0 < 8; t0++) {
        // stage 128-key K/V tile, converting to tf32 bits
#pragma unroll
        for (int r = 0; r < 4; r++) {
            int idx4 = tid + r * 256;           // 0..1023
            int key = idx4 >> 3, c4 = (idx4 & 7) * 4;
            int goff = t0 * 4096 + key * 32 + c4;
            float4 kv = *(const float4*)&kgl[goff];
            *(uint4*)&Ks[key * KPAD + c4] =
                make_uint4(f2tf(kv.x), f2tf(kv.y), f2tf(kv.z), f2tf(kv.w));
            float4 vv = *(const float4*)&vgl[goff];
            *(uint4*)&Vs[key * VPAD + c4] =
                make_uint4(f2tf(vv.x), f2tf(vv.y), f2tf(vv.z), f2tf(vv.w));
        }
        __syncthreads();

#pragma unroll 2
        for (int kch = 0; kch < 16; kch++) {
            const int key0 = kch * 8;
            // ---- QK^T: S[16,8] ----
            float s0 = 0.f, s1 = 0.f, s2 = 0.f, s3 = 0.f;
            const uint32_t* kr = &Ks[(key0 + gid) * KPAD + tig];
#pragma unroll
            for (int kc = 0; kc < 4; kc++) {
                uint32_t kb0 = kr[kc * 8];
                uint32_t kb1 = kr[kc * 8 + 4];
                mma_tf32(s0, s1, s2, s3,
                         qa[kc][0], qa[kc][1], qa[kc][2], qa[kc][3], kb0, kb1);
            }
            // ---- softmax weights (tf32-rounded so numerator == denominator) ----
            uint32_t p0 = f2tf(__expf(s0));
            uint32_t p1 = f2tf(__expf(s1));
            uint32_t p2 = f2tf(__expf(s2));
            uint32_t p3 = f2tf(__expf(s3));
            llo += __uint_as_float(p0) + __uint_as_float(p1);
            lhi += __uint_as_float(p2) + __uint_as_float(p3);
            // ---- C-frag -> A-frag permutation ----
            uint32_t e0, e1;
            e0 = __shfl_sync(0xffffffffu, p0, src0);
            e1 = __shfl_sync(0xffffffffu, p1, src0);
            uint32_t pa0 = odd ? e1 : e0;
            e0 = __shfl_sync(0xffffffffu, p0, src0 + 2);
            e1 = __shfl_sync(0xffffffffu, p1, src0 + 2);
            uint32_t pa2 = odd ? e1 : e0;
            e0 = __shfl_sync(0xffffffffu, p2, src0);
            e1 = __shfl_sync(0xffffffffu, p3, src0);
            uint32_t pa1 = odd ? e1 : e0;
            e0 = __shfl_sync(0xffffffffu, p2, src0 + 2);
            e1 = __shfl_sync(0xffffffffu, p3, src0 + 2);
            uint32_t pa3 = odd ? e1 : e0;
            // ---- P @ V ----
            const uint32_t* vr0 = &Vs[(key0 + tig) * VPAD + gid];
            const uint32_t* vr1 = &Vs[(key0 + tig + 4) * VPAD + gid];
#pragma unroll
            for (int nt = 0; nt < 4; nt++) {
                uint32_t vb0 = vr0[nt * 8];
                uint32_t vb1 = vr1[nt * 8];
                mma_tf32(o[nt][0], o[nt][1], o[nt][2], o[nt][3],
                         pa0, pa1, pa2, pa3, vb0, vb1);
            }
        }
        __syncthreads();
    }

    // reduce l across the 4-thread group
    llo += __shfl_xor_sync(0xffffffffu, llo, 1);
    llo += __shfl_xor_sync(0xffffffffu, llo, 2);
    lhi += __shfl_xor_sync(0xffffffffu, lhi, 1);
    lhi += __shfl_xor_sync(0xffffffffu, lhi, 2);
    const float invlo = 1.f / llo;
    const float invhi = 1.f / lhi;

    const int rlo = q0 + gid;
    const int rhi = rlo + 8;
    const float dvlo = (rlo < 32) ? g_dvec[b * 32 + rlo] : 0.f;
    const float dvhi = (rhi < 32) ? g_dvec[b * 32 + rhi] : 0.f;
    const float* cs = g_csum + bh * 32;
    float* ob = g_ao + ((size_t)b * 256 + head * 32) * 1024;
#pragma unroll
    for (int nt = 0; nt < 4; nt++) {
        int c0 = nt * 8 + 2 * tig;
        int c1 = c0 + 1;
        float cs0 = cs[c0], cs1 = cs[c1];
        ob[(size_t)c0 * 1024 + rlo] = o[nt][0] * invlo + dvlo * cs0;
        ob[(size_t)c1 * 1024 + rlo] = o[nt][1] * invlo + dvlo * cs1;
        ob[(size_t)c0 * 1024 + rhi] = o[nt][2] * invhi + dvhi * cs0;
        ob[(size_t)c1 * 1024 + rhi] = o[nt][3] * invhi + dvhi * cs1;
    }
}

// ---------------------------------------------------------------------------
// K4a: gate hidden
// ---------------------------------------------------------------------------
__global__ __launch_bounds__(256) void gate1_kernel(const float* __restrict__ x,
                                                    const float* __restrict__ w_g1,
                                                    const float* __restrict__ b_g1) {
    const int b = blockIdx.y;
    const int p0 = blockIdx.x * 64;
    const int tid = threadIdx.x;
    const int tx = tid & 15, ty = tid >> 4;

    __shared__ float Ws[32 * 68];   // [c][u]
    __shared__ float Xs[32 * 64];   // [c][p]

    u64 acc2[4][2];
#pragma unroll
    for (int i = 0; i < 4; i++) { acc2[i][0] = 0ull; acc2[i][1] = 0ull; }

    for (int kk = 0; kk < 256; kk += 32) {
#pragma unroll
        for (int t = 0; t < 2; t++) {
            int idx4 = tid + t * 256;
            int uu = idx4 >> 3;
            int cc4 = idx4 & 7;
            float4 wv = *(const float4*)&w_g1[uu * 256 + kk + cc4 * 4];
            Ws[(cc4 * 4 + 0) * 68 + uu] = wv.x;
            Ws[(cc4 * 4 + 1) * 68 + uu] = wv.y;
            Ws[(cc4 * 4 + 2) * 68 + uu] = wv.z;
            Ws[(cc4 * 4 + 3) * 68 + uu] = wv.w;
        }
#pragma unroll
        for (int t = 0; t < 8; t++) {
            int idx = tid + t * 256;
            int cc = idx >> 6;
            int pp = idx & 63;
            int p = p0 + pp;
            int hh = p >> 5;
            int wj = (p & 31) >> 1;
            const float* row = x + ((size_t)(b * 256) + kk + cc) * 1024 + hh * 32;
            Xs[cc * 64 + pp] = fabsf(row[wj] - row[31 - wj]);
        }
        __syncthreads();
#pragma unroll
        for (int c = 0; c < 32; c++) {
            float4 a = *(float4*)&Ws[c * 68 + ty * 4];
            double2 bd = *(const double2*)&Xs[c * 64 + tx * 4];
            u64 b01 = d2u(bd.x), b23 = d2u(bd.y);
            acc2[0][0] = ffma2(dup2(a.x), b01, acc2[0][0]);
            acc2[0][1] = ffma2(dup2(a.x), b23, acc2[0][1]);
            acc2[1][0] = ffma2(dup2(a.y), b01, acc2[1][0]);
            acc2[1][1] = ffma2(dup2(a.y), b23, acc2[1][1]);
            acc2[2][0] = ffma2(dup2(a.z), b01, acc2[2][0]);
            acc2[2][1] = ffma2(dup2(a.z), b23, acc2[2][1]);
            acc2[3][0] = ffma2(dup2(a.w), b01, acc2[3][0]);
            acc2[3][1] = ffma2(dup2(a.w), b23, acc2[3][1]);
        }
        __syncthreads();
    }

#pragma unroll
    for (int ui = 0; ui < 4; ui++) {
        int u = ty * 4 + ui;
        float bias = b_g1[u];
        float2 lo = unpk(acc2[ui][0]), hi = unpk(acc2[ui][1]);
        float v0 = lo.x + bias, v1 = lo.y + bias;
        float v2 = hi.x + bias, v3 = hi.y + bias;
        float4 vout;
        vout.x = 0.5f * v0 * (1.f + erff(v0 * 0.70710678118654752f));
        vout.y = 0.5f * v1 * (1.f + erff(v1 * 0.70710678118654752f));
        vout.z = 0.5f * v2 * (1.f + erff(v2 * 0.70710678118654752f));
        vout.w = 0.5f * v3 * (1.f + erff(v3 * 0.70710678118654752f));
        *(float4*)&g_g1buf[((size_t)(b * 64) + u) * 1024 + p0 + tx * 4] = vout;
    }
}

// ---------------------------------------------------------------------------
// K4b: gate output
// ---------------------------------------------------------------------------
__global__ __launch_bounds__(256) void gate2_kernel(const float* __restrict__ w_g2,
                                                    const float* __restrict__ b_g2) {
    const int idx = blockIdx.x * 256 + threadIdx.x;  // 0..8191
    const int b = idx >> 10;
    const int p = idx & 1023;
    float acc = b_g2[0];
#pragma unroll 8
    for (int u = 0; u < 64; u++)
        acc += g_g1buf[((size_t)(b * 64) + u) * 1024 + p] * w_g2[u];
    g_gate[idx] = 1.f / (1.f + expf(-acc));
}

// ---------------------------------------------------------------------------
// K5: out-proj with gate folded in
// ---------------------------------------------------------------------------
__global__ __launch_bounds__(256) void outproj_kernel(const float* __restrict__ w_out,
                                                      const float* __restrict__ b_out,
                                                      float* __restrict__ out) {
    const int b = blockIdx.z;
    const int o0 = blockIdx.y * 64;
    const int p0 = blockIdx.x * 64;
    const int tid = threadIdx.x;
    const int tx = tid & 15, ty = tid >> 4;

    __shared__ float Ws[32 * 68];
    __shared__ float Xs[32 * 64];
    __shared__ float Gs[64];

    if (tid < 64) Gs[tid] = 1.f + g_gate[b * 1024 + p0 + tid];
    __syncthreads();

    u64 acc2[4][2];
#pragma unroll
    for (int i = 0; i < 4; i++) { acc2[i][0] = 0ull; acc2[i][1] = 0ull; }

    for (int kk = 0; kk < 256; kk += 32) {
#pragma unroll
        for (int t = 0; t < 2; t++) {
            int idx4 = tid + t * 256;
            int oo = idx4 >> 3;
            int cc4 = idx4 & 7;
            float4 wv = *(const float4*)&w_out[(o0 + oo) * 256 + kk + cc4 * 4];
            Ws[(cc4 * 4 + 0) * 68 + oo] = wv.x;
            Ws[(cc4 * 4 + 1) * 68 + oo] = wv.y;
            Ws[(cc4 * 4 + 2) * 68 + oo] = wv.z;
            Ws[(cc4 * 4 + 3) * 68 + oo] = wv.w;
        }
#pragma unroll
        for (int t = 0; t < 2; t++) {
            int idx4 = tid + t * 256;
            int cc = idx4 >> 4;
            int pp4 = idx4 & 15;
            float4 av = *(const float4*)&g_ao[((size_t)(b * 256) + kk + cc) * 1024 + p0 + pp4 * 4];
            av.x *= Gs[pp4 * 4 + 0];
            av.y *= Gs[pp4 * 4 + 1];
            av.z *= Gs[pp4 * 4 + 2];
            av.w *= Gs[pp4 * 4 + 3];
            *(float4*)&Xs[cc * 64 + pp4 * 4] = av;
        }
        __syncthreads();
#pragma unroll
        for (int c = 0; c < 32; c++) {
            float4 a = *(float4*)&Ws[c * 68 + ty * 4];
            double2 bd = *(const double2*)&Xs[c * 64 + tx * 4];
            u64 b01 = d2u(bd.x), b23 = d2u(bd.y);
            acc2[0][0] = ffma2(dup2(a.x), b01, acc2[0][0]);
            acc2[0][1] = ffma2(dup2(a.x), b23, acc2[0][1]);
            acc2[1][0] = ffma2(dup2(a.y), b01, acc2[1][0]);
            acc2[1][1] = ffma2(dup2(a.y), b23, acc2[1][1]);
            acc2[2][0] = ffma2(dup2(a.z), b01, acc2[2][0]);
            acc2[2][1] = ffma2(dup2(a.z), b23, acc2[2][1]);
            acc2[3][0] = ffma2(dup2(a.w), b01, acc2[3][0]);
            acc2[3][1] = ffma2(dup2(a.w), b23, acc2[3][1]);
        }
        __syncthreads();
    }

#pragma unroll
    for (int oi = 0; oi < 4; oi++) {
        int o = o0 + ty * 4 + oi;
        float bias = b_out[o];
        float2 lo = unpk(acc2[oi][0]), hi = unpk(acc2[oi][1]);
        float4 vout = make_float4(lo.x + bias, lo.y + bias, hi.x + bias, hi.y + bias);
        *(float4*)&out[((size_t)(b * 256) + o) * 1024 + p0 + tx * 4] = vout;
    }
}

// ---------------------------------------------------------------------------
extern "C" void kernel_launch(void* const* d_in, const int* in_sizes, int n_in,
                              void* d_out, int out_size) {
    const float* x     = (const float*)d_in[0];
    const float* w_qkv = (const float*)d_in[1];
    const float* w_out = (const float*)d_in[2];
    const float* b_out = (const float*)d_in[3];
    const float* w_g1  = (const float*)d_in[4];
    const float* b_g1  = (const float*)d_in[5];
    const float* w_g2  = (const float*)d_in[6];
    const float* b_g2  = (const float*)d_in[7];
    float* out = (float*)d_out;

    qkv_kernel<<<dim3(16, 12, 8), 256>>>(x, w_qkv);
    colsum_kernel<<<64, 256>>>();
    diag_kernel<<<8, 256>>>();
    attn_kernel<<<dim3(8, 64), 256>>>();
    gate1_kernel<<<dim3(16, 8), 256>>>(x, w_g1, b_g1);
    gate2_kernel<<<32, 256>>>(w_g2, b_g2);
    outproj_kernel<<<dim3(16, 4, 8), 256>>>(w_out, b_out, out);
}

// round 6
// speedup vs baseline: 2.7638x; 1.4722x over previous
#include <cuda_runtime.h>
#include <math.h>
#include <stdint.h>

// ---------------------------------------------------------------------------
// DiagonalMicroAttention: b=8, c=256, h=w=32, heads=8, d=32, n=1024
//   K1 qkv GEMM via tf32 mma -> q,k,v stored as tf32-rounded fp32,
//      q pre-scaled by 1/sqrt(d)
//   K2 colsum(V), diag_vec
//   K3 flash attention via tf32 mma.sync, fused epilogue
//   K4 gate MLP (FFMA2)
//   K5 out-proj via tf32 mma with (1+g) gate folded in
// ---------------------------------------------------------------------------

#define B 8
#define HEADS 8
#define D 32
#define N 1024
#define C 256
#define SCALE 0.1767766952966369f   // 1/sqrt(32)
#define BHND (B * HEADS * N * D)

typedef unsigned long long u64;

__device__ __forceinline__ u64 ffma2(u64 a, u64 b, u64 c) {
    u64 d; asm("fma.rn.f32x2 %0,%1,%2,%3;" : "=l"(d) : "l"(a), "l"(b), "l"(c));
    return d;
}
__device__ __forceinline__ u64 dup2(float v) {
    u64 r; asm("mov.b64 %0, {%1,%1};" : "=l"(r) : "f"(v));
    return r;
}
__device__ __forceinline__ float2 unpk(u64 v) {
    float2 f; asm("mov.b64 {%0,%1}, %2;" : "=f"(f.x), "=f"(f.y) : "l"(v));
    return f;
}
__device__ __forceinline__ u64 d2u(double d) { return __double_as_longlong(d); }

__device__ __forceinline__ uint32_t f2tf(float f) {
    uint32_t r; asm("cvt.rna.tf32.f32 %0, %1;" : "=r"(r) : "f"(f));
    return r;
}
__device__ __forceinline__ void mma_tf32(float& d0, float& d1, float& d2, float& d3,
                                         uint32_t a0, uint32_t a1, uint32_t a2, uint32_t a3,
                                         uint32_t b0, uint32_t b1) {
    asm("mma.sync.aligned.m16n8k8.row.col.f32.tf32.tf32.f32 "
        "{%0,%1,%2,%3}, {%4,%5,%6,%7}, {%8,%9}, {%0,%1,%2,%3};"
        : "+f"(d0), "+f"(d1), "+f"(d2), "+f"(d3)
        : "r"(a0), "r"(a1), "r"(a2), "r"(a3), "r"(b0), "r"(b1));
}

__device__ float g_q[BHND];                // tf32-rounded, pre-scaled by SCALE
__device__ float g_k[BHND];                // tf32-rounded
__device__ float g_v[BHND];                // tf32-rounded
__device__ float g_ao[B * C * N];          // attention output, [b][c][n]
__device__ float g_g1buf[B * 64 * N];      // gate hidden
__device__ float g_gate[B * N];            // sigmoid gate per pixel
__device__ float g_dvec[B * D];            // 0.3/8 * diag sums (q already scaled)
__device__ float g_csum[B * HEADS * D];    // column sums of V

// ---------------------------------------------------------------------------
// K1: qkv projection via tf32 MMA.
// Y[b,o,p] = sum_c W[o,c] * x[b,c,p], o in [0,768). CTA tile 128o x 128p,
// 8 warps of 64o x 32p. Epilogue: tf32-round (q also scaled), direct scatter
// stores into [bh][n][d] (fully sector-coalesced by fragment layout).
// ---------------------------------------------------------------------------
#define WPAD 36
#define XPAD 136

__global__ __launch_bounds__(256) void qkv_kernel(const float* __restrict__ x,
                                                  const float* __restrict__ w) {
    const int b = blockIdx.z;
    const int o0 = blockIdx.y * 128;
    const int p0 = blockIdx.x * 128;
    const int tid = threadIdx.x;
    const int warp = tid >> 5;
    const int lane = tid & 31;
    const int gid = lane >> 2;
    const int tig = lane & 3;
    const int o_w = (warp >> 2) * 64;
    const int p_w = (warp & 3) * 32;

    __shared__ uint32_t Ws[128 * WPAD];
    __shared__ uint32_t Xs[32 * XPAD];

    float acc[4][4][4];
#pragma unroll
    for (int m = 0; m < 4; m++)
#pragma unroll
        for (int n = 0; n < 4; n++)
#pragma unroll
            for (int r = 0; r < 4; r++) acc[m][n][r] = 0.f;

    for (int kk = 0; kk < 256; kk += 32) {
#pragma unroll
        for (int t = 0; t < 4; t++) {
            int idx4 = tid + t * 256;
            int oo = idx4 >> 3, c4 = (idx4 & 7) * 4;
            float4 wv = *(const float4*)&w[(o0 + oo) * 256 + kk + c4];
            *(uint4*)&Ws[oo * WPAD + c4] =
                make_uint4(f2tf(wv.x), f2tf(wv.y), f2tf(wv.z), f2tf(wv.w));
        }
#pragma unroll
        for (int t = 0; t < 4; t++) {
            int idx4 = tid + t * 256;
            int cc = idx4 >> 5, p4 = (idx4 & 31) * 4;
            float4 xv = *(const float4*)&x[((b * 256) + kk + cc) * 1024 + p0 + p4];
            *(uint4*)&Xs[cc * XPAD + p4] =
                make_uint4(f2tf(xv.x), f2tf(xv.y), f2tf(xv.z), f2tf(xv.w));
        }
        __syncthreads();
#pragma unroll
        for (int kc = 0; kc < 4; kc++) {
            const int ck = kc * 8;
            uint32_t af[4][4];
#pragma unroll
            for (int m = 0; m < 4; m++) {
                const uint32_t* wr = &Ws[(o_w + m * 16 + gid) * WPAD + ck + tig];
                af[m][0] = wr[0];
                af[m][1] = wr[8 * WPAD];
                af[m][2] = wr[4];
                af[m][3] = wr[8 * WPAD + 4];
            }
            uint32_t bf[4][2];
#pragma unroll
            for (int n = 0; n < 4; n++) {
                const uint32_t* xr = &Xs[(ck + tig) * XPAD + p_w + n * 8 + gid];
                bf[n][0] = xr[0];
                bf[n][1] = xr[4 * XPAD];
            }
#pragma unroll
            for (int m = 0; m < 4; m++)
#pragma unroll
                for (int n = 0; n < 4; n++)
                    mma_tf32(acc[m][n][0], acc[m][n][1], acc[m][n][2], acc[m][n][3],
                             af[m][0], af[m][1], af[m][2], af[m][3],
                             bf[n][0], bf[n][1]);
        }
        __syncthreads();
    }

    // epilogue: route to q/k/v, tf32-round, q scaled.
    const int part = (o0 + o_w) >> 8;
    float* dst = (part == 0) ? g_q : ((part == 1) ? g_k : g_v);
    const float mult = (part == 0) ? SCALE : 1.0f;
#pragma unroll
    for (int m = 0; m < 4; m++) {
        const int ob = o0 + o_w + m * 16;
        const int head = (ob >> 5) & 7;
        const int dd = (ob & 31) + gid;
        float* hb = dst + ((size_t)(b * 8 + head) * 1024) * 32;
#pragma unroll
        for (int n = 0; n < 4; n++) {
            const int p = p0 + p_w + n * 8 + 2 * tig;
            float* pb = hb + (size_t)p * 32;
            pb[dd]          = __uint_as_float(f2tf(acc[m][n][0] * mult));
            pb[32 + dd]     = __uint_as_float(f2tf(acc[m][n][1] * mult));
            pb[dd + 8]      = __uint_as_float(f2tf(acc[m][n][2] * mult));
            pb[32 + dd + 8] = __uint_as_float(f2tf(acc[m][n][3] * mult));
        }
    }
}

// ---------------------------------------------------------------------------
// K2a: column sums of V per (b,h)
// ---------------------------------------------------------------------------
__global__ __launch_bounds__(256) void colsum_kernel() {
    const int bh = blockIdx.x;
    const int tid = threadIdx.x;
    const int dd = tid & 31;
    const int sl = tid >> 5;
    const float* vb = g_v + (size_t)bh * 1024 * 32;
    float s = 0.f;
    for (int j = sl * 128; j < sl * 128 + 128; j++) s += vb[(size_t)j * 32 + dd];
    __shared__ float red[256];
    red[tid] = s;
    __syncthreads();
    if (tid < 32) {
        float t = 0.f;
#pragma unroll
        for (int r = 0; r < 8; r++) t += red[tid + r * 32];
        g_csum[bh * 32 + tid] = t;
    }
}

// ---------------------------------------------------------------------------
// K2b: diag_vec.  q already carries SCALE, so factor is 0.3/8 only.
// ---------------------------------------------------------------------------
__global__ __launch_bounds__(256) void diag_kernel() {
    const int b = blockIdx.x;
    const int tid = threadIdx.x;
    const int i = tid & 31;
    const int h = tid >> 5;
    const size_t base = ((size_t)(b * 8 + h) * 1024) * 32;
    float s = 0.f;
#pragma unroll 4
    for (int ss = 0; ss < 32; ss++) {
        size_t off = base + (size_t)(ss * 33) * 32 + i;
        s += g_q[off] * g_k[off];
    }
    __shared__ float red[256];
    red[tid] = s;
    __syncthreads();
    if (tid < 32) {
        float t = 0.f;
#pragma unroll
        for (int r = 0; r < 8; r++) t += red[tid + r * 32];
        g_dvec[b * 32 + tid] = t * (0.3f / 8.0f);
    }
}

// ---------------------------------------------------------------------------
// K3: tf32 tensor-core flash attention. Inputs already tf32-rounded (and Q
// pre-scaled), so staging is a plain copy and Q fragments load raw bits.
// ---------------------------------------------------------------------------
#define KPAD 36
#define VPAD 40

__global__ __launch_bounds__(256) void attn_kernel() {
    const int bh = blockIdx.y;
    const int b = bh >> 3;
    const int head = bh & 7;
    const int tid = threadIdx.x;
    const int warp = tid >> 5;
    const int lane = tid & 31;
    const int gid = lane >> 2;
    const int tig = lane & 3;
    const int q0 = blockIdx.x * 128 + warp * 16;

    __shared__ uint32_t Ks[128 * KPAD];
    __shared__ uint32_t Vs[128 * VPAD];

    const float* qb = g_q + (size_t)bh * (N * D);
    uint32_t qa[4][4];
#pragma unroll
    for (int kc = 0; kc < 4; kc++) {
        qa[kc][0] = __float_as_uint(qb[(q0 + gid) * 32 + kc * 8 + tig]);
        qa[kc][1] = __float_as_uint(qb[(q0 + gid + 8) * 32 + kc * 8 + tig]);
        qa[kc][2] = __float_as_uint(qb[(q0 + gid) * 32 + kc * 8 + tig + 4]);
        qa[kc][3] = __float_as_uint(qb[(q0 + gid + 8) * 32 + kc * 8 + tig + 4]);
    }

    float o[4][4];
#pragma unroll
    for (int nt = 0; nt < 4; nt++)
#pragma unroll
        for (int r = 0; r < 4; r++) o[nt][r] = 0.f;
    float llo = 0.f, lhi = 0.f;

    const uint4* kgl = (const uint4*)(g_k + (size_t)bh * (N * D));
    const uint4* vgl = (const uint4*)(g_v + (size_t)bh * (N * D));
    const int src0 = (lane & 28) | (tig >> 1);
    const bool odd = (tig & 1);

    for (int t0 = 0; t0 < 8; t0++) {
#pragma unroll
        for (int r = 0; r < 4; r++) {
            int idx4 = tid + r * 256;           // 0..1023
            int key = idx4 >> 3, c4 = (idx4 & 7) * 4;
            int goff4 = t0 * 1024 + key * 8 + (c4 >> 2);
            *(uint4*)&Ks[key * KPAD + c4] = kgl[goff4];
            *(uint4*)&Vs[key * VPAD + c4] = vgl[goff4];
        }
        __syncthreads();

#pragma unroll 2
        for (int kch = 0; kch < 16; kch++) {
            const int key0 = kch * 8;
            float s0 = 0.f, s1 = 0.f, s2 = 0.f, s3 = 0.f;
            const uint32_t* kr = &Ks[(key0 + gid) * KPAD + tig];
#pragma unroll
            for (int kc = 0; kc < 4; kc++) {
                uint32_t kb0 = kr[kc * 8];
                uint32_t kb1 = kr[kc * 8 + 4];
                mma_tf32(s0, s1, s2, s3,
                         qa[kc][0], qa[kc][1], qa[kc][2], qa[kc][3], kb0, kb1);
            }
            uint32_t p0 = f2tf(__expf(s0));
            uint32_t p1 = f2tf(__expf(s1));
            uint32_t p2 = f2tf(__expf(s2));
            uint32_t p3 = f2tf(__expf(s3));
            llo += __uint_as_float(p0) + __uint_as_float(p1);
            lhi += __uint_as_float(p2) + __uint_as_float(p3);
            uint32_t e0, e1;
            e0 = __shfl_sync(0xffffffffu, p0, src0);
            e1 = __shfl_sync(0xffffffffu, p1, src0);
            uint32_t pa0 = odd ? e1 : e0;
            e0 = __shfl_sync(0xffffffffu, p0, src0 + 2);
            e1 = __shfl_sync(0xffffffffu, p1, src0 + 2);
            uint32_t pa2 = odd ? e1 : e0;
            e0 = __shfl_sync(0xffffffffu, p2, src0);
            e1 = __shfl_sync(0xffffffffu, p3, src0);
            uint32_t pa1 = odd ? e1 : e0;
            e0 = __shfl_sync(0xffffffffu, p2, src0 + 2);
            e1 = __shfl_sync(0xffffffffu, p3, src0 + 2);
            uint32_t pa3 = odd ? e1 : e0;
            const uint32_t* vr0 = &Vs[(key0 + tig) * VPAD + gid];
            const uint32_t* vr1 = &Vs[(key0 + tig + 4) * VPAD + gid];
#pragma unroll
            for (int nt = 0; nt < 4; nt++) {
                uint32_t vb0 = vr0[nt * 8];
                uint32_t vb1 = vr1[nt * 8];
                mma_tf32(o[nt][0], o[nt][1], o[nt][2], o[nt][3],
                         pa0, pa1, pa2, pa3, vb0, vb1);
            }
        }
        __syncthreads();
    }

    llo += __shfl_xor_sync(0xffffffffu, llo, 1);
    llo += __shfl_xor_sync(0xffffffffu, llo, 2);
    lhi += __shfl_xor_sync(0xffffffffu, lhi, 1);
    lhi += __shfl_xor_sync(0xffffffffu, lhi, 2);
    const float invlo = 1.f / llo;
    const float invhi = 1.f / lhi;

    const int rlo = q0 + gid;
    const int rhi = rlo + 8;
    const float dvlo = (rlo < 32) ? g_dvec[b * 32 + rlo] : 0.f;
    const float dvhi = (rhi < 32) ? g_dvec[b * 32 + rhi] : 0.f;
    const float* cs = g_csum + bh * 32;
    float* ob = g_ao + ((size_t)b * 256 + head * 32) * 1024;
#pragma unroll
    for (int nt = 0; nt < 4; nt++) {
        int c0 = nt * 8 + 2 * tig;
        int c1 = c0 + 1;
        float cs0 = cs[c0], cs1 = cs[c1];
        ob[(size_t)c0 * 1024 + rlo] = o[nt][0] * invlo + dvlo * cs0;
        ob[(size_t)c1 * 1024 + rlo] = o[nt][1] * invlo + dvlo * cs1;
        ob[(size_t)c0 * 1024 + rhi] = o[nt][2] * invhi + dvhi * cs0;
        ob[(size_t)c1 * 1024 + rhi] = o[nt][3] * invhi + dvhi * cs1;
    }
}

// ---------------------------------------------------------------------------
// K4a: gate hidden (FFMA2)
// ---------------------------------------------------------------------------
__global__ __launch_bounds__(256) void gate1_kernel(const float* __restrict__ x,
                                                    const float* __restrict__ w_g1,
                                                    const float* __restrict__ b_g1) {
    const int b = blockIdx.y;
    const int p0 = blockIdx.x * 64;
    const int tid = threadIdx.x;
    const int tx = tid & 15, ty = tid >> 4;

    __shared__ float Ws2[32 * 68];   // [c][u]
    __shared__ float Xs2[32 * 64];   // [c][p]

    u64 acc2[4][2];
#pragma unroll
    for (int i = 0; i < 4; i++) { acc2[i][0] = 0ull; acc2[i][1] = 0ull; }

    for (int kk = 0; kk < 256; kk += 32) {
#pragma unroll
        for (int t = 0; t < 2; t++) {
            int idx4 = tid + t * 256;
            int uu = idx4 >> 3;
            int cc4 = idx4 & 7;
            float4 wv = *(const float4*)&w_g1[uu * 256 + kk + cc4 * 4];
            Ws2[(cc4 * 4 + 0) * 68 + uu] = wv.x;
            Ws2[(cc4 * 4 + 1) * 68 + uu] = wv.y;
            Ws2[(cc4 * 4 + 2) * 68 + uu] = wv.z;
            Ws2[(cc4 * 4 + 3) * 68 + uu] = wv.w;
        }
#pragma unroll
        for (int t = 0; t < 8; t++) {
            int idx = tid + t * 256;
            int cc = idx >> 6;
            int pp = idx & 63;
            int p = p0 + pp;
            int hh = p >> 5;
            int wj = (p & 31) >> 1;
            const float* row = x + ((size_t)(b * 256) + kk + cc) * 1024 + hh * 32;
            Xs2[cc * 64 + pp] = fabsf(row[wj] - row[31 - wj]);
        }
        __syncthreads();
#pragma unroll
        for (int c = 0; c < 32; c++) {
            float4 a = *(float4*)&Ws2[c * 68 + ty * 4];
            double2 bd = *(const double2*)&Xs2[c * 64 + tx * 4];
            u64 b01 = d2u(bd.x), b23 = d2u(bd.y);
            acc2[0][0] = ffma2(dup2(a.x), b01, acc2[0][0]);
            acc2[0][1] = ffma2(dup2(a.x), b23, acc2[0][1]);
            acc2[1][0] = ffma2(dup2(a.y), b01, acc2[1][0]);
            acc2[1][1] = ffma2(dup2(a.y), b23, acc2[1][1]);
            acc2[2][0] = ffma2(dup2(a.z), b01, acc2[2][0]);
            acc2[2][1] = ffma2(dup2(a.z), b23, acc2[2][1]);
            acc2[3][0] = ffma2(dup2(a.w), b01, acc2[3][0]);
            acc2[3][1] = ffma2(dup2(a.w), b23, acc2[3][1]);
        }
        __syncthreads();
    }

#pragma unroll
    for (int ui = 0; ui < 4; ui++) {
        int u = ty * 4 + ui;
        float bias = b_g1[u];
        float2 lo = unpk(acc2[ui][0]), hi = unpk(acc2[ui][1]);
        float v0 = lo.x + bias, v1 = lo.y + bias;
        float v2 = hi.x + bias, v3 = hi.y + bias;
        float4 vout;
        vout.x = 0.5f * v0 * (1.f + erff(v0 * 0.70710678118654752f));
        vout.y = 0.5f * v1 * (1.f + erff(v1 * 0.70710678118654752f));
        vout.z = 0.5f * v2 * (1.f + erff(v2 * 0.70710678118654752f));
        vout.w = 0.5f * v3 * (1.f + erff(v3 * 0.70710678118654752f));
        *(float4*)&g_g1buf[((size_t)(b * 64) + u) * 1024 + p0 + tx * 4] = vout;
    }
}

// ---------------------------------------------------------------------------
// K4b: gate output
// ---------------------------------------------------------------------------
__global__ __launch_bounds__(256) void gate2_kernel(const float* __restrict__ w_g2,
                                                    const float* __restrict__ b_g2) {
    const int idx = blockIdx.x * 256 + threadIdx.x;  // 0..8191
    const int b = idx >> 10;
    const int p = idx & 1023;
    float acc = b_g2[0];
#pragma unroll 8
    for (int u = 0; u < 64; u++)
        acc += g_g1buf[((size_t)(b * 64) + u) * 1024 + p] * w_g2[u];
    g_gate[idx] = 1.f / (1.f + expf(-acc));
}

// ---------------------------------------------------------------------------
// K5: out-proj via tf32 MMA, gate folded in at staging.
// Y[b,o,p] = b_out[o] + sum_c W[o,c] * (ao[b,c,p]*(1+g[b,p]))
// ---------------------------------------------------------------------------
__global__ __launch_bounds__(256) void outproj_kernel(const float* __restrict__ w_out,
                                                      const float* __restrict__ b_out,
                                                      float* __restrict__ out) {
    const int b = blockIdx.z;
    const int o0 = blockIdx.y * 128;
    const int p0 = blockIdx.x * 128;
    const int tid = threadIdx.x;
    const int warp = tid >> 5;
    const int lane = tid & 31;
    const int gid = lane >> 2;
    const int tig = lane & 3;
    const int o_w = (warp >> 2) * 64;
    const int p_w = (warp & 3) * 32;

    __shared__ uint32_t Ws[128 * WPAD];
    __shared__ uint32_t Xs[32 * XPAD];

    float acc[4][4][4];
#pragma unroll
    for (int m = 0; m < 4; m++)
#pragma unroll
        for (int n = 0; n < 4; n++)
#pragma unroll
            for (int r = 0; r < 4; r++) acc[m][n][r] = 0.f;

    for (int kk = 0; kk < 256; kk += 32) {
#pragma unroll
        for (int t = 0; t < 4; t++) {
            int idx4 = tid + t * 256;
            int oo = idx4 >> 3, c4 = (idx4 & 7) * 4;
            float4 wv = *(const float4*)&w_out[(o0 + oo) * 256 + kk + c4];
            *(uint4*)&Ws[oo * WPAD + c4] =
                make_uint4(f2tf(wv.x), f2tf(wv.y), f2tf(wv.z), f2tf(wv.w));
        }
#pragma unroll
        for (int t = 0; t < 4; t++) {
            int idx4 = tid + t * 256;
            int cc = idx4 >> 5, p4 = (idx4 & 31) * 4;
            float4 xv = *(const float4*)&g_ao[((size_t)(b * 256) + kk + cc) * 1024 + p0 + p4];
            float4 gv = *(const float4*)&g_gate[b * 1024 + p0 + p4];
            xv.x *= (1.f + gv.x); xv.y *= (1.f + gv.y);
            xv.z *= (1.f + gv.z); xv.w *= (1.f + gv.w);
            *(uint4*)&Xs[cc * XPAD + p4] =
                make_uint4(f2tf(xv.x), f2tf(xv.y), f2tf(xv.z), f2tf(xv.w));
        }
        __syncthreads();
#pragma unroll
        for (int kc = 0; kc < 4; kc++) {
            const int ck = kc * 8;
            uint32_t af[4][4];
#pragma unroll
            for (int m = 0; m < 4; m++) {
                const uint32_t* wr = &Ws[(o_w + m * 16 + gid) * WPAD + ck + tig];
                af[m][0] = wr[0];
                af[m][1] = wr[8 * WPAD];
                af[m][2] = wr[4];
                af[m][3] = wr[8 * WPAD + 4];
            }
            uint32_t bf[4][2];
#pragma unroll
            for (int n = 0; n < 4; n++) {
                const uint32_t* xr = &Xs[(ck + tig) * XPAD + p_w + n * 8 + gid];
                bf[n][0] = xr[0];
                bf[n][1] = xr[4 * XPAD];
            }
#pragma unroll
            for (int m = 0; m < 4; m++)
#pragma unroll
                for (int n = 0; n < 4; n++)
                    mma_tf32(acc[m][n][0], acc[m][n][1], acc[m][n][2], acc[m][n][3],
                             af[m][0], af[m][1], af[m][2], af[m][3],
                             bf[n][0], bf[n][1]);
        }
        __syncthreads();
    }

#pragma unroll
    for (int m = 0; m < 4; m++) {
        const int og0 = o0 + o_w + m * 16 + gid;
        const float bs0 = b_out[og0];
        const float bs1 = b_out[og0 + 8];
        float* r0 = out + ((size_t)(b * 256) + og0) * 1024;
        float* r1 = out + ((size_t)(b * 256) + og0 + 8) * 1024;
#pragma unroll
        for (int n = 0; n < 4; n++) {
            const int p = p0 + p_w + n * 8 + 2 * tig;
            *(float2*)&r0[p] = make_float2(acc[m][n][0] + bs0, acc[m][n][1] + bs0);
            *(float2*)&r1[p] = make_float2(acc[m][n][2] + bs1, acc[m][n][3] + bs1);
        }
    }
}

// ---------------------------------------------------------------------------
extern "C" void kernel_launch(void* const* d_in, const int* in_sizes, int n_in,
                              void* d_out, int out_size) {
    const float* x     = (const float*)d_in[0];
    const float* w_qkv = (const float*)d_in[1];
    const float* w_out = (const float*)d_in[2];
    const float* b_out = (const float*)d_in[3];
    const float* w_g1  = (const float*)d_in[4];
    const float* b_g1  = (const float*)d_in[5];
    const float* w_g2  = (const float*)d_in[6];
    const float* b_g2  = (const float*)d_in[7];
    float* out = (float*)d_out;

    qkv_kernel<<<dim3(8, 6, 8), 256>>>(x, w_qkv);
    colsum_kernel<<<64, 256>>>();
    diag_kernel<<<8, 256>>>();
    attn_kernel<<<dim3(8, 64), 256>>>();
    gate1_kernel<<<dim3(16, 8), 256>>>(x, w_g1, b_g1);
    gate2_kernel<<<32, 256>>>(w_g2, b_g2);
    outproj_kernel<<<dim3(8, 2, 8), 256>>>(w_out, b_out, out);
}

// round 7
// speedup vs baseline: 3.0278x; 1.0955x over previous
#include <cuda_runtime.h>
#include <math.h>
#include <stdint.h>

// ---------------------------------------------------------------------------
// DiagonalMicroAttention: b=8, c=256, h=w=32, heads=8, d=32, n=1024
//   K1 qkv GEMM via tf32 mma -> q (scaled by SCALE*log2e, logical layout),
//      k (physK-permuted), v (physV-permuted), all tf32-rounded
//   K2 colsum(V), diag_vec
//   K3 flash attention via tf32 mma, LDS.128 fragments, ex2 softmax
//   K4 gate hidden (FFMA2)
//   K5 out-proj via tf32 mma, gate2 + (1+g) fused in
// ---------------------------------------------------------------------------

#define B 8
#define HEADS 8
#define D 32
#define N 1024
#define C 256
#define SCALE 0.1767766952966369f   // 1/sqrt(32)
#define LOG2E 1.4426950408889634f
#define BHND (B * HEADS * N * D)

typedef unsigned long long u64;

__device__ __forceinline__ u64 ffma2(u64 a, u64 b, u64 c) {
    u64 d; asm("fma.rn.f32x2 %0,%1,%2,%3;" : "=l"(d) : "l"(a), "l"(b), "l"(c));
    return d;
}
__device__ __forceinline__ u64 dup2(float v) {
    u64 r; asm("mov.b64 %0, {%1,%1};" : "=l"(r) : "f"(v));
    return r;
}
__device__ __forceinline__ float2 unpk(u64 v) {
    float2 f; asm("mov.b64 {%0,%1}, %2;" : "=f"(f.x), "=f"(f.y) : "l"(v));
    return f;
}
__device__ __forceinline__ u64 d2u(double d) { return __double_as_longlong(d); }

__device__ __forceinline__ uint32_t f2tf(float f) {
    uint32_t r; asm("cvt.rna.tf32.f32 %0, %1;" : "=r"(r) : "f"(f));
    return r;
}
__device__ __forceinline__ float ex2f(float x) {
    float r; asm("ex2.approx.ftz.f32 %0, %1;" : "=f"(r) : "f"(x));
    return r;
}
__device__ __forceinline__ void mma_tf32(float& d0, float& d1, float& d2, float& d3,
                                         uint32_t a0, uint32_t a1, uint32_t a2, uint32_t a3,
                                         uint32_t b0, uint32_t b1) {
    asm("mma.sync.aligned.m16n8k8.row.col.f32.tf32.tf32.f32 "
        "{%0,%1,%2,%3}, {%4,%5,%6,%7}, {%8,%9}, {%0,%1,%2,%3};"
        : "+f"(d0), "+f"(d1), "+f"(d2), "+f"(d3)
        : "r"(a0), "r"(a1), "r"(a2), "r"(a3), "r"(b0), "r"(b1));
}

// in-row permutations for MMA-fragment-friendly K/V storage
__device__ __forceinline__ int physK(int d) {
    return (d & 3) * 8 + (d >> 3) * 2 + ((d >> 2) & 1);
}
__device__ __forceinline__ int physV(int d) {
    return (d & 7) * 4 + (d >> 3);
}

__device__ float g_q[BHND];                // logical layout, x SCALE*LOG2E
__device__ float g_k[BHND];                // physK-permuted rows
__device__ float g_v[BHND];                // physV-permuted rows
__device__ float g_ao[B * C * N];          // attention output, [b][c][n]
__device__ float g_g1buf[B * 64 * N];      // gate hidden
__device__ float g_dvec[B * D];            // ln2*0.3/8 * diag sums
__device__ float g_csum[B * HEADS * D];    // colsum of V, physV order

// ---------------------------------------------------------------------------
// K1: qkv projection via tf32 MMA. CTA tile 128o x 128p, 8 warps 64o x 32p.
// ---------------------------------------------------------------------------
#define WPAD 36
#define XPAD 136

__global__ __launch_bounds__(256) void qkv_kernel(const float* __restrict__ x,
                                                  const float* __restrict__ w) {
    const int b = blockIdx.z;
    const int o0 = blockIdx.y * 128;
    const int p0 = blockIdx.x * 128;
    const int tid = threadIdx.x;
    const int warp = tid >> 5;
    const int lane = tid & 31;
    const int gid = lane >> 2;
    const int tig = lane & 3;
    const int o_w = (warp >> 2) * 64;
    const int p_w = (warp & 3) * 32;

    __shared__ uint32_t Ws[128 * WPAD];
    __shared__ uint32_t Xs[32 * XPAD];

    float acc[4][4][4];
#pragma unroll
    for (int m = 0; m < 4; m++)
#pragma unroll
        for (int n = 0; n < 4; n++)
#pragma unroll
            for (int r = 0; r < 4; r++) acc[m][n][r] = 0.f;

    for (int kk = 0; kk < 256; kk += 32) {
#pragma unroll
        for (int t = 0; t < 4; t++) {
            int idx4 = tid + t * 256;
            int oo = idx4 >> 3, c4 = (idx4 & 7) * 4;
            float4 wv = *(const float4*)&w[(o0 + oo) * 256 + kk + c4];
            *(uint4*)&Ws[oo * WPAD + c4] =
                make_uint4(f2tf(wv.x), f2tf(wv.y), f2tf(wv.z), f2tf(wv.w));
        }
#pragma unroll
        for (int t = 0; t < 4; t++) {
            int idx4 = tid + t * 256;
            int cc = idx4 >> 5, p4 = (idx4 & 31) * 4;
            float4 xv = *(const float4*)&x[((b * 256) + kk + cc) * 1024 + p0 + p4];
            *(uint4*)&Xs[cc * XPAD + p4] =
                make_uint4(f2tf(xv.x), f2tf(xv.y), f2tf(xv.z), f2tf(xv.w));
        }
        __syncthreads();
#pragma unroll
        for (int kc = 0; kc < 4; kc++) {
            const int ck = kc * 8;
            uint32_t af[4][4];
#pragma unroll
            for (int m = 0; m < 4; m++) {
                const uint32_t* wr = &Ws[(o_w + m * 16 + gid) * WPAD + ck + tig];
                af[m][0] = wr[0];
                af[m][1] = wr[8 * WPAD];
                af[m][2] = wr[4];
                af[m][3] = wr[8 * WPAD + 4];
            }
            uint32_t bf[4][2];
#pragma unroll
            for (int n = 0; n < 4; n++) {
                const uint32_t* xr = &Xs[(ck + tig) * XPAD + p_w + n * 8 + gid];
                bf[n][0] = xr[0];
                bf[n][1] = xr[4 * XPAD];
            }
#pragma unroll
            for (int m = 0; m < 4; m++)
#pragma unroll
                for (int n = 0; n < 4; n++)
                    mma_tf32(acc[m][n][0], acc[m][n][1], acc[m][n][2], acc[m][n][3],
                             af[m][0], af[m][1], af[m][2], af[m][3],
                             bf[n][0], bf[n][1]);
        }
        __syncthreads();
    }

    // epilogue: route to q/k/v with per-part layout + scaling
    const int part = (o0 + o_w) >> 8;
    float* dst = (part == 0) ? g_q : ((part == 1) ? g_k : g_v);
    const float mult = (part == 0) ? (SCALE * LOG2E) : 1.0f;
#pragma unroll
    for (int m = 0; m < 4; m++) {
        const int ob = o0 + o_w + m * 16;
        const int head = (ob >> 5) & 7;
        const int dl0 = (ob & 31) + gid;
        const int dl1 = dl0 + 8;
        int d0, d1;
        if (part == 0)      { d0 = dl0;        d1 = dl1; }
        else if (part == 1) { d0 = physK(dl0); d1 = physK(dl1); }
        else                { d0 = physV(dl0); d1 = physV(dl1); }
        float* hb = dst + ((size_t)(b * 8 + head) * 1024) * 32;
#pragma unroll
        for (int n = 0; n < 4; n++) {
            const int p = p0 + p_w + n * 8 + 2 * tig;
            float* pb = hb + (size_t)p * 32;
            pb[d0]      = __uint_as_float(f2tf(acc[m][n][0] * mult));
            pb[32 + d0] = __uint_as_float(f2tf(acc[m][n][1] * mult));
            pb[d1]      = __uint_as_float(f2tf(acc[m][n][2] * mult));
            pb[32 + d1] = __uint_as_float(f2tf(acc[m][n][3] * mult));
        }
    }
}

// ---------------------------------------------------------------------------
// K2a: column sums of V per (b,h). V rows are physV-permuted; sums land in
// physV order, which is what the attn epilogue indexes.
// ---------------------------------------------------------------------------
__global__ __launch_bounds__(256) void colsum_kernel() {
    const int bh = blockIdx.x;
    const int tid = threadIdx.x;
    const int dd = tid & 31;
    const int sl = tid >> 5;
    const float* vb = g_v + (size_t)bh * 1024 * 32;
    float s = 0.f;
    for (int j = sl * 128; j < sl * 128 + 128; j++) s += vb[(size_t)j * 32 + dd];
    __shared__ float red[256];
    red[tid] = s;
    __syncthreads();
    if (tid < 32) {
        float t = 0.f;
#pragma unroll
        for (int r = 0; r < 8; r++) t += red[tid + r * 32];
        g_csum[bh * 32 + tid] = t;
    }
}

// ---------------------------------------------------------------------------
// K2b: diag_vec. q carries SCALE*LOG2E -> factor 0.3*ln2/8. k is physK-perm.
// ---------------------------------------------------------------------------
__global__ __launch_bounds__(256) void diag_kernel() {
    const int b = blockIdx.x;
    const int tid = threadIdx.x;
    const int i = tid & 31;
    const int h = tid >> 5;
    const int ik = physK(i);
    const size_t base = ((size_t)(b * 8 + h) * 1024) * 32;
    float s = 0.f;
#pragma unroll 4
    for (int ss = 0; ss < 32; ss++) {
        size_t off = base + (size_t)(ss * 33) * 32;
        s += g_q[off + i] * g_k[off + ik];
    }
    __shared__ float red[256];
    red[tid] = s;
    __syncthreads();
    if (tid < 32) {
        float t = 0.f;
#pragma unroll
        for (int r = 0; r < 8; r++) t += red[tid + r * 32];
        g_dvec[b * 32 + tid] = t * (0.3f * 0.6931471805599453f / 8.0f);
    }
}

// ---------------------------------------------------------------------------
// K3: tf32 tensor-core flash attention. K/V fragment loads are LDS.128 from
// permuted rows; softmax is a bare ex2 (q pre-scaled by SCALE*log2e).
// ---------------------------------------------------------------------------
#define KPAD 36
#define VPAD 40

__global__ __launch_bounds__(256) void attn_kernel() {
    const int bh = blockIdx.y;
    const int b = bh >> 3;
    const int head = bh & 7;
    const int tid = threadIdx.x;
    const int warp = tid >> 5;
    const int lane = tid & 31;
    const int gid = lane >> 2;
    const int tig = lane & 3;
    const int q0 = blockIdx.x * 128 + warp * 16;

    __shared__ uint32_t Ks[128 * KPAD];
    __shared__ uint32_t Vs[128 * VPAD];

    const float* qb = g_q + (size_t)bh * (N * D);
    uint32_t qa[4][4];
#pragma unroll
    for (int kc = 0; kc < 4; kc++) {
        qa[kc][0] = __float_as_uint(qb[(q0 + gid) * 32 + kc * 8 + tig]);
        qa[kc][1] = __float_as_uint(qb[(q0 + gid + 8) * 32 + kc * 8 + tig]);
        qa[kc][2] = __float_as_uint(qb[(q0 + gid) * 32 + kc * 8 + tig + 4]);
        qa[kc][3] = __float_as_uint(qb[(q0 + gid + 8) * 32 + kc * 8 + tig + 4]);
    }

    float o[4][4];
#pragma unroll
    for (int nt = 0; nt < 4; nt++)
#pragma unroll
        for (int r = 0; r < 4; r++) o[nt][r] = 0.f;
    float llo = 0.f, lhi = 0.f;

    const uint4* kgl = (const uint4*)(g_k + (size_t)bh * (N * D));
    const uint4* vgl = (const uint4*)(g_v + (size_t)bh * (N * D));
    const int src0 = (lane & 28) | (tig >> 1);
    const bool odd = (tig & 1);

    for (int t0 = 0; t0 < 8; t0++) {
#pragma unroll
        for (int r = 0; r < 4; r++) {
            int idx4 = tid + r * 256;           // 0..1023
            int key = idx4 >> 3, c4 = (idx4 & 7) * 4;
            int goff4 = t0 * 1024 + key * 8 + (c4 >> 2);
            *(uint4*)&Ks[key * KPAD + c4] = kgl[goff4];
            *(uint4*)&Vs[key * VPAD + c4] = vgl[goff4];
        }
        __syncthreads();

#pragma unroll 2
        for (int kch = 0; kch < 16; kch++) {
            const int key0 = kch * 8;
            // ---- QK^T ----
            float s0 = 0.f, s1 = 0.f, s2 = 0.f, s3 = 0.f;
            const uint32_t* krow = &Ks[(key0 + gid) * KPAD + tig * 8];
            uint4 kf0 = *(const uint4*)krow;
            uint4 kf1 = *(const uint4*)(krow + 4);
            mma_tf32(s0, s1, s2, s3, qa[0][0], qa[0][1], qa[0][2], qa[0][3], kf0.x, kf0.y);
            mma_tf32(s0, s1, s2, s3, qa[1][0], qa[1][1], qa[1][2], qa[1][3], kf0.z, kf0.w);
            mma_tf32(s0, s1, s2, s3, qa[2][0], qa[2][1], qa[2][2], qa[2][3], kf1.x, kf1.y);
            mma_tf32(s0, s1, s2, s3, qa[3][0], qa[3][1], qa[3][2], qa[3][3], kf1.z, kf1.w);
            // ---- softmax weights ----
            uint32_t p0 = f2tf(ex2f(s0));
            uint32_t p1 = f2tf(ex2f(s1));
            uint32_t p2 = f2tf(ex2f(s2));
            uint32_t p3 = f2tf(ex2f(s3));
            llo += __uint_as_float(p0) + __uint_as_float(p1);
            lhi += __uint_as_float(p2) + __uint_as_float(p3);
            // ---- C-frag -> A-frag permutation ----
            uint32_t e0, e1;
            e0 = __shfl_sync(0xffffffffu, p0, src0);
            e1 = __shfl_sync(0xffffffffu, p1, src0);
            uint32_t pa0 = odd ? e1 : e0;
            e0 = __shfl_sync(0xffffffffu, p0, src0 + 2);
            e1 = __shfl_sync(0xffffffffu, p1, src0 + 2);
            uint32_t pa2 = odd ? e1 : e0;
            e0 = __shfl_sync(0xffffffffu, p2, src0);
            e1 = __shfl_sync(0xffffffffu, p3, src0);
            uint32_t pa1 = odd ? e1 : e0;
            e0 = __shfl_sync(0xffffffffu, p2, src0 + 2);
            e1 = __shfl_sync(0xffffffffu, p3, src0 + 2);
            uint32_t pa3 = odd ? e1 : e0;
            // ---- P @ V ----
            uint4 vf0 = *(const uint4*)&Vs[(key0 + tig) * VPAD + gid * 4];
            uint4 vf1 = *(const uint4*)&Vs[(key0 + tig + 4) * VPAD + gid * 4];
            mma_tf32(o[0][0], o[0][1], o[0][2], o[0][3], pa0, pa1, pa2, pa3, vf0.x, vf1.x);
            mma_tf32(o[1][0], o[1][1], o[1][2], o[1][3], pa0, pa1, pa2, pa3, vf0.y, vf1.y);
            mma_tf32(o[2][0], o[2][1], o[2][2], o[2][3], pa0, pa1, pa2, pa3, vf0.z, vf1.z);
            mma_tf32(o[3][0], o[3][1], o[3][2], o[3][3], pa0, pa1, pa2, pa3, vf0.w, vf1.w);
        }
        __syncthreads();
    }

    llo += __shfl_xor_sync(0xffffffffu, llo, 1);
    llo += __shfl_xor_sync(0xffffffffu, llo, 2);
    lhi += __shfl_xor_sync(0xffffffffu, lhi, 1);
    lhi += __shfl_xor_sync(0xffffffffu, lhi, 2);
    const float invlo = 1.f / llo;
    const float invhi = 1.f / lhi;

    const int rlo = q0 + gid;
    const int rhi = rlo + 8;
    const float dvlo = (rlo < 32) ? g_dvec[b * 32 + rlo] : 0.f;
    const float dvhi = (rhi < 32) ? g_dvec[b * 32 + rhi] : 0.f;
    const float* cs = g_csum + bh * 32;   // physV order
    float* ob = g_ao + ((size_t)b * 256 + head * 32) * 1024;
#pragma unroll
    for (int nt = 0; nt < 4; nt++) {
        int c0 = nt * 8 + 2 * tig;
        int c1 = c0 + 1;
        float cs0 = cs[8 * tig + nt];          // physV(c0)
        float cs1 = cs[8 * tig + 4 + nt];      // physV(c1)
        ob[(size_t)c0 * 1024 + rlo] = o[nt][0] * invlo + dvlo * cs0;
        ob[(size_t)c1 * 1024 + rlo] = o[nt][1] * invlo + dvlo * cs1;
        ob[(size_t)c0 * 1024 + rhi] = o[nt][2] * invhi + dvhi * cs0;
        ob[(size_t)c1 * 1024 + rhi] = o[nt][3] * invhi + dvhi * cs1;
    }
}

// ---------------------------------------------------------------------------
// K4a: gate hidden (FFMA2)
// ---------------------------------------------------------------------------
__global__ __launch_bounds__(256) void gate1_kernel(const float* __restrict__ x,
                                                    const float* __restrict__ w_g1,
                                                    const float* __restrict__ b_g1) {
    const int b = blockIdx.y;
    const int p0 = blockIdx.x * 64;
    const int tid = threadIdx.x;
    const int tx = tid & 15, ty = tid >> 4;

    __shared__ float Ws2[32 * 68];   // [c][u]
    __shared__ float Xs2[32 * 64];   // [c][p]

    u64 acc2[4][2];
#pragma unroll
    for (int i = 0; i < 4; i++) { acc2[i][0] = 0ull; acc2[i][1] = 0ull; }

    for (int kk = 0; kk < 256; kk += 32) {
#pragma unroll
        for (int t = 0; t < 2; t++) {
            int idx4 = tid + t * 256;
            int uu = idx4 >> 3;
            int cc4 = idx4 & 7;
            float4 wv = *(const float4*)&w_g1[uu * 256 + kk + cc4 * 4];
            Ws2[(cc4 * 4 + 0) * 68 + uu] = wv.x;
            Ws2[(cc4 * 4 + 1) * 68 + uu] = wv.y;
            Ws2[(cc4 * 4 + 2) * 68 + uu] = wv.z;
            Ws2[(cc4 * 4 + 3) * 68 + uu] = wv.w;
        }
#pragma unroll
        for (int t = 0; t < 8; t++) {
            int idx = tid + t * 256;
            int cc = idx >> 6;
            int pp = idx & 63;
            int p = p0 + pp;
            int hh = p >> 5;
            int wj = (p & 31) >> 1;
            const float* row = x + ((size_t)(b * 256) + kk + cc) * 1024 + hh * 32;
            Xs2[cc * 64 + pp] = fabsf(row[wj] - row[31 - wj]);
        }
        __syncthreads();
#pragma unroll
        for (int c = 0; c < 32; c++) {
            float4 a = *(float4*)&Ws2[c * 68 + ty * 4];
            double2 bd = *(const double2*)&Xs2[c * 64 + tx * 4];
            u64 b01 = d2u(bd.x), b23 = d2u(bd.y);
            acc2[0][0] = ffma2(dup2(a.x), b01, acc2[0][0]);
            acc2[0][1] = ffma2(dup2(a.x), b23, acc2[0][1]);
            acc2[1][0] = ffma2(dup2(a.y), b01, acc2[1][0]);
            acc2[1][1] = ffma2(dup2(a.y), b23, acc2[1][1]);
            acc2[2][0] = ffma2(dup2(a.z), b01, acc2[2][0]);
            acc2[2][1] = ffma2(dup2(a.z), b23, acc2[2][1]);
            acc2[3][0] = ffma2(dup2(a.w), b01, acc2[3][0]);
            acc2[3][1] = ffma2(dup2(a.w), b23, acc2[3][1]);
        }
        __syncthreads();
    }

#pragma unroll
    for (int ui = 0; ui < 4; ui++) {
        int u = ty * 4 + ui;
        float bias = b_g1[u];
        float2 lo = unpk(acc2[ui][0]), hi = unpk(acc2[ui][1]);
        float v0 = lo.x + bias, v1 = lo.y + bias;
        float v2 = hi.x + bias, v3 = hi.y + bias;
        float4 vout;
        vout.x = 0.5f * v0 * (1.f + erff(v0 * 0.70710678118654752f));
        vout.y = 0.5f * v1 * (1.f + erff(v1 * 0.70710678118654752f));
        vout.z = 0.5f * v2 * (1.f + erff(v2 * 0.70710678118654752f));
        vout.w = 0.5f * v3 * (1.f + erff(v3 * 0.70710678118654752f));
        *(float4*)&g_g1buf[((size_t)(b * 64) + u) * 1024 + p0 + tx * 4] = vout;
    }
}

// ---------------------------------------------------------------------------
// K5: out-proj via tf32 MMA; gate2 (sigmoid reduction) computed in-CTA and
// (1+g) folded into staging.
// ---------------------------------------------------------------------------
__global__ __launch_bounds__(256) void outproj_kernel(const float* __restrict__ w_out,
                                                      const float* __restrict__ b_out,
                                                      const float* __restrict__ w_g2,
                                                      const float* __restrict__ b_g2,
                                                      float* __restrict__ out) {
    const int b = blockIdx.z;
    const int o0 = blockIdx.y * 128;
    const int p0 = blockIdx.x * 128;
    const int tid = threadIdx.x;
    const int warp = tid >> 5;
    const int lane = tid & 31;
    const int gid = lane >> 2;
    const int tig = lane & 3;
    const int o_w = (warp >> 2) * 64;
    const int p_w = (warp & 3) * 32;

    __shared__ uint32_t Ws[128 * WPAD];
    __shared__ uint32_t Xs[32 * XPAD];
    __shared__ float Gs[128];

    // fused gate2: g[p] = 1 + sigmoid(b_g2 + sum_u g1[b,u,p] w_g2[u])
    if (tid < 128) {
        float a = b_g2[0];
        const float* g1 = g_g1buf + (size_t)(b * 64) * 1024 + p0 + tid;
#pragma unroll 8
        for (int u = 0; u < 64; u++) a += g1[(size_t)u * 1024] * w_g2[u];
        Gs[tid] = 1.f + 1.f / (1.f + ex2f(-a * LOG2E));
    }

    float acc[4][4][4];
#pragma unroll
    for (int m = 0; m < 4; m++)
#pragma unroll
        for (int n = 0; n < 4; n++)
#pragma unroll
            for (int r = 0; r < 4; r++) acc[m][n][r] = 0.f;
    __syncthreads();

    for (int kk = 0; kk < 256; kk += 32) {
#pragma unroll
        for (int t = 0; t < 4; t++) {
            int idx4 = tid + t * 256;
            int oo = idx4 >> 3, c4 = (idx4 & 7) * 4;
            float4 wv = *(const float4*)&w_out[(o0 + oo) * 256 + kk + c4];
            *(uint4*)&Ws[oo * WPAD + c4] =
                make_uint4(f2tf(wv.x), f2tf(wv.y), f2tf(wv.z), f2tf(wv.w));
        }
#pragma unroll
        for (int t = 0; t < 4; t++) {
            int idx4 = tid + t * 256;
            int cc = idx4 >> 5, p4 = (idx4 & 31) * 4;
            float4 xv = *(const float4*)&g_ao[((size_t)(b * 256) + kk + cc) * 1024 + p0 + p4];
            xv.x *= Gs[p4 + 0]; xv.y *= Gs[p4 + 1];
            xv.z *= Gs[p4 + 2]; xv.w *= Gs[p4 + 3];
            *(uint4*)&Xs[cc * XPAD + p4] =
                make_uint4(f2tf(xv.x), f2tf(xv.y), f2tf(xv.z), f2tf(xv.w));
        }
        __syncthreads();
#pragma unroll
        for (int kc = 0; kc < 4; kc++) {
            const int ck = kc * 8;
            uint32_t af[4][4];
#pragma unroll
            for (int m = 0; m < 4; m++) {
                const uint32_t* wr = &Ws[(o_w + m * 16 + gid) * WPAD + ck + tig];
                af[m][0] = wr[0];
                af[m][1] = wr[8 * WPAD];
                af[m][2] = wr[4];
                af[m][3] = wr[8 * WPAD + 4];
            }
            uint32_t bf[4][2];
#pragma unroll
            for (int n = 0; n < 4; n++) {
                const uint32_t* xr = &Xs[(ck + tig) * XPAD + p_w + n * 8 + gid];
                bf[n][0] = xr[0];
                bf[n][1] = xr[4 * XPAD];
            }
#pragma unroll
            for (int m = 0; m < 4; m++)
#pragma unroll
                for (int n = 0; n < 4; n++)
                    mma_tf32(acc[m][n][0], acc[m][n][1], acc[m][n][2], acc[m][n][3],
                             af[m][0], af[m][1], af[m][2], af[m][3],
                             bf[n][0], bf[n][1]);
        }
        __syncthreads();
    }

#pragma unroll
    for (int m = 0; m < 4; m++) {
        const int og0 = o0 + o_w + m * 16 + gid;
        const float bs0 = b_out[og0];
        const float bs1 = b_out[og0 + 8];
        float* r0 = out + ((size_t)(b * 256) + og0) * 1024;
        float* r1 = out + ((size_t)(b * 256) + og0 + 8) * 1024;
#pragma unroll
        for (int n = 0; n < 4; n++) {
            const int p = p0 + p_w + n * 8 + 2 * tig;
            *(float2*)&r0[p] = make_float2(acc[m][n][0] + bs0, acc[m][n][1] + bs0);
            *(float2*)&r1[p] = make_float2(acc[m][n][2] + bs1, acc[m][n][3] + bs1);
        }
    }
}

// ---------------------------------------------------------------------------
extern "C" void kernel_launch(void* const* d_in, const int* in_sizes, int n_in,
                              void* d_out, int out_size) {
    const float* x     = (const float*)d_in[0];
    const float* w_qkv = (const float*)d_in[1];
    const float* w_out = (const float*)d_in[2];
    const float* b_out = (const float*)d_in[3];
    const float* w_g1  = (const float*)d_in[4];
    const float* b_g1  = (const float*)d_in[5];
    const float* w_g2  = (const float*)d_in[6];
    const float* b_g2  = (const float*)d_in[7];
    float* out = (float*)d_out;

    qkv_kernel<<<dim3(8, 6, 8), 256>>>(x, w_qkv);
    colsum_kernel<<<64, 256>>>();
    diag_kernel<<<8, 256>>>();
    attn_kernel<<<dim3(8, 64), 256>>>();
    gate1_kernel<<<dim3(16, 8), 256>>>(x, w_g1, b_g1);
    outproj_kernel<<<dim3(8, 2, 8), 256>>>(w_out, b_out, w_g2, b_g2, out);
}

// round 9
// speedup vs baseline: 3.1509x; 1.0406x over previous
#include <cuda_runtime.h>
#include <math.h>
#include <stdint.h>

// ---------------------------------------------------------------------------
// DiagonalMicroAttention: b=8, c=256, h=w=32, heads=8, d=32, n=1024
//   K1 qkv GEMM via tf32 mma -> q (scaled by SCALE*log2e, logical layout),
//      k (physK-permuted), v (physV-permuted), all tf32-rounded
//   K2 colsum(V), diag_vec
//   K3 flash attention via tf32 mma, 32 q-rows per warp, ex2 softmax
//   K4 gate hidden (FFMA2)
//   K5 out-proj via tf32 mma, gate2 + (1+g) fused in
// ---------------------------------------------------------------------------

#define B 8
#define HEADS 8
#define D 32
#define N 1024
#define C 256
#define SCALE 0.1767766952966369f   // 1/sqrt(32)
#define LOG2E 1.4426950408889634f
#define BHND (B * HEADS * N * D)

typedef unsigned long long u64;

__device__ __forceinline__ u64 ffma2(u64 a, u64 b, u64 c) {
    u64 d; asm("fma.rn.f32x2 %0,%1,%2,%3;" : "=l"(d) : "l"(a), "l"(b), "l"(c));
    return d;
}
__device__ __forceinline__ u64 dup2(float v) {
    u64 r; asm("mov.b64 %0, {%1,%1};" : "=l"(r) : "f"(v));
    return r;
}
__device__ __forceinline__ float2 unpk(u64 v) {
    float2 f; asm("mov.b64 {%0,%1}, %2;" : "=f"(f.x), "=f"(f.y) : "l"(v));
    return f;
}
__device__ __forceinline__ u64 d2u(double d) { return __double_as_longlong(d); }

__device__ __forceinline__ uint32_t f2tf(float f) {
    uint32_t r; asm("cvt.rna.tf32.f32 %0, %1;" : "=r"(r) : "f"(f));
    return r;
}
__device__ __forceinline__ float ex2f(float x) {
    float r; asm("ex2.approx.ftz.f32 %0, %1;" : "=f"(r) : "f"(x));
    return r;
}
__device__ __forceinline__ void mma_tf32(float& d0, float& d1, float& d2, float& d3,
                                         uint32_t a0, uint32_t a1, uint32_t a2, uint32_t a3,
                                         uint32_t b0, uint32_t b1) {
    asm("mma.sync.aligned.m16n8k8.row.col.f32.tf32.tf32.f32 "
        "{%0,%1,%2,%3}, {%4,%5,%6,%7}, {%8,%9}, {%0,%1,%2,%3};"
        : "+f"(d0), "+f"(d1), "+f"(d2), "+f"(d3)
        : "r"(a0), "r"(a1), "r"(a2), "r"(a3), "r"(b0), "r"(b1));
}

// in-row permutations for MMA-fragment-friendly K/V storage
__device__ __forceinline__ int physK(int d) {
    return (d & 3) * 8 + (d >> 3) * 2 + ((d >> 2) & 1);
}
__device__ __forceinline__ int physV(int d) {
    return (d & 7) * 4 + (d >> 3);
}

__device__ float g_q[BHND];                // logical layout, x SCALE*LOG2E
__device__ float g_k[BHND];                // physK-permuted rows
__device__ float g_v[BHND];                // physV-permuted rows
__device__ float g_ao[B * C * N];          // attention output, [b][c][n]
__device__ float g_g1buf[B * 64 * N];      // gate hidden
__device__ float g_dvec[B * D];            // ln2*0.3/8 * diag sums
__device__ float g_csum[B * HEADS * D];    // colsum of V, physV order

// ---------------------------------------------------------------------------
// K1: qkv projection via tf32 MMA. CTA tile 128o x 128p, 8 warps 64o x 32p.
// ---------------------------------------------------------------------------
#define WPAD 36
#define XPAD 136

__global__ __launch_bounds__(256) void qkv_kernel(const float* __restrict__ x,
                                                  const float* __restrict__ w) {
    const int b = blockIdx.z;
    const int o0 = blockIdx.y * 128;
    const int p0 = blockIdx.x * 128;
    const int tid = threadIdx.x;
    const int warp = tid >> 5;
    const int lane = tid & 31;
    const int gid = lane >> 2;
    const int tig = lane & 3;
    const int o_w = (warp >> 2) * 64;
    const int p_w = (warp & 3) * 32;

    __shared__ uint32_t Ws[128 * WPAD];
    __shared__ uint32_t Xs[32 * XPAD];

    float acc[4][4][4];
#pragma unroll
    for (int m = 0; m < 4; m++)
#pragma unroll
        for (int n = 0; n < 4; n++)
#pragma unroll
            for (int r = 0; r < 4; r++) acc[m][n][r] = 0.f;

    for (int kk = 0; kk < 256; kk += 32) {
#pragma unroll
        for (int t = 0; t < 4; t++) {
            int idx4 = tid + t * 256;
            int oo = idx4 >> 3, c4 = (idx4 & 7) * 4;
            float4 wv = *(const float4*)&w[(o0 + oo) * 256 + kk + c4];
            *(uint4*)&Ws[oo * WPAD + c4] =
                make_uint4(f2tf(wv.x), f2tf(wv.y), f2tf(wv.z), f2tf(wv.w));
        }
#pragma unroll
        for (int t = 0; t < 4; t++) {
            int idx4 = tid + t * 256;
            int cc = idx4 >> 5, p4 = (idx4 & 31) * 4;
            float4 xv = *(const float4*)&x[((b * 256) + kk + cc) * 1024 + p0 + p4];
            *(uint4*)&Xs[cc * XPAD + p4] =
                make_uint4(f2tf(xv.x), f2tf(xv.y), f2tf(xv.z), f2tf(xv.w));
        }
        __syncthreads();
#pragma unroll
        for (int kc = 0; kc < 4; kc++) {
            const int ck = kc * 8;
            uint32_t af[4][4];
#pragma unroll
            for (int m = 0; m < 4; m++) {
                const uint32_t* wr = &Ws[(o_w + m * 16 + gid) * WPAD + ck + tig];
                af[m][0] = wr[0];
                af[m][1] = wr[8 * WPAD];
                af[m][2] = wr[4];
                af[m][3] = wr[8 * WPAD + 4];
            }
            uint32_t bf[4][2];
#pragma unroll
            for (int n = 0; n < 4; n++) {
                const uint32_t* xr = &Xs[(ck + tig) * XPAD + p_w + n * 8 + gid];
                bf[n][0] = xr[0];
                bf[n][1] = xr[4 * XPAD];
            }
#pragma unroll
            for (int m = 0; m < 4; m++)
#pragma unroll
                for (int n = 0; n < 4; n++)
                    mma_tf32(acc[m][n][0], acc[m][n][1], acc[m][n][2], acc[m][n][3],
                             af[m][0], af[m][1], af[m][2], af[m][3],
                             bf[n][0], bf[n][1]);
        }
        __syncthreads();
    }

    // epilogue: route to q/k/v with per-part layout + scaling
    const int part = (o0 + o_w) >> 8;
    float* dst = (part == 0) ? g_q : ((part == 1) ? g_k : g_v);
    const float mult = (part == 0) ? (SCALE * LOG2E) : 1.0f;
#pragma unroll
    for (int m = 0; m < 4; m++) {
        const int ob = o0 + o_w + m * 16;
        const int head = (ob >> 5) & 7;
        const int dl0 = (ob & 31) + gid;
        const int dl1 = dl0 + 8;
        int d0, d1;
        if (part == 0)      { d0 = dl0;        d1 = dl1; }
        else if (part == 1) { d0 = physK(dl0); d1 = physK(dl1); }
        else                { d0 = physV(dl0); d1 = physV(dl1); }
        float* hb = dst + ((size_t)(b * 8 + head) * 1024) * 32;
#pragma unroll
        for (int n = 0; n < 4; n++) {
            const int p = p0 + p_w + n * 8 + 2 * tig;
            float* pb = hb + (size_t)p * 32;
            pb[d0]      = __uint_as_float(f2tf(acc[m][n][0] * mult));
            pb[32 + d0] = __uint_as_float(f2tf(acc[m][n][1] * mult));
            pb[d1]      = __uint_as_float(f2tf(acc[m][n][2] * mult));
            pb[32 + d1] = __uint_as_float(f2tf(acc[m][n][3] * mult));
        }
    }
}

// ---------------------------------------------------------------------------
// K2a: column sums of V per (b,h), physV order.
// ---------------------------------------------------------------------------
__global__ __launch_bounds__(256) void colsum_kernel() {
    const int bh = blockIdx.x;
    const int tid = threadIdx.x;
    const int dd = tid & 31;
    const int sl = tid >> 5;
    const float* vb = g_v + (size_t)bh * 1024 * 32;
    float s = 0.f;
    for (int j = sl * 128; j < sl * 128 + 128; j++) s += vb[(size_t)j * 32 + dd];
    __shared__ float red[256];
    red[tid] = s;
    __syncthreads();
    if (tid < 32) {
        float t = 0.f;
#pragma unroll
        for (int r = 0; r < 8; r++) t += red[tid + r * 32];
        g_csum[bh * 32 + tid] = t;
    }
}

// ---------------------------------------------------------------------------
// K2b: diag_vec. q carries SCALE*LOG2E -> factor 0.3*ln2/8. k is physK-perm.
// ---------------------------------------------------------------------------
__global__ __launch_bounds__(256) void diag_kernel() {
    const int b = blockIdx.x;
    const int tid = threadIdx.x;
    const int i = tid & 31;
    const int h = tid >> 5;
    const int ik = physK(i);
    const size_t base = ((size_t)(b * 8 + h) * 1024) * 32;
    float s = 0.f;
#pragma unroll 4
    for (int ss = 0; ss < 32; ss++) {
        size_t off = base + (size_t)(ss * 33) * 32;
        s += g_q[off + i] * g_k[off + ik];
    }
    __shared__ float red[256];
    red[tid] = s;
    __syncthreads();
    if (tid < 32) {
        float t = 0.f;
#pragma unroll
        for (int r = 0; r < 8; r++) t += red[tid + r * 32];
        g_dvec[b * 32 + tid] = t * (0.3f * 0.6931471805599453f / 8.0f);
    }
}

// ---------------------------------------------------------------------------
// K3: tf32 flash attention, 4 warps/CTA, 32 q-rows per warp (2 m16 tiles).
// Same K/V fragments feed 16 MMAs per 8-key chunk.
// ---------------------------------------------------------------------------
#define KPAD 36
#define VPAD 40

__global__ __launch_bounds__(128, 4) void attn_kernel() {
    const int bh = blockIdx.y;
    const int b = bh >> 3;
    const int head = bh & 7;
    const int tid = threadIdx.x;
    const int warp = tid >> 5;
    const int lane = tid & 31;
    const int gid = lane >> 2;
    const int tig = lane & 3;
    const int q0 = blockIdx.x * 128 + warp * 32;

    __shared__ uint32_t Ks[128 * KPAD];
    __shared__ uint32_t Vs[128 * VPAD];

    const float* qb = g_q + (size_t)bh * (N * D);
    uint32_t qa[2][4][4];
#pragma unroll
    for (int tt = 0; tt < 2; tt++) {
        const int rb = q0 + tt * 16;
#pragma unroll
        for (int kc = 0; kc < 4; kc++) {
            qa[tt][kc][0] = __float_as_uint(qb[(rb + gid) * 32 + kc * 8 + tig]);
            qa[tt][kc][1] = __float_as_uint(qb[(rb + gid + 8) * 32 + kc * 8 + tig]);
            qa[tt][kc][2] = __float_as_uint(qb[(rb + gid) * 32 + kc * 8 + tig + 4]);
            qa[tt][kc][3] = __float_as_uint(qb[(rb + gid + 8) * 32 + kc * 8 + tig + 4]);
        }
    }

    float o[2][4][4];
#pragma unroll
    for (int tt = 0; tt < 2; tt++)
#pragma unroll
        for (int nt = 0; nt < 4; nt++)
#pragma unroll
            for (int r = 0; r < 4; r++) o[tt][nt][r] = 0.f;
    float lv[2][2];
    lv[0][0] = lv[0][1] = lv[1][0] = lv[1][1] = 0.f;

    const uint4* kgl = (const uint4*)(g_k + (size_t)bh * (N * D));
    const uint4* vgl = (const uint4*)(g_v + (size_t)bh * (N * D));
    const int src0 = (lane & 28) | (tig >> 1);
    const bool odd = (tig & 1);

    for (int t0 = 0; t0 < 8; t0++) {
#pragma unroll
        for (int r = 0; r < 8; r++) {
            int idx4 = tid + r * 128;           // 0..1023
            int key = idx4 >> 3, c4 = (idx4 & 7) * 4;
            int goff4 = t0 * 1024 + key * 8 + (c4 >> 2);
            *(uint4*)&Ks[key * KPAD + c4] = kgl[goff4];
            *(uint4*)&Vs[key * VPAD + c4] = vgl[goff4];
        }
        __syncthreads();

#pragma unroll 2
        for (int kch = 0; kch < 16; kch++) {
            const int key0 = kch * 8;
            // ---- K fragments (shared by both m-tiles) ----
            const uint32_t* krow = &Ks[(key0 + gid) * KPAD + tig * 8];
            uint4 kf0 = *(const uint4*)krow;
            uint4 kf1 = *(const uint4*)(krow + 4);
            // ---- V fragments (shared by both m-tiles) ----
            uint4 vf0 = *(const uint4*)&Vs[(key0 + tig) * VPAD + gid * 4];
            uint4 vf1 = *(const uint4*)&Vs[(key0 + tig + 4) * VPAD + gid * 4];

#pragma unroll
            for (int tt = 0; tt < 2; tt++) {
                // ---- QK^T ----
                float s0 = 0.f, s1 = 0.f, s2 = 0.f, s3 = 0.f;
                mma_tf32(s0, s1, s2, s3, qa[tt][0][0], qa[tt][0][1], qa[tt][0][2], qa[tt][0][3], kf0.x, kf0.y);
                mma_tf32(s0, s1, s2, s3, qa[tt][1][0], qa[tt][1][1], qa[tt][1][2], qa[tt][1][3], kf0.z, kf0.w);
                mma_tf32(s0, s1, s2, s3, qa[tt][2][0], qa[tt][2][1], qa[tt][2][2], qa[tt][2][3], kf1.x, kf1.y);
                mma_tf32(s0, s1, s2, s3, qa[tt][3][0], qa[tt][3][1], qa[tt][3][2], qa[tt][3][3], kf1.z, kf1.w);
                // ---- softmax weights ----
                float f0 = ex2f(s0), f1 = ex2f(s1), f2 = ex2f(s2), f3 = ex2f(s3);
                lv[tt][0] += f0 + f1;
                lv[tt][1] += f2 + f3;
                uint32_t p0 = __float_as_uint(f0);
                uint32_t p1 = __float_as_uint(f1);
                uint32_t p2 = __float_as_uint(f2);
                uint32_t p3 = __float_as_uint(f3);
                // ---- C-frag -> A-frag permutation ----
                uint32_t e0, e1;
                e0 = __shfl_sync(0xffffffffu, p0, src0);
                e1 = __shfl_sync(0xffffffffu, p1, src0);
                uint32_t pa0 = odd ? e1 : e0;
                e0 = __shfl_sync(0xffffffffu, p0, src0 + 2);
                e1 = __shfl_sync(0xffffffffu, p1, src0 + 2);
                uint32_t pa2 = odd ? e1 : e0;
                e0 = __shfl_sync(0xffffffffu, p2, src0);
                e1 = __shfl_sync(0xffffffffu, p3, src0);
                uint32_t pa1 = odd ? e1 : e0;
                e0 = __shfl_sync(0xffffffffu, p2, src0 + 2);
                e1 = __shfl_sync(0xffffffffu, p3, src0 + 2);
                uint32_t pa3 = odd ? e1 : e0;
                // ---- P @ V ----
                mma_tf32(o[tt][0][0], o[tt][0][1], o[tt][0][2], o[tt][0][3], pa0, pa1, pa2, pa3, vf0.x, vf1.x);
                mma_tf32(o[tt][1][0], o[tt][1][1], o[tt][1][2], o[tt][1][3], pa0, pa1, pa2, pa3, vf0.y, vf1.y);
                mma_tf32(o[tt][2][0], o[tt][2][1], o[tt][2][2], o[tt][2][3], pa0, pa1, pa2, pa3, vf0.z, vf1.z);
                mma_tf32(o[tt][3][0], o[tt][3][1], o[tt][3][2], o[tt][3][3], pa0, pa1, pa2, pa3, vf0.w, vf1.w);
            }
        }
        __syncthreads();
    }

    const float* cs = g_csum + bh * 32;   // physV order
    float* ob = g_ao + ((size_t)b * 256 + head * 32) * 1024;
#pragma unroll
    for (int tt = 0; tt < 2; tt++) {
        float llo = lv[tt][0], lhi = lv[tt][1];
        llo += __shfl_xor_sync(0xffffffffu, llo, 1);
        llo += __shfl_xor_sync(0xffffffffu, llo, 2);
        lhi += __shfl_xor_sync(0xffffffffu, lhi, 1);
        lhi += __shfl_xor_sync(0xffffffffu, lhi, 2);
        const float invlo = 1.f / llo;
        const float invhi = 1.f / lhi;

        const int rlo = q0 + tt * 16 + gid;
        const int rhi = rlo + 8;
        const float dvlo = (rlo < 32) ? g_dvec[b * 32 + rlo] : 0.f;
        const float dvhi = (rhi < 32) ? g_dvec[b * 32 + rhi] : 0.f;
#pragma unroll
        for (int nt = 0; nt < 4; nt++) {
            int c0 = nt * 8 + 2 * tig;
            int c1 = c0 + 1;
            float cs0 = cs[8 * tig + nt];          // physV(c0)
            float cs1 = cs[8 * tig + 4 + nt];      // physV(c1)
            ob[(size_t)c0 * 1024 + rlo] = o[tt][nt][0] * invlo + dvlo * cs0;
            ob[(size_t)c1 * 1024 + rlo] = o[tt][nt][1] * invlo + dvlo * cs1;
            ob[(size_t)c0 * 1024 + rhi] = o[tt][nt][2] * invhi + dvhi * cs0;
            ob[(size_t)c1 * 1024 + rhi] = o[tt][nt][3] * invhi + dvhi * cs1;
        }
    }
}

// ---------------------------------------------------------------------------
// K4a: gate hidden (FFMA2)
// ---------------------------------------------------------------------------
__global__ __launch_bounds__(256) void gate1_kernel(const float* __restrict__ x,
                                                    const float* __restrict__ w_g1,
                                                    const float* __restrict__ b_g1) {
    const int b = blockIdx.y;
    const int p0 = blockIdx.x * 64;
    const int tid = threadIdx.x;
    const int tx = tid & 15, ty = tid >> 4;

    __shared__ float Ws2[32 * 68];   // [c][u]
    __shared__ float Xs2[32 * 64];   // [c][p]

    u64 acc2[4][2];
#pragma unroll
    for (int i = 0; i < 4; i++) { acc2[i][0] = 0ull; acc2[i][1] = 0ull; }

    for (int kk = 0; kk < 256; kk += 32) {
#pragma unroll
        for (int t = 0; t < 2; t++) {
            int idx4 = tid + t * 256;
            int uu = idx4 >> 3;
            int cc4 = idx4 & 7;
            float4 wv = *(const float4*)&w_g1[uu * 256 + kk + cc4 * 4];
            Ws2[(cc4 * 4 + 0) * 68 + uu] = wv.x;
            Ws2[(cc4 * 4 + 1) * 68 + uu] = wv.y;
            Ws2[(cc4 * 4 + 2) * 68 + uu] = wv.z;
            Ws2[(cc4 * 4 + 3) * 68 + uu] = wv.w;
        }
#pragma unroll
        for (int t = 0; t < 8; t++) {
            int idx = tid + t * 256;
            int cc = idx >> 6;
            int pp = idx & 63;
            int p = p0 + pp;
            int hh = p >> 5;
            int wj = (p & 31) >> 1;
            const float* row = x + ((size_t)(b * 256) + kk + cc) * 1024 + hh * 32;
            Xs2[cc * 64 + pp] = fabsf(row[wj] - row[31 - wj]);
        }
        __syncthreads();
#pragma unroll
        for (int c = 0; c < 32; c++) {
            float4 a = *(float4*)&Ws2[c * 68 + ty * 4];
            double2 bd = *(const double2*)&Xs2[c * 64 + tx * 4];
            u64 b01 = d2u(bd.x), b23 = d2u(bd.y);
            acc2[0][0] = ffma2(dup2(a.x), b01, acc2[0][0]);
            acc2[0][1] = ffma2(dup2(a.x), b23, acc2[0][1]);
            acc2[1][0] = ffma2(dup2(a.y), b01, acc2[1][0]);
            acc2[1][1] = ffma2(dup2(a.y), b23, acc2[1][1]);
            acc2[2][0] = ffma2(dup2(a.z), b01, acc2[2][0]);
            acc2[2][1] = ffma2(dup2(a.z), b23, acc2[2][1]);
            acc2[3][0] = ffma2(dup2(a.w), b01, acc2[3][0]);
            acc2[3][1] = ffma2(dup2(a.w), b23, acc2[3][1]);
        }
        __syncthreads();
    }

#pragma unroll
    for (int ui = 0; ui < 4; ui++) {
        int u = ty * 4 + ui;
        float bias = b_g1[u];
        float2 lo = unpk(acc2[ui][0]), hi = unpk(acc2[ui][1]);
        float v0 = lo.x + bias, v1 = lo.y + bias;
        float v2 = hi.x + bias, v3 = hi.y + bias;
        float4 vout;
        vout.x = 0.5f * v0 * (1.f + erff(v0 * 0.70710678118654752f));
        vout.y = 0.5f * v1 * (1.f + erff(v1 * 0.70710678118654752f));
        vout.z = 0.5f * v2 * (1.f + erff(v2 * 0.70710678118654752f));
        vout.w = 0.5f * v3 * (1.f + erff(v3 * 0.70710678118654752f));
        *(float4*)&g_g1buf[((size_t)(b * 64) + u) * 1024 + p0 + tx * 4] = vout;
    }
}

// ---------------------------------------------------------------------------
// K5: out-proj via tf32 MMA; gate2 computed in-CTA, (1+g) folded into staging.
// ---------------------------------------------------------------------------
__global__ __launch_bounds__(256) void outproj_kernel(const float* __restrict__ w_out,
                                                      const float* __restrict__ b_out,
                                                      const float* __restrict__ w_g2,
                                                      const float* __restrict__ b_g2,
                                                      float* __restrict__ out) {
    const int b = blockIdx.z;
    const int o0 = blockIdx.y * 128;
    const int p0 = blockIdx.x * 128;
    const int tid = threadIdx.x;
    const int warp = tid >> 5;
    const int lane = tid & 31;
    const int gid = lane >> 2;
    const int tig = lane & 3;
    const int o_w = (warp >> 2) * 64;
    const int p_w = (warp & 3) * 32;

    __shared__ uint32_t Ws[128 * WPAD];
    __shared__ uint32_t Xs[32 * XPAD];
    __shared__ float Gs[128];

    if (tid < 128) {
        float a = b_g2[0];
        const float* g1 = g_g1buf + (size_t)(b * 64) * 1024 + p0 + tid;
#pragma unroll 8
        for (int u = 0; u < 64; u++) a += g1[(size_t)u * 1024] * w_g2[u];
        Gs[tid] = 1.f + 1.f / (1.f + ex2f(-a * LOG2E));
    }

    float acc[4][4][4];
#pragma unroll
    for (int m = 0; m < 4; m++)
#pragma unroll
        for (int n = 0; n < 4; n++)
#pragma unroll
            for (int r = 0; r < 4; r++) acc[m][n][r] = 0.f;
    __syncthreads();

    for (int kk = 0; kk < 256; kk += 32) {
#pragma unroll
        for (int t = 0; t < 4; t++) {
            int idx4 = tid + t * 256;
            int oo = idx4 >> 3, c4 = (idx4 & 7) * 4;
            float4 wv = *(const float4*)&w_out[(o0 + oo) * 256 + kk + c4];
            *(uint4*)&Ws[oo * WPAD + c4] =
                make_uint4(f2tf(wv.x), f2tf(wv.y), f2tf(wv.z), f2tf(wv.w));
        }
#pragma unroll
        for (int t = 0; t < 4; t++) {
            int idx4 = tid + t * 256;
            int cc = idx4 >> 5, p4 = (idx4 & 31) * 4;
            float4 xv = *(const float4*)&g_ao[((size_t)(b * 256) + kk + cc) * 1024 + p0 + p4];
            xv.x *= Gs[p4 + 0]; xv.y *= Gs[p4 + 1];
            xv.z *= Gs[p4 + 2]; xv.w *= Gs[p4 + 3];
            *(uint4*)&Xs[cc * XPAD + p4] =
                make_uint4(f2tf(xv.x), f2tf(xv.y), f2tf(xv.z), f2tf(xv.w));
        }
        __syncthreads();
#pragma unroll
        for (int kc = 0; kc < 4; kc++) {
            const int ck = kc * 8;
            uint32_t af[4][4];
#pragma unroll
            for (int m = 0; m < 4; m++) {
                const uint32_t* wr = &Ws[(o_w + m * 16 + gid) * WPAD + ck + tig];
                af[m][0] = wr[0];
                af[m][1] = wr[8 * WPAD];
                af[m][2] = wr[4];
                af[m][3] = wr[8 * WPAD + 4];
            }
            uint32_t bf[4][2];
#pragma unroll
            for (int n = 0; n < 4; n++) {
                const uint32_t* xr = &Xs[(ck + tig) * XPAD + p_w + n * 8 + gid];
                bf[n][0] = xr[0];
                bf[n][1] = xr[4 * XPAD];
            }
#pragma unroll
            for (int m = 0; m < 4; m++)
#pragma unroll
                for (int n = 0; n < 4; n++)
                    mma_tf32(acc[m][n][0], acc[m][n][1], acc[m][n][2], acc[m][n][3],
                             af[m][0], af[m][1], af[m][2], af[m][3],
                             bf[n][0], bf[n][1]);
        }
        __syncthreads();
    }

#pragma unroll
    for (int m = 0; m < 4; m++) {
        const int og0 = o0 + o_w + m * 16 + gid;
        const float bs0 = b_out[og0];
        const float bs1 = b_out[og0 + 8];
        float* r0 = out + ((size_t)(b * 256) + og0) * 1024;
        float* r1 = out + ((size_t)(b * 256) + og0 + 8) * 1024;
#pragma unroll
        for (int n = 0; n < 4; n++) {
            const int p = p0 + p_w + n * 8 + 2 * tig;
            *(float2*)&r0[p] = make_float2(acc[m][n][0] + bs0, acc[m][n][1] + bs0);
            *(float2*)&r1[p] = make_float2(acc[m][n][2] + bs1, acc[m][n][3] + bs1);
        }
    }
}

// ---------------------------------------------------------------------------
extern "C" void kernel_launch(void* const* d_in, const int* in_sizes, int n_in,
                              void* d_out, int out_size) {
    const float* x     = (const float*)d_in[0];
    const float* w_qkv = (const float*)d_in[1];
    const float* w_out = (const float*)d_in[2];
    const float* b_out = (const float*)d_in[3];
    const float* w_g1  = (const float*)d_in[4];
    const float* b_g1  = (const float*)d_in[5];
    const float* w_g2  = (const float*)d_in[6];
    const float* b_g2  = (const float*)d_in[7];
    float* out = (float*)d_out;

    qkv_kernel<<<dim3(8, 6, 8), 256>>>(x, w_qkv);
    colsum_kernel<<<64, 256>>>();
    diag_kernel<<<8, 256>>>();
    attn_kernel<<<dim3(8, 64), 128>>>();
    gate1_kernel<<<dim3(16, 8), 256>>>(x, w_g1, b_g1);
    outproj_kernel<<<dim3(8, 2, 8), 256>>>(w_out, b_out, w_g2, b_g2, out);
}

// round 10
// speedup vs baseline: 3.3476x; 1.0625x over previous
#include <cuda_runtime.h>
#include <math.h>
#include <stdint.h>

// ---------------------------------------------------------------------------
// DiagonalMicroAttention: b=8, c=256, h=w=32, heads=8, d=32, n=1024
//   K1 qkv GEMM via tf32 mma -> q (scaled by SCALE*log2e, logical layout),
//      k (physK-permuted), v (physV-permuted), all tf32-rounded
//   K2 colsum(V) + diag_vec (fused)
//   K3 flash attention via tf32 mma, 32 q-rows/warp, cp.async pipelined K/V
//   K4 gate hidden (FFMA2)
//   K5 out-proj via tf32 mma, gate2 + (1+g) fused in
// ---------------------------------------------------------------------------

#define B 8
#define HEADS 8
#define D 32
#define N 1024
#define C 256
#define SCALE 0.1767766952966369f   // 1/sqrt(32)
#define LOG2E 1.4426950408889634f
#define BHND (B * HEADS * N * D)

typedef unsigned long long u64;

__device__ __forceinline__ u64 ffma2(u64 a, u64 b, u64 c) {
    u64 d; asm("fma.rn.f32x2 %0,%1,%2,%3;" : "=l"(d) : "l"(a), "l"(b), "l"(c));
    return d;
}
__device__ __forceinline__ u64 dup2(float v) {
    u64 r; asm("mov.b64 %0, {%1,%1};" : "=l"(r) : "f"(v));
    return r;
}
__device__ __forceinline__ float2 unpk(u64 v) {
    float2 f; asm("mov.b64 {%0,%1}, %2;" : "=f"(f.x), "=f"(f.y) : "l"(v));
    return f;
}
__device__ __forceinline__ u64 d2u(double d) { return __double_as_longlong(d); }

__device__ __forceinline__ uint32_t f2tf(float f) {
    uint32_t r; asm("cvt.rna.tf32.f32 %0, %1;" : "=r"(r) : "f"(f));
    return r;
}
__device__ __forceinline__ float ex2f(float x) {
    float r; asm("ex2.approx.ftz.f32 %0, %1;" : "=f"(r) : "f"(x));
    return r;
}
__device__ __forceinline__ void mma_tf32(float& d0, float& d1, float& d2, float& d3,
                                         uint32_t a0, uint32_t a1, uint32_t a2, uint32_t a3,
                                         uint32_t b0, uint32_t b1) {
    asm("mma.sync.aligned.m16n8k8.row.col.f32.tf32.tf32.f32 "
        "{%0,%1,%2,%3}, {%4,%5,%6,%7}, {%8,%9}, {%0,%1,%2,%3};"
        : "+f"(d0), "+f"(d1), "+f"(d2), "+f"(d3)
        : "r"(a0), "r"(a1), "r"(a2), "r"(a3), "r"(b0), "r"(b1));
}
__device__ __forceinline__ void cp16(uint32_t smem_addr, const void* gptr) {
    asm volatile("cp.async.cg.shared.global [%0], [%1], 16;"
                 :: "r"(smem_addr), "l"(gptr));
}

// in-row permutations for MMA-fragment-friendly K/V storage
__device__ __forceinline__ int physK(int d) {
    return (d & 3) * 8 + (d >> 3) * 2 + ((d >> 2) & 1);
}
__device__ __forceinline__ int physV(int d) {
    return (d & 7) * 4 + (d >> 3);
}

__device__ float g_q[BHND];                // logical layout, x SCALE*LOG2E
__device__ float g_k[BHND];                // physK-permuted rows
__device__ float g_v[BHND];                // physV-permuted rows
__device__ float g_ao[B * C * N];          // attention output, [b][c][n]
__device__ float g_g1buf[B * 64 * N];      // gate hidden
__device__ float g_dvec[B * D];            // ln2*0.3/8 * diag sums
__device__ float g_csum[B * HEADS * D];    // colsum of V, physV order

// ---------------------------------------------------------------------------
// K1: qkv projection via tf32 MMA. CTA tile 128o x 128p, 8 warps 64o x 32p.
// ---------------------------------------------------------------------------
#define WPAD 36
#define XPAD 136

__global__ __launch_bounds__(256) void qkv_kernel(const float* __restrict__ x,
                                                  const float* __restrict__ w) {
    const int b = blockIdx.z;
    const int o0 = blockIdx.y * 128;
    const int p0 = blockIdx.x * 128;
    const int tid = threadIdx.x;
    const int warp = tid >> 5;
    const int lane = tid & 31;
    const int gid = lane >> 2;
    const int tig = lane & 3;
    const int o_w = (warp >> 2) * 64;
    const int p_w = (warp & 3) * 32;

    __shared__ uint32_t Ws[128 * WPAD];
    __shared__ uint32_t Xs[32 * XPAD];

    float acc[4][4][4];
#pragma unroll
    for (int m = 0; m < 4; m++)
#pragma unroll
        for (int n = 0; n < 4; n++)
#pragma unroll
            for (int r = 0; r < 4; r++) acc[m][n][r] = 0.f;

    for (int kk = 0; kk < 256; kk += 32) {
#pragma unroll
        for (int t = 0; t < 4; t++) {
            int idx4 = tid + t * 256;
            int oo = idx4 >> 3, c4 = (idx4 & 7) * 4;
            float4 wv = *(const float4*)&w[(o0 + oo) * 256 + kk + c4];
            *(uint4*)&Ws[oo * WPAD + c4] =
                make_uint4(f2tf(wv.x), f2tf(wv.y), f2tf(wv.z), f2tf(wv.w));
        }
#pragma unroll
        for (int t = 0; t < 4; t++) {
            int idx4 = tid + t * 256;
            int cc = idx4 >> 5, p4 = (idx4 & 31) * 4;
            float4 xv = *(const float4*)&x[((b * 256) + kk + cc) * 1024 + p0 + p4];
            *(uint4*)&Xs[cc * XPAD + p4] =
                make_uint4(f2tf(xv.x), f2tf(xv.y), f2tf(xv.z), f2tf(xv.w));
        }
        __syncthreads();
#pragma unroll
        for (int kc = 0; kc < 4; kc++) {
            const int ck = kc * 8;
            uint32_t af[4][4];
#pragma unroll
            for (int m = 0; m < 4; m++) {
                const uint32_t* wr = &Ws[(o_w + m * 16 + gid) * WPAD + ck + tig];
                af[m][0] = wr[0];
                af[m][1] = wr[8 * WPAD];
                af[m][2] = wr[4];
                af[m][3] = wr[8 * WPAD + 4];
            }
            uint32_t bf[4][2];
#pragma unroll
            for (int n = 0; n < 4; n++) {
                const uint32_t* xr = &Xs[(ck + tig) * XPAD + p_w + n * 8 + gid];
                bf[n][0] = xr[0];
                bf[n][1] = xr[4 * XPAD];
            }
#pragma unroll
            for (int m = 0; m < 4; m++)
#pragma unroll
                for (int n = 0; n < 4; n++)
                    mma_tf32(acc[m][n][0], acc[m][n][1], acc[m][n][2], acc[m][n][3],
                             af[m][0], af[m][1], af[m][2], af[m][3],
                             bf[n][0], bf[n][1]);
        }
        __syncthreads();
    }

    // epilogue: route to q/k/v with per-part layout + scaling
    const int part = (o0 + o_w) >> 8;
    float* dst = (part == 0) ? g_q : ((part == 1) ? g_k : g_v);
    const float mult = (part == 0) ? (SCALE * LOG2E) : 1.0f;
#pragma unroll
    for (int m = 0; m < 4; m++) {
        const int ob = o0 + o_w + m * 16;
        const int head = (ob >> 5) & 7;
        const int dl0 = (ob & 31) + gid;
        const int dl1 = dl0 + 8;
        int d0, d1;
        if (part == 0)      { d0 = dl0;        d1 = dl1; }
        else if (part == 1) { d0 = physK(dl0); d1 = physK(dl1); }
        else                { d0 = physV(dl0); d1 = physV(dl1); }
        float* hb = dst + ((size_t)(b * 8 + head) * 1024) * 32;
#pragma unroll
        for (int n = 0; n < 4; n++) {
            const int p = p0 + p_w + n * 8 + 2 * tig;
            float* pb = hb + (size_t)p * 32;
            pb[d0]      = __uint_as_float(f2tf(acc[m][n][0] * mult));
            pb[32 + d0] = __uint_as_float(f2tf(acc[m][n][1] * mult));
            pb[d1]      = __uint_as_float(f2tf(acc[m][n][2] * mult));
            pb[32 + d1] = __uint_as_float(f2tf(acc[m][n][3] * mult));
        }
    }
}

// ---------------------------------------------------------------------------
// K2: fused colsum(V) (blocks 0..63) + diag_vec (blocks 64..71).
// ---------------------------------------------------------------------------
__global__ __launch_bounds__(256) void reduce_kernel() {
    const int tid = threadIdx.x;
    __shared__ float red[256];
    if (blockIdx.x < 64) {
        const int bh = blockIdx.x;
        const int dd = tid & 31;
        const int sl = tid >> 5;
        const float* vb = g_v + (size_t)bh * 1024 * 32;
        float s = 0.f;
        for (int j = sl * 128; j < sl * 128 + 128; j++) s += vb[(size_t)j * 32 + dd];
        red[tid] = s;
        __syncthreads();
        if (tid < 32) {
            float t = 0.f;
#pragma unroll
            for (int r = 0; r < 8; r++) t += red[tid + r * 32];
            g_csum[bh * 32 + tid] = t;
        }
    } else {
        const int b = blockIdx.x - 64;
        const int i = tid & 31;
        const int h = tid >> 5;
        const int ik = physK(i);
        const size_t base = ((size_t)(b * 8 + h) * 1024) * 32;
        float s = 0.f;
#pragma unroll 4
        for (int ss = 0; ss < 32; ss++) {
            size_t off = base + (size_t)(ss * 33) * 32;
            s += g_q[off + i] * g_k[off + ik];
        }
        red[tid] = s;
        __syncthreads();
        if (tid < 32) {
            float t = 0.f;
#pragma unroll
            for (int r = 0; r < 8; r++) t += red[tid + r * 32];
            g_dvec[b * 32 + tid] = t * (0.3f * 0.6931471805599453f / 8.0f);
        }
    }
}

// ---------------------------------------------------------------------------
// K3: tf32 flash attention, 4 warps/CTA, 32 q-rows/warp, cp.async-pipelined
// K/V staging (2-slot ring of 64-key halves inside the same smem footprint).
// ---------------------------------------------------------------------------
#define KPAD 36
#define VPAD 40

__global__ __launch_bounds__(128, 4) void attn_kernel() {
    const int bh = blockIdx.y;
    const int b = bh >> 3;
    const int head = bh & 7;
    const int tid = threadIdx.x;
    const int warp = tid >> 5;
    const int lane = tid & 31;
    const int gid = lane >> 2;
    const int tig = lane & 3;
    const int q0 = blockIdx.x * 128 + warp * 32;

    __shared__ uint32_t Ks[128 * KPAD];   // 2 x 64-key slots
    __shared__ uint32_t Vs[128 * VPAD];

    const float* qb = g_q + (size_t)bh * (N * D);
    uint32_t qa[2][4][4];
#pragma unroll
    for (int tt = 0; tt < 2; tt++) {
        const int rb = q0 + tt * 16;
#pragma unroll
        for (int kc = 0; kc < 4; kc++) {
            qa[tt][kc][0] = __float_as_uint(qb[(rb + gid) * 32 + kc * 8 + tig]);
            qa[tt][kc][1] = __float_as_uint(qb[(rb + gid + 8) * 32 + kc * 8 + tig]);
            qa[tt][kc][2] = __float_as_uint(qb[(rb + gid) * 32 + kc * 8 + tig + 4]);
            qa[tt][kc][3] = __float_as_uint(qb[(rb + gid + 8) * 32 + kc * 8 + tig + 4]);
        }
    }

    float o[2][4][4];
#pragma unroll
    for (int tt = 0; tt < 2; tt++)
#pragma unroll
        for (int nt = 0; nt < 4; nt++)
#pragma unroll
            for (int r = 0; r < 4; r++) o[tt][nt][r] = 0.f;
    float lv[2][2];
    lv[0][0] = lv[0][1] = lv[1][0] = lv[1][1] = 0.f;

    const uint4* kgl = (const uint4*)(g_k + (size_t)bh * (N * D));
    const uint4* vgl = (const uint4*)(g_v + (size_t)bh * (N * D));
    const uint32_t ksb = (uint32_t)__cvta_generic_to_shared(Ks);
    const uint32_t vsb = (uint32_t)__cvta_generic_to_shared(Vs);
    const int src0 = (lane & 28) | (tig >> 1);
    const bool odd = (tig & 1);

    // per-thread load assignment for a 64-key half: 4 x (16B K + 16B V)
    const int lkey0 = tid >> 3;            // thread's base key (advances by 16)
    const int lc16 = tid & 7;              // 16B column unit within 128B row

    // prologue: halves 0 and 1 in flight
#pragma unroll
    for (int h = 0; h < 2; h++) {
#pragma unroll
        for (int r = 0; r < 4; r++) {
            int key = lkey0 + r * 16;
            cp16(ksb + (((h & 1) * 64 + key) * KPAD + lc16 * 4) * 4,
                 kgl + (size_t)(h * 64 + key) * 8 + lc16);
            cp16(vsb + (((h & 1) * 64 + key) * VPAD + lc16 * 4) * 4,
                 vgl + (size_t)(h * 64 + key) * 8 + lc16);
        }
        asm volatile("cp.async.commit_group;");
    }

    for (int h = 0; h < 16; h++) {
        if (h < 15) asm volatile("cp.async.wait_group 1;");
        else        asm volatile("cp.async.wait_group 0;");
        __syncthreads();

        const int rbase = (h & 1) * 64;
#pragma unroll 2
        for (int kch = 0; kch < 8; kch++) {
            const int key0 = rbase + kch * 8;
            const uint32_t* krow = &Ks[(key0 + gid) * KPAD + tig * 8];
            uint4 kf0 = *(const uint4*)krow;
            uint4 kf1 = *(const uint4*)(krow + 4);
            uint4 vf0 = *(const uint4*)&Vs[(key0 + tig) * VPAD + gid * 4];
            uint4 vf1 = *(const uint4*)&Vs[(key0 + tig + 4) * VPAD + gid * 4];

#pragma unroll
            for (int tt = 0; tt < 2; tt++) {
                float s0 = 0.f, s1 = 0.f, s2 = 0.f, s3 = 0.f;
                mma_tf32(s0, s1, s2, s3, qa[tt][0][0], qa[tt][0][1], qa[tt][0][2], qa[tt][0][3], kf0.x, kf0.y);
                mma_tf32(s0, s1, s2, s3, qa[tt][1][0], qa[tt][1][1], qa[tt][1][2], qa[tt][1][3], kf0.z, kf0.w);
                mma_tf32(s0, s1, s2, s3, qa[tt][2][0], qa[tt][2][1], qa[tt][2][2], qa[tt][2][3], kf1.x, kf1.y);
                mma_tf32(s0, s1, s2, s3, qa[tt][3][0], qa[tt][3][1], qa[tt][3][2], qa[tt][3][3], kf1.z, kf1.w);
                float f0 = ex2f(s0), f1 = ex2f(s1), f2 = ex2f(s2), f3 = ex2f(s3);
                lv[tt][0] += f0 + f1;
                lv[tt][1] += f2 + f3;
                uint32_t p0 = __float_as_uint(f0);
                uint32_t p1 = __float_as_uint(f1);
                uint32_t p2 = __float_as_uint(f2);
                uint32_t p3 = __float_as_uint(f3);
                uint32_t e0, e1;
                e0 = __shfl_sync(0xffffffffu, p0, src0);
                e1 = __shfl_sync(0xffffffffu, p1, src0);
                uint32_t pa0 = odd ? e1 : e0;
                e0 = __shfl_sync(0xffffffffu, p0, src0 + 2);
                e1 = __shfl_sync(0xffffffffu, p1, src0 + 2);
                uint32_t pa2 = odd ? e1 : e0;
                e0 = __shfl_sync(0xffffffffu, p2, src0);
                e1 = __shfl_sync(0xffffffffu, p3, src0);
                uint32_t pa1 = odd ? e1 : e0;
                e0 = __shfl_sync(0xffffffffu, p2, src0 + 2);
                e1 = __shfl_sync(0xffffffffu, p3, src0 + 2);
                uint32_t pa3 = odd ? e1 : e0;
                mma_tf32(o[tt][0][0], o[tt][0][1], o[tt][0][2], o[tt][0][3], pa0, pa1, pa2, pa3, vf0.x, vf1.x);
                mma_tf32(o[tt][1][0], o[tt][1][1], o[tt][1][2], o[tt][1][3], pa0, pa1, pa2, pa3, vf0.y, vf1.y);
                mma_tf32(o[tt][2][0], o[tt][2][1], o[tt][2][2], o[tt][2][3], pa0, pa1, pa2, pa3, vf0.z, vf1.z);
                mma_tf32(o[tt][3][0], o[tt][3][1], o[tt][3][2], o[tt][3][3], pa0, pa1, pa2, pa3, vf0.w, vf1.w);
            }
        }
        __syncthreads();

        if (h + 2 < 16) {
            const int hn = h + 2;
#pragma unroll
            for (int r = 0; r < 4; r++) {
                int key = lkey0 + r * 16;
                cp16(ksb + (((hn & 1) * 64 + key) * KPAD + lc16 * 4) * 4,
                     kgl + (size_t)(hn * 64 + key) * 8 + lc16);
                cp16(vsb + (((hn & 1) * 64 + key) * VPAD + lc16 * 4) * 4,
                     vgl + (size_t)(hn * 64 + key) * 8 + lc16);
            }
            asm volatile("cp.async.commit_group;");
        }
    }

    const float* cs = g_csum + bh * 32;   // physV order
    float* ob = g_ao + ((size_t)b * 256 + head * 32) * 1024;
#pragma unroll
    for (int tt = 0; tt < 2; tt++) {
        float llo = lv[tt][0], lhi = lv[tt][1];
        llo += __shfl_xor_sync(0xffffffffu, llo, 1);
        llo += __shfl_xor_sync(0xffffffffu, llo, 2);
        lhi += __shfl_xor_sync(0xffffffffu, lhi, 1);
        lhi += __shfl_xor_sync(0xffffffffu, lhi, 2);
        const float invlo = 1.f / llo;
        const float invhi = 1.f / lhi;

        const int rlo = q0 + tt * 16 + gid;
        const int rhi = rlo + 8;
        const float dvlo = (rlo < 32) ? g_dvec[b * 32 + rlo] : 0.f;
        const float dvhi = (rhi < 32) ? g_dvec[b * 32 + rhi] : 0.f;
#pragma unroll
        for (int nt = 0; nt < 4; nt++) {
            int c0 = nt * 8 + 2 * tig;
            int c1 = c0 + 1;
            float cs0 = cs[8 * tig + nt];          // physV(c0)
            float cs1 = cs[8 * tig + 4 + nt];      // physV(c1)
            ob[(size_t)c0 * 1024 + rlo] = o[tt][nt][0] * invlo + dvlo * cs0;
            ob[(size_t)c1 * 1024 + rlo] = o[tt][nt][1] * invlo + dvlo * cs1;
            ob[(size_t)c0 * 1024 + rhi] = o[tt][nt][2] * invhi + dvhi * cs0;
            ob[(size_t)c1 * 1024 + rhi] = o[tt][nt][3] * invhi + dvhi * cs1;
        }
    }
}

// ---------------------------------------------------------------------------
// K4a: gate hidden (FFMA2)
// ---------------------------------------------------------------------------
__global__ __launch_bounds__(256) void gate1_kernel(const float* __restrict__ x,
                                                    const float* __restrict__ w_g1,
                                                    const float* __restrict__ b_g1) {
    const int b = blockIdx.y;
    const int p0 = blockIdx.x * 64;
    const int tid = threadIdx.x;
    const int tx = tid & 15, ty = tid >> 4;

    __shared__ float Ws2[32 * 68];   // [c][u]
    __shared__ float Xs2[32 * 64];   // [c][p]

    u64 acc2[4][2];
#pragma unroll
    for (int i = 0; i < 4; i++) { acc2[i][0] = 0ull; acc2[i][1] = 0ull; }

    for (int kk = 0; kk < 256; kk += 32) {
#pragma unroll
        for (int t = 0; t < 2; t++) {
            int idx4 = tid + t * 256;
            int uu = idx4 >> 3;
            int cc4 = idx4 & 7;
            float4 wv = *(const float4*)&w_g1[uu * 256 + kk + cc4 * 4];
            Ws2[(cc4 * 4 + 0) * 68 + uu] = wv.x;
            Ws2[(cc4 * 4 + 1) * 68 + uu] = wv.y;
            Ws2[(cc4 * 4 + 2) * 68 + uu] = wv.z;
            Ws2[(cc4 * 4 + 3) * 68 + uu] = wv.w;
        }
#pragma unroll
        for (int t = 0; t < 8; t++) {
            int idx = tid + t * 256;
            int cc = idx >> 6;
            int pp = idx & 63;
            int p = p0 + pp;
            int hh = p >> 5;
            int wj = (p & 31) >> 1;
            const float* row = x + ((size_t)(b * 256) + kk + cc) * 1024 + hh * 32;
            Xs2[cc * 64 + pp] = fabsf(row[wj] - row[31 - wj]);
        }
        __syncthreads();
#pragma unroll
        for (int c = 0; c < 32; c++) {
            float4 a = *(float4*)&Ws2[c * 68 + ty * 4];
            double2 bd = *(const double2*)&Xs2[c * 64 + tx * 4];
            u64 b01 = d2u(bd.x), b23 = d2u(bd.y);
            acc2[0][0] = ffma2(dup2(a.x), b01, acc2[0][0]);
            acc2[0][1] = ffma2(dup2(a.x), b23, acc2[0][1]);
            acc2[1][0] = ffma2(dup2(a.y), b01, acc2[1][0]);
            acc2[1][1] = ffma2(dup2(a.y), b23, acc2[1][1]);
            acc2[2][0] = ffma2(dup2(a.z), b01, acc2[2][0]);
            acc2[2][1] = ffma2(dup2(a.z), b23, acc2[2][1]);
            acc2[3][0] = ffma2(dup2(a.w), b01, acc2[3][0]);
            acc2[3][1] = ffma2(dup2(a.w), b23, acc2[3][1]);
        }
        __syncthreads();
    }

#pragma unroll
    for (int ui = 0; ui < 4; ui++) {
        int u = ty * 4 + ui;
        float bias = b_g1[u];
        float2 lo = unpk(acc2[ui][0]), hi = unpk(acc2[ui][1]);
        float v0 = lo.x + bias, v1 = lo.y + bias;
        float v2 = hi.x + bias, v3 = hi.y + bias;
        float4 vout;
        vout.x = 0.5f * v0 * (1.f + erff(v0 * 0.70710678118654752f));
        vout.y = 0.5f * v1 * (1.f + erff(v1 * 0.70710678118654752f));
        vout.z = 0.5f * v2 * (1.f + erff(v2 * 0.70710678118654752f));
        vout.w = 0.5f * v3 * (1.f + erff(v3 * 0.70710678118654752f));
        *(float4*)&g_g1buf[((size_t)(b * 64) + u) * 1024 + p0 + tx * 4] = vout;
    }
}

// ---------------------------------------------------------------------------
// K5: out-proj via tf32 MMA; gate2 computed in-CTA, (1+g) folded into staging.
// ---------------------------------------------------------------------------
__global__ __launch_bounds__(256) void outproj_kernel(const float* __restrict__ w_out,
                                                      const float* __restrict__ b_out,
                                                      const float* __restrict__ w_g2,
                                                      const float* __restrict__ b_g2,
                                                      float* __restrict__ out) {
    const int b = blockIdx.z;
    const int o0 = blockIdx.y * 128;
    const int p0 = blockIdx.x * 128;
    const int tid = threadIdx.x;
    const int warp = tid >> 5;
    const int lane = tid & 31;
    const int gid = lane >> 2;
    const int tig = lane & 3;
    const int o_w = (warp >> 2) * 64;
    const int p_w = (warp & 3) * 32;

    __shared__ uint32_t Ws[128 * WPAD];
    __shared__ uint32_t Xs[32 * XPAD];
    __shared__ float Gs[128];

    if (tid < 128) {
        float a = b_g2[0];
        const float* g1 = g_g1buf + (size_t)(b * 64) * 1024 + p0 + tid;
#pragma unroll 8
        for (int u = 0; u < 64; u++) a += g1[(size_t)u * 1024] * w_g2[u];
        Gs[tid] = 1.f + 1.f / (1.f + ex2f(-a * LOG2E));
    }

    float acc[4][4][4];
#pragma unroll
    for (int m = 0; m < 4; m++)
#pragma unroll
        for (int n = 0; n < 4; n++)
#pragma unroll
            for (int r = 0; r < 4; r++) acc[m][n][r] = 0.f;
    __syncthreads();

    for (int kk = 0; kk < 256; kk += 32) {
#pragma unroll
        for (int t = 0; t < 4; t++) {
            int idx4 = tid + t * 256;
            int oo = idx4 >> 3, c4 = (idx4 & 7) * 4;
            float4 wv = *(const float4*)&w_out[(o0 + oo) * 256 + kk + c4];
            *(uint4*)&Ws[oo * WPAD + c4] =
                make_uint4(f2tf(wv.x), f2tf(wv.y), f2tf(wv.z), f2tf(wv.w));
        }
#pragma unroll
        for (int t = 0; t < 4; t++) {
            int idx4 = tid + t * 256;
            int cc = idx4 >> 5, p4 = (idx4 & 31) * 4;
            float4 xv = *(const float4*)&g_ao[((size_t)(b * 256) + kk + cc) * 1024 + p0 + p4];
            xv.x *= Gs[p4 + 0]; xv.y *= Gs[p4 + 1];
            xv.z *= Gs[p4 + 2]; xv.w *= Gs[p4 + 3];
            *(uint4*)&Xs[cc * XPAD + p4] =
                make_uint4(f2tf(xv.x), f2tf(xv.y), f2tf(xv.z), f2tf(xv.w));
        }
        __syncthreads();
#pragma unroll
        for (int kc = 0; kc < 4; kc++) {
            const int ck = kc * 8;
            uint32_t af[4][4];
#pragma unroll
            for (int m = 0; m < 4; m++) {
                const uint32_t* wr = &Ws[(o_w + m * 16 + gid) * WPAD + ck + tig];
                af[m][0] = wr[0];
                af[m][1] = wr[8 * WPAD];
                af[m][2] = wr[4];
                af[m][3] = wr[8 * WPAD + 4];
            }
            uint32_t bf[4][2];
#pragma unroll
            for (int n = 0; n < 4; n++) {
                const uint32_t* xr = &Xs[(ck + tig) * XPAD + p_w + n * 8 + gid];
                bf[n][0] = xr[0];
                bf[n][1] = xr[4 * XPAD];
            }
#pragma unroll
            for (int m = 0; m < 4; m++)
#pragma unroll
                for (int n = 0; n < 4; n++)
                    mma_tf32(acc[m][n][0], acc[m][n][1], acc[m][n][2], acc[m][n][3],
                             af[m][0], af[m][1], af[m][2], af[m][3],
                             bf[n][0], bf[n][1]);
        }
        __syncthreads();
    }

#pragma unroll
    for (int m = 0; m < 4; m++) {
        const int og0 = o0 + o_w + m * 16 + gid;
        const float bs0 = b_out[og0];
        const float bs1 = b_out[og0 + 8];
        float* r0 = out + ((size_t)(b * 256) + og0) * 1024;
        float* r1 = out + ((size_t)(b * 256) + og0 + 8) * 1024;
#pragma unroll
        for (int n = 0; n < 4; n++) {
            const int p = p0 + p_w + n * 8 + 2 * tig;
            *(float2*)&r0[p] = make_float2(acc[m][n][0] + bs0, acc[m][n][1] + bs0);
            *(float2*)&r1[p] = make_float2(acc[m][n][2] + bs1, acc[m][n][3] + bs1);
        }
    }
}

// ---------------------------------------------------------------------------
extern "C" void kernel_launch(void* const* d_in, const int* in_sizes, int n_in,
                              void* d_out, int out_size) {
    const float* x     = (const float*)d_in[0];
    const float* w_qkv = (const float*)d_in[1];
    const float* w_out = (const float*)d_in[2];
    const float* b_out = (const float*)d_in[3];
    const float* w_g1  = (const float*)d_in[4];
    const float* b_g1  = (const float*)d_in[5];
    const float* w_g2  = (const float*)d_in[6];
    const float* b_g2  = (const float*)d_in[7];
    float* out = (float*)d_out;

    qkv_kernel<<<dim3(8, 6, 8), 256>>>(x, w_qkv);
    reduce_kernel<<<72, 256>>>();
    attn_kernel<<<dim3(8, 64), 128>>>();
    gate1_kernel<<<dim3(16, 8), 256>>>(x, w_g1, b_g1);
    outproj_kernel<<<dim3(8, 2, 8), 256>>>(w_out, b_out, w_g2, b_g2, out);
}

// round 11
// speedup vs baseline: 3.3646x; 1.0051x over previous
#include <cuda_runtime.h>
#include <math.h>
#include <stdint.h>

// ---------------------------------------------------------------------------
// DiagonalMicroAttention: b=8, c=256, h=w=32, heads=8, d=32, n=1024
//   K1 qkv GEMM via tf32 mma -> q (scaled by SCALE*log2e, logical layout),
//      k (physK-permuted), v (physV-permuted), all tf32-rounded
//   K2 colsum(V) + diag_vec (fused)
//   K3 flash attention via tf32 mma, 32 q-rows/warp, cp.async pipelined K/V
//   K4 gate hidden via tf32 mma (pooled abs-diff staged, gelu epilogue)
//   K5 out-proj via tf32 mma, gate2 + (1+g) fused in
// ---------------------------------------------------------------------------

#define B 8
#define HEADS 8
#define D 32
#define N 1024
#define C 256
#define SCALE 0.1767766952966369f   // 1/sqrt(32)
#define LOG2E 1.4426950408889634f
#define BHND (B * HEADS * N * D)

__device__ __forceinline__ uint32_t f2tf(float f) {
    uint32_t r; asm("cvt.rna.tf32.f32 %0, %1;" : "=r"(r) : "f"(f));
    return r;
}
__device__ __forceinline__ float ex2f(float x) {
    float r; asm("ex2.approx.ftz.f32 %0, %1;" : "=f"(r) : "f"(x));
    return r;
}
__device__ __forceinline__ void mma_tf32(float& d0, float& d1, float& d2, float& d3,
                                         uint32_t a0, uint32_t a1, uint32_t a2, uint32_t a3,
                                         uint32_t b0, uint32_t b1) {
    asm("mma.sync.aligned.m16n8k8.row.col.f32.tf32.tf32.f32 "
        "{%0,%1,%2,%3}, {%4,%5,%6,%7}, {%8,%9}, {%0,%1,%2,%3};"
        : "+f"(d0), "+f"(d1), "+f"(d2), "+f"(d3)
        : "r"(a0), "r"(a1), "r"(a2), "r"(a3), "r"(b0), "r"(b1));
}
__device__ __forceinline__ void cp16(uint32_t smem_addr, const void* gptr) {
    asm volatile("cp.async.cg.shared.global [%0], [%1], 16;"
                 :: "r"(smem_addr), "l"(gptr));
}

// in-row permutations for MMA-fragment-friendly K/V storage
__device__ __forceinline__ int physK(int d) {
    return (d & 3) * 8 + (d >> 3) * 2 + ((d >> 2) & 1);
}
__device__ __forceinline__ int physV(int d) {
    return (d & 7) * 4 + (d >> 3);
}

__device__ float g_q[BHND];                // logical layout, x SCALE*LOG2E
__device__ float g_k[BHND];                // physK-permuted rows
__device__ float g_v[BHND];                // physV-permuted rows
__device__ float g_ao[B * C * N];          // attention output, [b][c][n]
__device__ float g_g1buf[B * 64 * N];      // gate hidden
__device__ float g_dvec[B * D];            // ln2*0.3/8 * diag sums
__device__ float g_csum[B * HEADS * D];    // colsum of V, physV order

// ---------------------------------------------------------------------------
// K1: qkv projection via tf32 MMA. CTA tile 128o x 128p, 8 warps 64o x 32p.
// ---------------------------------------------------------------------------
#define WPAD 36
#define XPAD 136

__global__ __launch_bounds__(256) void qkv_kernel(const float* __restrict__ x,
                                                  const float* __restrict__ w) {
    const int b = blockIdx.z;
    const int o0 = blockIdx.y * 128;
    const int p0 = blockIdx.x * 128;
    const int tid = threadIdx.x;
    const int warp = tid >> 5;
    const int lane = tid & 31;
    const int gid = lane >> 2;
    const int tig = lane & 3;
    const int o_w = (warp >> 2) * 64;
    const int p_w = (warp & 3) * 32;

    __shared__ uint32_t Ws[128 * WPAD];
    __shared__ uint32_t Xs[32 * XPAD];

    float acc[4][4][4];
#pragma unroll
    for (int m = 0; m < 4; m++)
#pragma unroll
        for (int n = 0; n < 4; n++)
#pragma unroll
            for (int r = 0; r < 4; r++) acc[m][n][r] = 0.f;

    for (int kk = 0; kk < 256; kk += 32) {
#pragma unroll
        for (int t = 0; t < 4; t++) {
            int idx4 = tid + t * 256;
            int oo = idx4 >> 3, c4 = (idx4 & 7) * 4;
            float4 wv = *(const float4*)&w[(o0 + oo) * 256 + kk + c4];
            *(uint4*)&Ws[oo * WPAD + c4] =
                make_uint4(f2tf(wv.x), f2tf(wv.y), f2tf(wv.z), f2tf(wv.w));
        }
#pragma unroll
        for (int t = 0; t < 4; t++) {
            int idx4 = tid + t * 256;
            int cc = idx4 >> 5, p4 = (idx4 & 31) * 4;
            float4 xv = *(const float4*)&x[((b * 256) + kk + cc) * 1024 + p0 + p4];
            *(uint4*)&Xs[cc * XPAD + p4] =
                make_uint4(f2tf(xv.x), f2tf(xv.y), f2tf(xv.z), f2tf(xv.w));
        }
        __syncthreads();
#pragma unroll
        for (int kc = 0; kc < 4; kc++) {
            const int ck = kc * 8;
            uint32_t af[4][4];
#pragma unroll
            for (int m = 0; m < 4; m++) {
                const uint32_t* wr = &Ws[(o_w + m * 16 + gid) * WPAD + ck + tig];
                af[m][0] = wr[0];
                af[m][1] = wr[8 * WPAD];
                af[m][2] = wr[4];
                af[m][3] = wr[8 * WPAD + 4];
            }
            uint32_t bf[4][2];
#pragma unroll
            for (int n = 0; n < 4; n++) {
                const uint32_t* xr = &Xs[(ck + tig) * XPAD + p_w + n * 8 + gid];
                bf[n][0] = xr[0];
                bf[n][1] = xr[4 * XPAD];
            }
#pragma unroll
            for (int m = 0; m < 4; m++)
#pragma unroll
                for (int n = 0; n < 4; n++)
                    mma_tf32(acc[m][n][0], acc[m][n][1], acc[m][n][2], acc[m][n][3],
                             af[m][0], af[m][1], af[m][2], af[m][3],
                             bf[n][0], bf[n][1]);
        }
        __syncthreads();
    }

    // epilogue: route to q/k/v with per-part layout + scaling
    const int part = (o0 + o_w) >> 8;
    float* dst = (part == 0) ? g_q : ((part == 1) ? g_k : g_v);
    const float mult = (part == 0) ? (SCALE * LOG2E) : 1.0f;
#pragma unroll
    for (int m = 0; m < 4; m++) {
        const int ob = o0 + o_w + m * 16;
        const int head = (ob >> 5) & 7;
        const int dl0 = (ob & 31) + gid;
        const int dl1 = dl0 + 8;
        int d0, d1;
        if (part == 0)      { d0 = dl0;        d1 = dl1; }
        else if (part == 1) { d0 = physK(dl0); d1 = physK(dl1); }
        else                { d0 = physV(dl0); d1 = physV(dl1); }
        float* hb = dst + ((size_t)(b * 8 + head) * 1024) * 32;
#pragma unroll
        for (int n = 0; n < 4; n++) {
            const int p = p0 + p_w + n * 8 + 2 * tig;
            float* pb = hb + (size_t)p * 32;
            pb[d0]      = __uint_as_float(f2tf(acc[m][n][0] * mult));
            pb[32 + d0] = __uint_as_float(f2tf(acc[m][n][1] * mult));
            pb[d1]      = __uint_as_float(f2tf(acc[m][n][2] * mult));
            pb[32 + d1] = __uint_as_float(f2tf(acc[m][n][3] * mult));
        }
    }
}

// ---------------------------------------------------------------------------
// K2: fused colsum(V) (blocks 0..63) + diag_vec (blocks 64..71).
// ---------------------------------------------------------------------------
__global__ __launch_bounds__(256) void reduce_kernel() {
    const int tid = threadIdx.x;
    __shared__ float red[256];
    if (blockIdx.x < 64) {
        const int bh = blockIdx.x;
        const int dd = tid & 31;
        const int sl = tid >> 5;
        const float* vb = g_v + (size_t)bh * 1024 * 32;
        float s = 0.f;
        for (int j = sl * 128; j < sl * 128 + 128; j++) s += vb[(size_t)j * 32 + dd];
        red[tid] = s;
        __syncthreads();
        if (tid < 32) {
            float t = 0.f;
#pragma unroll
            for (int r = 0; r < 8; r++) t += red[tid + r * 32];
            g_csum[bh * 32 + tid] = t;
        }
    } else {
        const int b = blockIdx.x - 64;
        const int i = tid & 31;
        const int h = tid >> 5;
        const int ik = physK(i);
        const size_t base = ((size_t)(b * 8 + h) * 1024) * 32;
        float s = 0.f;
#pragma unroll 4
        for (int ss = 0; ss < 32; ss++) {
            size_t off = base + (size_t)(ss * 33) * 32;
            s += g_q[off + i] * g_k[off + ik];
        }
        red[tid] = s;
        __syncthreads();
        if (tid < 32) {
            float t = 0.f;
#pragma unroll
            for (int r = 0; r < 8; r++) t += red[tid + r * 32];
            g_dvec[b * 32 + tid] = t * (0.3f * 0.6931471805599453f / 8.0f);
        }
    }
}

// ---------------------------------------------------------------------------
// K3: tf32 flash attention, 4 warps/CTA, 32 q-rows/warp, cp.async-pipelined
// K/V staging (2-slot ring of 64-key halves inside the same smem footprint).
// ---------------------------------------------------------------------------
#define KPAD 36
#define VPAD 40

__global__ __launch_bounds__(128, 4) void attn_kernel() {
    const int bh = blockIdx.y;
    const int b = bh >> 3;
    const int head = bh & 7;
    const int tid = threadIdx.x;
    const int warp = tid >> 5;
    const int lane = tid & 31;
    const int gid = lane >> 2;
    const int tig = lane & 3;
    const int q0 = blockIdx.x * 128 + warp * 32;

    __shared__ uint32_t Ks[128 * KPAD];   // 2 x 64-key slots
    __shared__ uint32_t Vs[128 * VPAD];

    const float* qb = g_q + (size_t)bh * (N * D);
    uint32_t qa[2][4][4];
#pragma unroll
    for (int tt = 0; tt < 2; tt++) {
        const int rb = q0 + tt * 16;
#pragma unroll
        for (int kc = 0; kc < 4; kc++) {
            qa[tt][kc][0] = __float_as_uint(qb[(rb + gid) * 32 + kc * 8 + tig]);
            qa[tt][kc][1] = __float_as_uint(qb[(rb + gid + 8) * 32 + kc * 8 + tig]);
            qa[tt][kc][2] = __float_as_uint(qb[(rb + gid) * 32 + kc * 8 + tig + 4]);
            qa[tt][kc][3] = __float_as_uint(qb[(rb + gid + 8) * 32 + kc * 8 + tig + 4]);
        }
    }

    float o[2][4][4];
#pragma unroll
    for (int tt = 0; tt < 2; tt++)
#pragma unroll
        for (int nt = 0; nt < 4; nt++)
#pragma unroll
            for (int r = 0; r < 4; r++) o[tt][nt][r] = 0.f;
    float lv[2][2];
    lv[0][0] = lv[0][1] = lv[1][0] = lv[1][1] = 0.f;

    const uint4* kgl = (const uint4*)(g_k + (size_t)bh * (N * D));
    const uint4* vgl = (const uint4*)(g_v + (size_t)bh * (N * D));
    const uint32_t ksb = (uint32_t)__cvta_generic_to_shared(Ks);
    const uint32_t vsb = (uint32_t)__cvta_generic_to_shared(Vs);
    const int src0 = (lane & 28) | (tig >> 1);
    const bool odd = (tig & 1);

    const int lkey0 = tid >> 3;
    const int lc16 = tid & 7;

#pragma unroll
    for (int h = 0; h < 2; h++) {
#pragma unroll
        for (int r = 0; r < 4; r++) {
            int key = lkey0 + r * 16;
            cp16(ksb + (((h & 1) * 64 + key) * KPAD + lc16 * 4) * 4,
                 kgl + (size_t)(h * 64 + key) * 8 + lc16);
            cp16(vsb + (((h & 1) * 64 + key) * VPAD + lc16 * 4) * 4,
                 vgl + (size_t)(h * 64 + key) * 8 + lc16);
        }
        asm volatile("cp.async.commit_group;");
    }

    for (int h = 0; h < 16; h++) {
        if (h < 15) asm volatile("cp.async.wait_group 1;");
        else        asm volatile("cp.async.wait_group 0;");
        __syncthreads();

        const int rbase = (h & 1) * 64;
#pragma unroll 2
        for (int kch = 0; kch < 8; kch++) {
            const int key0 = rbase + kch * 8;
            const uint32_t* krow = &Ks[(key0 + gid) * KPAD + tig * 8];
            uint4 kf0 = *(const uint4*)krow;
            uint4 kf1 = *(const uint4*)(krow + 4);
            uint4 vf0 = *(const uint4*)&Vs[(key0 + tig) * VPAD + gid * 4];
            uint4 vf1 = *(const uint4*)&Vs[(key0 + tig + 4) * VPAD + gid * 4];

#pragma unroll
            for (int tt = 0; tt < 2; tt++) {
                float s0 = 0.f, s1 = 0.f, s2 = 0.f, s3 = 0.f;
                mma_tf32(s0, s1, s2, s3, qa[tt][0][0], qa[tt][0][1], qa[tt][0][2], qa[tt][0][3], kf0.x, kf0.y);
                mma_tf32(s0, s1, s2, s3, qa[tt][1][0], qa[tt][1][1], qa[tt][1][2], qa[tt][1][3], kf0.z, kf0.w);
                mma_tf32(s0, s1, s2, s3, qa[tt][2][0], qa[tt][2][1], qa[tt][2][2], qa[tt][2][3], kf1.x, kf1.y);
                mma_tf32(s0, s1, s2, s3, qa[tt][3][0], qa[tt][3][1], qa[tt][3][2], qa[tt][3][3], kf1.z, kf1.w);
                float f0 = ex2f(s0), f1 = ex2f(s1), f2 = ex2f(s2), f3 = ex2f(s3);
                lv[tt][0] += f0 + f1;
                lv[tt][1] += f2 + f3;
                uint32_t p0 = __float_as_uint(f0);
                uint32_t p1 = __float_as_uint(f1);
                uint32_t p2 = __float_as_uint(f2);
                uint32_t p3 = __float_as_uint(f3);
                uint32_t e0, e1;
                e0 = __shfl_sync(0xffffffffu, p0, src0);
                e1 = __shfl_sync(0xffffffffu, p1, src0);
                uint32_t pa0 = odd ? e1 : e0;
                e0 = __shfl_sync(0xffffffffu, p0, src0 + 2);
                e1 = __shfl_sync(0xffffffffu, p1, src0 + 2);
                uint32_t pa2 = odd ? e1 : e0;
                e0 = __shfl_sync(0xffffffffu, p2, src0);
                e1 = __shfl_sync(0xffffffffu, p3, src0);
                uint32_t pa1 = odd ? e1 : e0;
                e0 = __shfl_sync(0xffffffffu, p2, src0 + 2);
                e1 = __shfl_sync(0xffffffffu, p3, src0 + 2);
                uint32_t pa3 = odd ? e1 : e0;
                mma_tf32(o[tt][0][0], o[tt][0][1], o[tt][0][2], o[tt][0][3], pa0, pa1, pa2, pa3, vf0.x, vf1.x);
                mma_tf32(o[tt][1][0], o[tt][1][1], o[tt][1][2], o[tt][1][3], pa0, pa1, pa2, pa3, vf0.y, vf1.y);
                mma_tf32(o[tt][2][0], o[tt][2][1], o[tt][2][2], o[tt][2][3], pa0, pa1, pa2, pa3, vf0.z, vf1.z);
                mma_tf32(o[tt][3][0], o[tt][3][1], o[tt][3][2], o[tt][3][3], pa0, pa1, pa2, pa3, vf0.w, vf1.w);
            }
        }
        __syncthreads();

        if (h + 2 < 16) {
            const int hn = h + 2;
#pragma unroll
            for (int r = 0; r < 4; r++) {
                int key = lkey0 + r * 16;
                cp16(ksb + (((hn & 1) * 64 + key) * KPAD + lc16 * 4) * 4,
                     kgl + (size_t)(hn * 64 + key) * 8 + lc16);
                cp16(vsb + (((hn & 1) * 64 + key) * VPAD + lc16 * 4) * 4,
                     vgl + (size_t)(hn * 64 + key) * 8 + lc16);
            }
            asm volatile("cp.async.commit_group;");
        }
    }

    const float* cs = g_csum + bh * 32;   // physV order
    float* ob = g_ao + ((size_t)b * 256 + head * 32) * 1024;
#pragma unroll
    for (int tt = 0; tt < 2; tt++) {
        float llo = lv[tt][0], lhi = lv[tt][1];
        llo += __shfl_xor_sync(0xffffffffu, llo, 1);
        llo += __shfl_xor_sync(0xffffffffu, llo, 2);
        lhi += __shfl_xor_sync(0xffffffffu, lhi, 1);
        lhi += __shfl_xor_sync(0xffffffffu, lhi, 2);
        const float invlo = 1.f / llo;
        const float invhi = 1.f / lhi;

        const int rlo = q0 + tt * 16 + gid;
        const int rhi = rlo + 8;
        const float dvlo = (rlo < 32) ? g_dvec[b * 32 + rlo] : 0.f;
        const float dvhi = (rhi < 32) ? g_dvec[b * 32 + rhi] : 0.f;
#pragma unroll
        for (int nt = 0; nt < 4; nt++) {
            int c0 = nt * 8 + 2 * tig;
            int c1 = c0 + 1;
            float cs0 = cs[8 * tig + nt];          // physV(c0)
            float cs1 = cs[8 * tig + 4 + nt];      // physV(c1)
            ob[(size_t)c0 * 1024 + rlo] = o[tt][nt][0] * invlo + dvlo * cs0;
            ob[(size_t)c1 * 1024 + rlo] = o[tt][nt][1] * invlo + dvlo * cs1;
            ob[(size_t)c0 * 1024 + rhi] = o[tt][nt][2] * invhi + dvhi * cs0;
            ob[(size_t)c1 * 1024 + rhi] = o[tt][nt][3] * invhi + dvhi * cs1;
        }
    }
}

// ---------------------------------------------------------------------------
// K4: gate hidden via tf32 MMA. M=64(u) x N=64(p) CTA tile, K=256 in chunks
// of 32. 8 warps: warp = (mw 0..3: 16u) x (nw 0..1: 32p). Pooled abs-diff
// computed during staging; gelu(erf) epilogue -> g1buf [b][u][p].
// ---------------------------------------------------------------------------
#define G1WPAD 36
#define G1XPAD 72

__global__ __launch_bounds__(256) void gate1_kernel(const float* __restrict__ x,
                                                    const float* __restrict__ w_g1,
                                                    const float* __restrict__ b_g1) {
    const int b = blockIdx.y;
    const int p0 = blockIdx.x * 64;
    const int tid = threadIdx.x;
    const int warp = tid >> 5;
    const int lane = tid & 31;
    const int gid = lane >> 2;
    const int tig = lane & 3;
    const int mw = warp & 3;      // 16-u tile
    const int nw = warp >> 2;     // 32-p half

    __shared__ uint32_t Ws[64 * G1WPAD];   // [u][c] tf32
    __shared__ uint32_t Xs[32 * G1XPAD];   // [c][p] pooled tf32

    float acc[4][4];
#pragma unroll
    for (int n = 0; n < 4; n++)
#pragma unroll
        for (int r = 0; r < 4; r++) acc[n][r] = 0.f;

    for (int kk = 0; kk < 256; kk += 32) {
        // stage W_g1 64x32 (tf32)
#pragma unroll
        for (int t = 0; t < 2; t++) {
            int idx4 = tid + t * 256;
            int uu = idx4 >> 3, c4 = (idx4 & 7) * 4;
            float4 wv = *(const float4*)&w_g1[uu * 256 + kk + c4];
            *(uint4*)&Ws[uu * G1WPAD + c4] =
                make_uint4(f2tf(wv.x), f2tf(wv.y), f2tf(wv.z), f2tf(wv.w));
        }
        // stage pooled 32x64
#pragma unroll
        for (int t = 0; t < 8; t++) {
            int idx = tid + t * 256;
            int cc = idx >> 6, pp = idx & 63;
            int p = p0 + pp;
            int hh = p >> 5;
            int wj = (p & 31) >> 1;
            const float* row = x + ((size_t)(b * 256) + kk + cc) * 1024 + hh * 32;
            Xs[cc * G1XPAD + pp] = f2tf(fabsf(row[wj] - row[31 - wj]));
        }
        __syncthreads();
#pragma unroll
        for (int kc = 0; kc < 4; kc++) {
            const int ck = kc * 8;
            const uint32_t* wr = &Ws[(mw * 16 + gid) * G1WPAD + ck + tig];
            uint32_t a0 = wr[0];
            uint32_t a1 = wr[8 * G1WPAD];
            uint32_t a2 = wr[4];
            uint32_t a3 = wr[8 * G1WPAD + 4];
#pragma unroll
            for (int n = 0; n < 4; n++) {
                const uint32_t* xr = &Xs[(ck + tig) * G1XPAD + nw * 32 + n * 8 + gid];
                mma_tf32(acc[n][0], acc[n][1], acc[n][2], acc[n][3],
                         a0, a1, a2, a3, xr[0], xr[4 * G1XPAD]);
            }
        }
        __syncthreads();
    }

    // epilogue: bias + gelu(erf), store to g1buf [b][u][p]
    const int u0 = mw * 16 + gid;
    const int u1 = u0 + 8;
    const float bias0 = b_g1[u0];
    const float bias1 = b_g1[u1];
    float* g0 = g_g1buf + ((size_t)(b * 64) + u0) * 1024;
    float* g1 = g_g1buf + ((size_t)(b * 64) + u1) * 1024;
#pragma unroll
    for (int n = 0; n < 4; n++) {
        const int p = p0 + nw * 32 + n * 8 + 2 * tig;
        float v0 = acc[n][0] + bias0, v1 = acc[n][1] + bias0;
        float v2 = acc[n][2] + bias1, v3 = acc[n][3] + bias1;
        v0 = 0.5f * v0 * (1.f + erff(v0 * 0.70710678118654752f));
        v1 = 0.5f * v1 * (1.f + erff(v1 * 0.70710678118654752f));
        v2 = 0.5f * v2 * (1.f + erff(v2 * 0.70710678118654752f));
        v3 = 0.5f * v3 * (1.f + erff(v3 * 0.70710678118654752f));
        *(float2*)&g0[p] = make_float2(v0, v1);
        *(float2*)&g1[p] = make_float2(v2, v3);
    }
}

// ---------------------------------------------------------------------------
// K5: out-proj via tf32 MMA; gate2 computed in-CTA, (1+g) folded into staging.
// ---------------------------------------------------------------------------
__global__ __launch_bounds__(256) void outproj_kernel(const float* __restrict__ w_out,
                                                      const float* __restrict__ b_out,
                                                      const float* __restrict__ w_g2,
                                                      const float* __restrict__ b_g2,
                                                      float* __restrict__ out) {
    const int b = blockIdx.z;
    const int o0 = blockIdx.y * 128;
    const int p0 = blockIdx.x * 128;
    const int tid = threadIdx.x;
    const int warp = tid >> 5;
    const int lane = tid & 31;
    const int gid = lane >> 2;
    const int tig = lane & 3;
    const int o_w = (warp >> 2) * 64;
    const int p_w = (warp & 3) * 32;

    __shared__ uint32_t Ws[128 * WPAD];
    __shared__ uint32_t Xs[32 * XPAD];
    __shared__ float Gs[128];

    if (tid < 128) {
        float a = b_g2[0];
        const float* g1 = g_g1buf + (size_t)(b * 64) * 1024 + p0 + tid;
#pragma unroll 8
        for (int u = 0; u < 64; u++) a += g1[(size_t)u * 1024] * w_g2[u];
        Gs[tid] = 1.f + 1.f / (1.f + ex2f(-a * LOG2E));
    }

    float acc[4][4][4];
#pragma unroll
    for (int m = 0; m < 4; m++)
#pragma unroll
        for (int n = 0; n < 4; n++)
#pragma unroll
            for (int r = 0; r < 4; r++) acc[m][n][r] = 0.f;
    __syncthreads();

    for (int kk = 0; kk < 256; kk += 32) {
#pragma unroll
        for (int t = 0; t < 4; t++) {
            int idx4 = tid + t * 256;
            int oo = idx4 >> 3, c4 = (idx4 & 7) * 4;
            float4 wv = *(const float4*)&w_out[(o0 + oo) * 256 + kk + c4];
            *(uint4*)&Ws[oo * WPAD + c4] =
                make_uint4(f2tf(wv.x), f2tf(wv.y), f2tf(wv.z), f2tf(wv.w));
        }
#pragma unroll
        for (int t = 0; t < 4; t++) {
            int idx4 = tid + t * 256;
            int cc = idx4 >> 5, p4 = (idx4 & 31) * 4;
            float4 xv = *(const float4*)&g_ao[((size_t)(b * 256) + kk + cc) * 1024 + p0 + p4];
            xv.x *= Gs[p4 + 0]; xv.y *= Gs[p4 + 1];
            xv.z *= Gs[p4 + 2]; xv.w *= Gs[p4 + 3];
            *(uint4*)&Xs[cc * XPAD + p4] =
                make_uint4(f2tf(xv.x), f2tf(xv.y), f2tf(xv.z), f2tf(xv.w));
        }
        __syncthreads();
#pragma unroll
        for (int kc = 0; kc < 4; kc++) {
            const int ck = kc * 8;
            uint32_t af[4][4];
#pragma unroll
            for (int m = 0; m < 4; m++) {
                const uint32_t* wr = &Ws[(o_w + m * 16 + gid) * WPAD + ck + tig];
                af[m][0] = wr[0];
                af[m][1] = wr[8 * WPAD];
                af[m][2] = wr[4];
                af[m][3] = wr[8 * WPAD + 4];
            }
            uint32_t bf[4][2];
#pragma unroll
            for (int n = 0; n < 4; n++) {
                const uint32_t* xr = &Xs[(ck + tig) * XPAD + p_w + n * 8 + gid];
                bf[n][0] = xr[0];
                bf[n][1] = xr[4 * XPAD];
            }
#pragma unroll
            for (int m = 0; m < 4; m++)
#pragma unroll
                for (int n = 0; n < 4; n++)
                    mma_tf32(acc[m][n][0], acc[m][n][1], acc[m][n][2], acc[m][n][3],
                             af[m][0], af[m][1], af[m][2], af[m][3],
                             bf[n][0], bf[n][1]);
        }
        __syncthreads();
    }

#pragma unroll
    for (int m = 0; m < 4; m++) {
        const int og0 = o0 + o_w + m * 16 + gid;
        const float bs0 = b_out[og0];
        const float bs1 = b_out[og0 + 8];
        float* r0 = out + ((size_t)(b * 256) + og0) * 1024;
        float* r1 = out + ((size_t)(b * 256) + og0 + 8) * 1024;
#pragma unroll
        for (int n = 0; n < 4; n++) {
            const int p = p0 + p_w + n * 8 + 2 * tig;
            *(float2*)&r0[p] = make_float2(acc[m][n][0] + bs0, acc[m][n][1] + bs0);
            *(float2*)&r1[p] = make_float2(acc[m][n][2] + bs1, acc[m][n][3] + bs1);
        }
    }
}

// ---------------------------------------------------------------------------
extern "C" void kernel_launch(void* const* d_in, const int* in_sizes, int n_in,
                              void* d_out, int out_size) {
    const float* x     = (const float*)d_in[0];
    const float* w_qkv = (const float*)d_in[1];
    const float* w_out = (const float*)d_in[2];
    const float* b_out = (const float*)d_in[3];
    const float* w_g1  = (const float*)d_in[4];
    const float* b_g1  = (const float*)d_in[5];
    const float* w_g2  = (const float*)d_in[6];
    const float* b_g2  = (const float*)d_in[7];
    float* out = (float*)d_out;

    qkv_kernel<<<dim3(8, 6, 8), 256>>>(x, w_qkv);
    reduce_kernel<<<72, 256>>>();
    attn_kernel<<<dim3(8, 64), 128>>>();
    gate1_kernel<<<dim3(16, 8), 256>>>(x, w_g1, b_g1);
    outproj_kernel<<<dim3(8, 2, 8), 256>>>(w_out, b_out, w_g2, b_g2, out);
}